// round 1
// baseline (speedup 1.0000x reference)
#include <cuda_runtime.h>
#include <math.h>

// ---------------------------------------------------------------------------
// Problem constants
// ---------------------------------------------------------------------------
static constexpr int B_    = 4;
static constexpr int NTOK  = 1040;   // 512 + 512 + 16
static constexpr int D_    = 1024;
static constexpr int H_    = 16;
static constexpr int DH_   = 64;
static constexpr int L_    = 4;
static constexpr int FF_   = 2730;
static constexpr int FF2_  = 5460;
static constexpr int ROWS  = B_ * NTOK;   // 4160

// ---------------------------------------------------------------------------
// Device scratch (static globals: no runtime allocation allowed)
// ---------------------------------------------------------------------------
__device__ float g_tokens[B_ * NTOK * D_];
__device__ float g_h     [B_ * NTOK * D_];
__device__ float g_q     [B_ * NTOK * D_];
__device__ float g_kv    [B_ * NTOK * 2 * D_];
__device__ float g_sim   [(long long)B_ * H_ * NTOK * NTOK];   // 277 MB
__device__ float g_ao    [B_ * NTOK * D_];
__device__ float g_ff1   [(long long)ROWS * FF2_];
__device__ float g_act   [(long long)ROWS * FF_];

// ---------------------------------------------------------------------------
// Helpers
// ---------------------------------------------------------------------------
__device__ __forceinline__ float blk_reduce(float v, bool ismax) {
    __shared__ float red[9];
    #pragma unroll
    for (int o = 16; o; o >>= 1) {
        float u = __shfl_xor_sync(0xffffffffu, v, o);
        v = ismax ? fmaxf(v, u) : (v + u);
    }
    if ((threadIdx.x & 31) == 0) red[threadIdx.x >> 5] = v;
    __syncthreads();
    if (threadIdx.x == 0) {
        float r = red[0];
        int nw = blockDim.x >> 5;
        for (int w = 1; w < nw; w++) r = ismax ? fmaxf(r, red[w]) : (r + red[w]);
        red[8] = r;
    }
    __syncthreads();
    float r = red[8];
    __syncthreads();
    return r;
}

__device__ __forceinline__ int token_type(int j) {
    return j < 512 ? 0 : (j < 1024 ? 1 : 2);   // 2 == FUSION
}

// ---------------------------------------------------------------------------
// Token concatenation: tokens[b, t, :] from m0 / m1 / fusion
// ---------------------------------------------------------------------------
__global__ void concat_kernel(const float4* __restrict__ m0,
                              const float4* __restrict__ m1,
                              const float4* __restrict__ fus,
                              float4* __restrict__ tokens) {
    int idx = blockIdx.x * blockDim.x + threadIdx.x;
    const int D4 = D_ / 4;
    int total = B_ * NTOK * D4;
    if (idx >= total) return;
    int d = idx % D4;
    int t = (idx / D4) % NTOK;
    int b = idx / (D4 * NTOK);
    float4 v;
    if (t < 512)       v = m0[((long)b * 512 + t) * D4 + d];
    else if (t < 1024) v = m1[((long)b * 512 + (t - 512)) * D4 + d];
    else               v = fus[(long)(t - 1024) * D4 + d];
    tokens[idx] = v;
}

// ---------------------------------------------------------------------------
// LayerNorm: one block (256 threads) per token row, D = 1024 (4 floats/thread)
// ---------------------------------------------------------------------------
__global__ void ln_kernel(const float* __restrict__ x,
                          const float* __restrict__ gamma,
                          float* __restrict__ out) {
    long row = blockIdx.x;
    const float4* xr = (const float4*)(x + row * D_);
    float4 v = xr[threadIdx.x];
    float s = v.x + v.y + v.z + v.w;
    float mean = blk_reduce(s, false) * (1.0f / D_);
    float dx = v.x - mean, dy = v.y - mean, dz = v.z - mean, dw = v.w - mean;
    float s2 = dx * dx + dy * dy + dz * dz + dw * dw;
    float var = blk_reduce(s2, false) * (1.0f / D_);
    float inv = rsqrtf(var + 1e-5f);
    float4 g = ((const float4*)gamma)[threadIdx.x];
    float4 o;
    o.x = dx * inv * g.x; o.y = dy * inv * g.y;
    o.z = dz * inv * g.z; o.w = dw * inv * g.w;
    ((float4*)(out + row * D_))[threadIdx.x] = o;
}

// ---------------------------------------------------------------------------
// Generic register-tiled GEMM (NN and NT), guarded, batched via z = zb*Hdiv+zh
//   C[M,Nn] = alpha * A[M,K] @ B      (+ Res)
//   TB=false: B is [K,Nn] row-major.  TB=true: B is [Nn,K] row-major (C=A@B^T)
// ---------------------------------------------------------------------------
template<int BM, int BN, int BK, int TM, int TN, bool TB>
__global__ void __launch_bounds__((BM / TM) * (BN / TN))
gemm_kernel(const float* __restrict__ A, const float* __restrict__ Bm,
            float* __restrict__ C, const float* __restrict__ Res,
            int M, int Nn, int K,
            int lda, int ldb, int ldc,
            long sAb, long sAh, long sBb, long sBh, long sCb, long sCh, int Hdiv,
            float alpha, int resRowMod, int ldres) {
    constexpr int THREADS = (BM / TM) * (BN / TN);
    constexpr int AELEM = BM * BK / THREADS;
    constexpr int BELEM = BK * BN / THREADS;

    int z = blockIdx.z;
    int zb = z / Hdiv, zh = z - zb * Hdiv;
    A  += (long)zb * sAb + (long)zh * sAh;
    Bm += (long)zb * sBb + (long)zh * sBh;
    C  += (long)zb * sCb + (long)zh * sCh;

    __shared__ __align__(16) float As[BK][BM + 4];
    __shared__ __align__(16) float Bs[BK][BN + 4];

    int tid = threadIdx.x;
    int tcol = tid % (BN / TN);
    int trow = tid / (BN / TN);
    int rowBase = blockIdx.y * BM;
    int colBase = blockIdx.x * BN;

    float acc[TM][TN] = {};

    for (int k0 = 0; k0 < K; k0 += BK) {
        #pragma unroll
        for (int e = 0; e < AELEM; e++) {
            int idx = tid + e * THREADS;
            int m = idx / BK, kk = idx % BK;
            int gr = rowBase + m, gc = k0 + kk;
            As[kk][m] = (gr < M && gc < K) ? A[(long)gr * lda + gc] : 0.0f;
        }
        #pragma unroll
        for (int e = 0; e < BELEM; e++) {
            int idx = tid + e * THREADS;
            int kk, n;
            if (!TB) { kk = idx / BN; n = idx % BN; }
            else     { n = idx / BK;  kk = idx % BK; }
            int gc = colBase + n, gk = k0 + kk;
            float v = 0.0f;
            if (gc < Nn && gk < K)
                v = TB ? Bm[(long)gc * ldb + gk] : Bm[(long)gk * ldb + gc];
            Bs[kk][n] = v;
        }
        __syncthreads();

        #pragma unroll
        for (int kk = 0; kk < BK; kk++) {
            float a[TM], bb[TN];
            #pragma unroll
            for (int i = 0; i < TM; i += 4) {
                float4 t = *(const float4*)&As[kk][trow * TM + i];
                a[i] = t.x; a[i + 1] = t.y; a[i + 2] = t.z; a[i + 3] = t.w;
            }
            #pragma unroll
            for (int j = 0; j < TN; j += 4) {
                float4 t = *(const float4*)&Bs[kk][tcol * TN + j];
                bb[j] = t.x; bb[j + 1] = t.y; bb[j + 2] = t.z; bb[j + 3] = t.w;
            }
            #pragma unroll
            for (int i = 0; i < TM; i++)
                #pragma unroll
                for (int j = 0; j < TN; j++)
                    acc[i][j] += a[i] * bb[j];
        }
        __syncthreads();
    }

    #pragma unroll
    for (int i = 0; i < TM; i++) {
        int r = rowBase + trow * TM + i;
        if (r >= M) continue;
        #pragma unroll
        for (int j = 0; j < TN; j++) {
            int c = colBase + tcol * TN + j;
            if (c >= Nn) continue;
            float v = alpha * acc[i][j];
            if (Res) {
                int rr = resRowMod ? (r % resRowMod) : r;
                v += Res[(long)rr * ldres + c];
            }
            C[(long)r * ldc + c] = v;
        }
    }
}

// ---------------------------------------------------------------------------
// Masked softmax over sim rows (self-attention). grid = B*H*NTOK blocks.
// Mask computed analytically: row i attends j iff tt(i)==FUSION || tt(j)==tt(i)
// ---------------------------------------------------------------------------
__global__ void softmax_self_kernel(float* __restrict__ sim) {
    long row = blockIdx.x;
    float* p = sim + row * NTOK;
    int i = (int)(row % NTOK);
    int ti = token_type(i);
    int tid = threadIdx.x;                 // 256 threads

    float vals[5];
    float mx = -3.4e38f;
    #pragma unroll
    for (int it = 0; it < 5; it++) {
        int j = tid + it * 256;
        float v = -3.4e38f;
        if (j < NTOK) {
            bool ok = (ti == 2) || (token_type(j) == ti);
            v = ok ? p[j] : -3.4e38f;
        }
        vals[it] = v;
        mx = fmaxf(mx, v);
    }
    mx = blk_reduce(mx, true);

    float e[5];
    float s = 0.0f;
    #pragma unroll
    for (int it = 0; it < 5; it++) {
        float ex = __expf(vals[it] - mx);   // masked -> underflow -> 0
        e[it] = ex;
        s += ex;
    }
    s = blk_reduce(s, false);
    float inv = 1.0f / s;
    #pragma unroll
    for (int it = 0; it < 5; it++) {
        int j = tid + it * 256;
        if (j < NTOK) p[j] = e[it] * inv;
    }
}

// Pool softmax: rows are [b,h,r] with r in 0..3. r==3 == GLOBAL attends all,
// otherwise attends tokens of type r (r==2 matches FUSION tokens).
__global__ void softmax_pool_kernel(float* __restrict__ sim) {
    long row = blockIdx.x;                 // B*H*4 rows
    float* p = sim + row * NTOK;
    int r = (int)(row % 4);
    int tid = threadIdx.x;

    float vals[5];
    float mx = -3.4e38f;
    #pragma unroll
    for (int it = 0; it < 5; it++) {
        int j = tid + it * 256;
        float v = -3.4e38f;
        if (j < NTOK) {
            bool ok = (r == 3) || (token_type(j) == r);
            v = ok ? p[j] : -3.4e38f;
        }
        vals[it] = v;
        mx = fmaxf(mx, v);
    }
    mx = blk_reduce(mx, true);

    float e[5];
    float s = 0.0f;
    #pragma unroll
    for (int it = 0; it < 5; it++) {
        float ex = __expf(vals[it] - mx);
        e[it] = ex;
        s += ex;
    }
    s = blk_reduce(s, false);
    float inv = 1.0f / s;
    #pragma unroll
    for (int it = 0; it < 5; it++) {
        int j = tid + it * 256;
        if (j < NTOK) p[j] = e[it] * inv;
    }
}

// ---------------------------------------------------------------------------
// GEGLU: act[row, f] = gelu_exact(ff1[row, FF+f]) * ff1[row, f]
// ---------------------------------------------------------------------------
__global__ void geglu_kernel(const float* __restrict__ ff1,
                             float* __restrict__ act) {
    long idx = (long)blockIdx.x * blockDim.x + threadIdx.x;
    long total = (long)ROWS * FF_;
    if (idx >= total) return;
    long row = idx / FF_;
    int f = (int)(idx - row * FF_);
    const float* p = ff1 + row * FF2_;
    float val = p[f];
    float gate = p[FF_ + f];
    float g = 0.5f * gate * (1.0f + erff(gate * 0.70710678118654752f));
    act[idx] = g * val;
}

// ---------------------------------------------------------------------------
// Host-side launch helpers
// ---------------------------------------------------------------------------
static inline void gemm_big(const float* A, const float* B, float* C,
                            const float* Res, int M, int Nn, int K,
                            int lda, int ldb, int ldc, float alpha,
                            int resRowMod = 0, int ldres = 0) {
    dim3 grid((Nn + 127) / 128, (M + 127) / 128, 1);
    gemm_kernel<128, 128, 8, 8, 8, false><<<grid, 256>>>(
        A, B, C, Res, M, Nn, K, lda, ldb, ldc,
        0, 0, 0, 0, 0, 0, 1, alpha, resRowMod, ldres);
}

extern "C" void kernel_launch(void* const* d_in, const int* in_sizes, int n_in,
                              void* d_out, int out_size) {
    const float* m0        = (const float*)d_in[0];
    const float* m1        = (const float*)d_in[1];
    const float* fusion    = (const float*)d_in[2];
    const float* ret_tok   = (const float*)d_in[3];
    const float* ln_gamma  = (const float*)d_in[4];
    const float* wq        = (const float*)d_in[5];
    const float* wkv       = (const float*)d_in[6];
    const float* wo        = (const float*)d_in[7];
    const float* ff_w1     = (const float*)d_in[8];
    const float* ff_w2     = (const float*)d_in[9];
    const float* pool_wq   = (const float*)d_in[10];
    const float* pool_wkv  = (const float*)d_in[11];
    const float* pool_wo   = (const float*)d_in[12];
    const float* final_g   = (const float*)d_in[13];
    float* out = (float*)d_out;

    float *tokens, *hbuf, *qbuf, *kvbuf, *simbuf, *aobuf, *ff1buf, *actbuf;
    cudaGetSymbolAddress((void**)&tokens, g_tokens);
    cudaGetSymbolAddress((void**)&hbuf,   g_h);
    cudaGetSymbolAddress((void**)&qbuf,   g_q);
    cudaGetSymbolAddress((void**)&kvbuf,  g_kv);
    cudaGetSymbolAddress((void**)&simbuf, g_sim);
    cudaGetSymbolAddress((void**)&aobuf,  g_ao);
    cudaGetSymbolAddress((void**)&ff1buf, g_ff1);
    cudaGetSymbolAddress((void**)&actbuf, g_act);

    // Build token sequence
    {
        int total = B_ * NTOK * (D_ / 4);
        concat_kernel<<<(total + 255) / 256, 256>>>(
            (const float4*)m0, (const float4*)m1, (const float4*)fusion,
            (float4*)tokens);
    }

    const float scale = 0.125f;   // DH^-0.5

    for (int l = 0; l < L_; l++) {
        const float* wq_l  = wq    + (long)l * D_ * D_;
        const float* wkv_l = wkv   + (long)l * D_ * 2 * D_;
        const float* wo_l  = wo    + (long)l * D_ * D_;
        const float* w1_l  = ff_w1 + (long)l * D_ * FF2_;
        const float* w2_l  = ff_w2 + (long)l * FF_ * D_;
        const float* g_l   = ln_gamma + (long)l * D_;

        // --- attention block ---
        ln_kernel<<<ROWS, 256>>>(tokens, g_l, hbuf);
        gemm_big(hbuf, wq_l,  qbuf,  nullptr, ROWS, D_,     D_, D_, D_,     D_,     scale);
        gemm_big(hbuf, wkv_l, kvbuf, nullptr, ROWS, 2 * D_, D_, D_, 2 * D_, 2 * D_, 1.0f);

        // sim[b,h,i,j] = q . k   (NT, batched over 64 (b,h) pairs)
        {
            dim3 grid((NTOK + 63) / 64, (NTOK + 63) / 64, B_ * H_);
            gemm_kernel<64, 64, 16, 4, 4, true><<<grid, 256>>>(
                qbuf, kvbuf, simbuf, nullptr,
                NTOK, NTOK, DH_, D_, 2 * D_, NTOK,
                (long)NTOK * D_, DH_,
                (long)NTOK * 2 * D_, DH_,
                (long)H_ * NTOK * NTOK, (long)NTOK * NTOK, H_,
                1.0f, 0, 0);
        }

        softmax_self_kernel<<<B_ * H_ * NTOK, 256>>>(simbuf);

        // out[b,i,h*64+d] = attn @ v
        {
            dim3 grid(1, (NTOK + 63) / 64, B_ * H_);
            gemm_kernel<64, 64, 16, 4, 4, false><<<grid, 256>>>(
                simbuf, kvbuf + D_, aobuf, nullptr,
                NTOK, DH_, NTOK, NTOK, 2 * D_, D_,
                (long)H_ * NTOK * NTOK, (long)NTOK * NTOK,
                (long)NTOK * 2 * D_, DH_,
                (long)NTOK * D_, DH_, H_,
                1.0f, 0, 0);
        }

        // tokens = attn_out @ wo + tokens
        gemm_big(aobuf, wo_l, tokens, tokens, ROWS, D_, D_, D_, D_, D_, 1.0f, 0, D_);

        // --- feed-forward block ---
        ln_kernel<<<ROWS, 256>>>(tokens, g_l, hbuf);
        gemm_big(hbuf, w1_l, ff1buf, nullptr, ROWS, FF2_, D_, D_, FF2_, FF2_, 1.0f);
        {
            long total = (long)ROWS * FF_;
            geglu_kernel<<<(int)((total + 255) / 256), 256>>>(ff1buf, actbuf);
        }
        gemm_big(actbuf, w2_l, tokens, tokens, ROWS, D_, FF_, FF_, D_, D_, 1.0f, 0, D_);
    }

    // --- final LN + attention pooling ---
    ln_kernel<<<ROWS, 256>>>(tokens, final_g, hbuf);

    // pool q: [4, D] @ pool_wq, scaled; shared across batches
    gemm_big(ret_tok, pool_wq, qbuf, nullptr, 4, D_, D_, D_, D_, D_, scale);
    // pool kv from final-normed tokens
    gemm_big(hbuf, pool_wkv, kvbuf, nullptr, ROWS, 2 * D_, D_, D_, 2 * D_, 2 * D_, 1.0f);

    // pool sim [b,h,r,j]
    {
        dim3 grid((NTOK + 63) / 64, 1, B_ * H_);
        gemm_kernel<64, 64, 16, 4, 4, true><<<grid, 256>>>(
            qbuf, kvbuf, simbuf, nullptr,
            4, NTOK, DH_, D_, 2 * D_, NTOK,
            0L, DH_,
            (long)NTOK * 2 * D_, DH_,
            (long)H_ * 4 * NTOK, (long)4 * NTOK, H_,
            1.0f, 0, 0);
    }

    softmax_pool_kernel<<<B_ * H_ * 4, 256>>>(simbuf);

    // pool out [b,r,h*64+d] = attn @ v
    {
        dim3 grid(1, 1, B_ * H_);
        gemm_kernel<64, 64, 16, 4, 4, false><<<grid, 256>>>(
            simbuf, kvbuf + D_, aobuf, nullptr,
            4, DH_, NTOK, NTOK, 2 * D_, D_,
            (long)H_ * 4 * NTOK, (long)4 * NTOK,
            (long)NTOK * 2 * D_, DH_,
            (long)4 * D_, DH_, H_,
            1.0f, 0, 0);
    }

    // pooled = pool_out @ pool_wo + return_tokens (broadcast over batch)
    gemm_big(aobuf, pool_wo, out, ret_tok, B_ * 4, D_, D_, D_, D_, D_, 1.0f,
             /*resRowMod=*/4, /*ldres=*/D_);
}

// round 3
// speedup vs baseline: 2.0972x; 2.0972x over previous
#include <cuda_runtime.h>
#include <math.h>
#include <stdint.h>

// ---------------------------------------------------------------------------
// Problem constants
// ---------------------------------------------------------------------------
static constexpr int B_    = 4;
static constexpr int NTOK  = 1040;   // 512 + 512 + 16
static constexpr int D_    = 1024;
static constexpr int H_    = 16;
static constexpr int DH_   = 64;
static constexpr int L_    = 4;
static constexpr int FF_   = 2730;
static constexpr int FF2_  = 5460;
static constexpr int ROWS  = B_ * NTOK;   // 4160

// ---------------------------------------------------------------------------
// Device scratch
// ---------------------------------------------------------------------------
__device__ float g_tokens[B_ * NTOK * D_];
__device__ float g_h     [B_ * NTOK * D_];
__device__ float g_q     [B_ * NTOK * D_];
__device__ float g_kv    [B_ * NTOK * 2 * D_];
__device__ float g_sim   [(long long)B_ * H_ * NTOK * NTOK];
__device__ float g_ao    [B_ * NTOK * D_];
__device__ float g_ff1   [(long long)ROWS * FF2_];
__device__ float g_act   [(long long)ROWS * FF_];

// ---------------------------------------------------------------------------
// tf32 helpers
// ---------------------------------------------------------------------------
__device__ __forceinline__ uint32_t f2tf32(float f) {
    uint32_t r;
    asm("cvt.rna.tf32.f32 %0, %1;" : "=r"(r) : "f"(f));
    return r;
}

__device__ __forceinline__ void mma_tf32(float* c, const uint32_t* a, const uint32_t* b) {
    asm volatile(
        "mma.sync.aligned.m16n8k8.row.col.f32.tf32.tf32.f32 "
        "{%0,%1,%2,%3}, {%4,%5,%6,%7}, {%8,%9}, {%0,%1,%2,%3};"
        : "+f"(c[0]), "+f"(c[1]), "+f"(c[2]), "+f"(c[3])
        : "r"(a[0]), "r"(a[1]), "r"(a[2]), "r"(a[3]), "r"(b[0]), "r"(b[1]));
}

// ---------------------------------------------------------------------------
// tf32 mma.sync GEMM.  C[M,N] = alpha * A[M,K] @ B (+Res)
//   TRANSW=true : B global is [K,N] row-major  (weights, V)
//   TRANSW=false: B global is [N,K] row-major  (QK: C = A @ B^T)
// BM=128, BK=32, 256 threads. Warp tile WTM x WTN.
// All strides/pointers assumed float2-aligned (all dims even in this problem).
// Batched via z = zb*Hdiv + zh.
// ---------------------------------------------------------------------------
template<int BN, int WTM, int WTN, bool TRANSW>
__global__ void __launch_bounds__(256)
mma_gemm(const float* __restrict__ A, const float* __restrict__ Bm,
         float* __restrict__ C, const float* __restrict__ Res,
         int M, int N, int K, int lda, int ldb, int ldc,
         long sAb, long sAh, long sBb, long sBh, long sCb, long sCh, int Hdiv,
         float alpha, int resRowMod, int ldres) {
    constexpr int WN = BN / WTN;          // warps along N
    constexpr int MT = WTM / 16;
    constexpr int NT = WTN / 8;
    constexpr int A_W = 32 * 136;         // words per A buffer (BK x (128+8))
    constexpr int B_W = 32 * (BN + 8);
    constexpr int RB  = BN / 16;          // float2 B-loads per thread

    extern __shared__ __align__(16) uint32_t smu[];

    const int tid = threadIdx.x;
    const int wid = tid >> 5;
    const int lane = tid & 31;
    const int g  = lane >> 2;
    const int t4 = lane & 3;
    const int wm = wid / WN;
    const int wn = wid % WN;

    int z = blockIdx.z;
    int zb = z / Hdiv, zh = z - zb * Hdiv;
    A   += (long)zb * sAb + (long)zh * sAh;
    Bm  += (long)zb * sBb + (long)zh * sBh;
    C   += (long)zb * sCb + (long)zh * sCh;

    const int rowBase = blockIdx.y * 128;
    const int colBase = blockIdx.x * BN;

    float acc[MT][NT][4];
    #pragma unroll
    for (int i = 0; i < MT; i++)
        #pragma unroll
        for (int j = 0; j < NT; j++)
            #pragma unroll
            for (int q = 0; q < 4; q++) acc[i][j][q] = 0.0f;

    const int KC = (K + 31) >> 5;

    float2 ra[8];
    float2 rb[RB];

    auto ld_global = [&](int c) {
        const int k0 = c << 5;
        #pragma unroll
        for (int e = 0; e < 8; e++) {
            int idx = tid + e * 256;
            int m = idx >> 4, k2 = idx & 15;
            int gr = rowBase + m, gk = k0 + k2 * 2;
            ra[e] = make_float2(0.f, 0.f);
            if (gr < M && gk < K) ra[e] = *(const float2*)(A + (long)gr * lda + gk);
        }
        if (TRANSW) {
            #pragma unroll
            for (int e = 0; e < RB; e++) {
                int idx = tid + e * 256;
                int n2 = idx & (BN / 2 - 1), kk = idx / (BN / 2);
                int gk = k0 + kk, gn = colBase + n2 * 2;
                rb[e] = make_float2(0.f, 0.f);
                if (gk < K && gn < N) rb[e] = *(const float2*)(Bm + (long)gk * ldb + gn);
            }
        } else {
            #pragma unroll
            for (int e = 0; e < RB; e++) {
                int idx = tid + e * 256;
                int n = idx >> 4, k2 = idx & 15;
                int gn = colBase + n, gk = k0 + k2 * 2;
                rb[e] = make_float2(0.f, 0.f);
                if (gn < N && gk < K) rb[e] = *(const float2*)(Bm + (long)gn * ldb + gk);
            }
        }
    };

    auto sts = [&](int buf) {
        uint32_t* Ad = smu + buf * A_W;
        #pragma unroll
        for (int e = 0; e < 8; e++) {
            int idx = tid + e * 256;
            int m = idx >> 4, k2 = idx & 15;
            Ad[(k2 * 2)     * 136 + m] = f2tf32(ra[e].x);
            Ad[(k2 * 2 + 1) * 136 + m] = f2tf32(ra[e].y);
        }
        uint32_t* Bd = smu + 2 * A_W + buf * B_W;
        if (TRANSW) {
            #pragma unroll
            for (int e = 0; e < RB; e++) {
                int idx = tid + e * 256;
                int n2 = idx & (BN / 2 - 1), kk = idx / (BN / 2);
                Bd[kk * (BN + 8) + n2 * 2]     = f2tf32(rb[e].x);
                Bd[kk * (BN + 8) + n2 * 2 + 1] = f2tf32(rb[e].y);
            }
        } else {
            #pragma unroll
            for (int e = 0; e < RB; e++) {
                int idx = tid + e * 256;
                int n = idx >> 4, k2 = idx & 15;
                Bd[(k2 * 2)     * (BN + 8) + n] = f2tf32(rb[e].x);
                Bd[(k2 * 2 + 1) * (BN + 8) + n] = f2tf32(rb[e].y);
            }
        }
    };

    ld_global(0);
    sts(0);
    __syncthreads();

    for (int c = 0; c < KC; c++) {
        int cur = c & 1;
        if (c + 1 < KC) ld_global(c + 1);     // LDGs in flight during MMA

        const uint32_t* Ab = smu + cur * A_W;
        const uint32_t* Bb = smu + 2 * A_W + cur * B_W;

        #pragma unroll
        for (int ks = 0; ks < 4; ks++) {
            const int kk = ks * 8;
            uint32_t af[MT][4], bf[NT][2];
            #pragma unroll
            for (int mt = 0; mt < MT; mt++) {
                int m = wm * WTM + mt * 16 + g;
                af[mt][0] = Ab[(kk + t4)     * 136 + m];
                af[mt][1] = Ab[(kk + t4)     * 136 + m + 8];
                af[mt][2] = Ab[(kk + 4 + t4) * 136 + m];
                af[mt][3] = Ab[(kk + 4 + t4) * 136 + m + 8];
            }
            #pragma unroll
            for (int nt = 0; nt < NT; nt++) {
                int n = wn * WTN + nt * 8 + g;
                bf[nt][0] = Bb[(kk + t4)     * (BN + 8) + n];
                bf[nt][1] = Bb[(kk + 4 + t4) * (BN + 8) + n];
            }
            #pragma unroll
            for (int mt = 0; mt < MT; mt++)
                #pragma unroll
                for (int nt = 0; nt < NT; nt++)
                    mma_tf32(acc[mt][nt], af[mt], bf[nt]);
        }
        __syncthreads();
        if (c + 1 < KC) {
            sts((c + 1) & 1);
        }
        __syncthreads();
    }

    // Epilogue: direct float2 stores
    #pragma unroll
    for (int mt = 0; mt < MT; mt++) {
        int r0 = rowBase + wm * WTM + mt * 16 + g;
        #pragma unroll
        for (int nt = 0; nt < NT; nt++) {
            int col = colBase + wn * WTN + nt * 8 + t4 * 2;
            if (col >= N) continue;
            #pragma unroll
            for (int hh = 0; hh < 2; hh++) {
                int rr = r0 + hh * 8;
                if (rr >= M) continue;
                float2 v;
                v.x = alpha * acc[mt][nt][hh * 2];
                v.y = alpha * acc[mt][nt][hh * 2 + 1];
                if (Res) {
                    int rx = resRowMod ? (rr % resRowMod) : rr;
                    float2 rv = *(const float2*)(Res + (long)rx * ldres + col);
                    v.x += rv.x; v.y += rv.y;
                }
                *(float2*)(C + (long)rr * ldc + col) = v;
            }
        }
    }
}

// ---------------------------------------------------------------------------
// Small SIMT GEMM (tiny pool launches)
// ---------------------------------------------------------------------------
template<int BM, int BN, int BK, int TM, int TN, bool TB>
__global__ void __launch_bounds__((BM / TM) * (BN / TN))
gemm_kernel(const float* __restrict__ A, const float* __restrict__ Bm,
            float* __restrict__ C, const float* __restrict__ Res,
            int M, int Nn, int K,
            int lda, int ldb, int ldc,
            long sAb, long sAh, long sBb, long sBh, long sCb, long sCh, int Hdiv,
            float alpha, int resRowMod, int ldres) {
    constexpr int THREADS = (BM / TM) * (BN / TN);
    constexpr int AELEM = BM * BK / THREADS;
    constexpr int BELEM = BK * BN / THREADS;

    int z = blockIdx.z;
    int zb = z / Hdiv, zh = z - zb * Hdiv;
    A  += (long)zb * sAb + (long)zh * sAh;
    Bm += (long)zb * sBb + (long)zh * sBh;
    C  += (long)zb * sCb + (long)zh * sCh;

    __shared__ __align__(16) float As[BK][BM + 4];
    __shared__ __align__(16) float Bs[BK][BN + 4];

    int tid = threadIdx.x;
    int tcol = tid % (BN / TN);
    int trow = tid / (BN / TN);
    int rowBase = blockIdx.y * BM;
    int colBase = blockIdx.x * BN;

    float acc[TM][TN] = {};

    for (int k0 = 0; k0 < K; k0 += BK) {
        #pragma unroll
        for (int e = 0; e < AELEM; e++) {
            int idx = tid + e * THREADS;
            int m = idx / BK, kk = idx % BK;
            int gr = rowBase + m, gc = k0 + kk;
            As[kk][m] = (gr < M && gc < K) ? A[(long)gr * lda + gc] : 0.0f;
        }
        #pragma unroll
        for (int e = 0; e < BELEM; e++) {
            int idx = tid + e * THREADS;
            int kk, n;
            if (!TB) { kk = idx / BN; n = idx % BN; }
            else     { n = idx / BK;  kk = idx % BK; }
            int gc = colBase + n, gk = k0 + kk;
            float v = 0.0f;
            if (gc < Nn && gk < K)
                v = TB ? Bm[(long)gc * ldb + gk] : Bm[(long)gk * ldb + gc];
            Bs[kk][n] = v;
        }
        __syncthreads();

        #pragma unroll
        for (int kk = 0; kk < BK; kk++) {
            float a[TM], bb[TN];
            #pragma unroll
            for (int i = 0; i < TM; i++) a[i] = As[kk][trow * TM + i];
            #pragma unroll
            for (int j = 0; j < TN; j++) bb[j] = Bs[kk][tcol * TN + j];
            #pragma unroll
            for (int i = 0; i < TM; i++)
                #pragma unroll
                for (int j = 0; j < TN; j++)
                    acc[i][j] += a[i] * bb[j];
        }
        __syncthreads();
    }

    #pragma unroll
    for (int i = 0; i < TM; i++) {
        int r = rowBase + trow * TM + i;
        if (r >= M) continue;
        #pragma unroll
        for (int j = 0; j < TN; j++) {
            int c = colBase + tcol * TN + j;
            if (c >= Nn) continue;
            float v = alpha * acc[i][j];
            if (Res) {
                int rr = resRowMod ? (r % resRowMod) : r;
                v += Res[(long)rr * ldres + c];
            }
            C[(long)r * ldc + c] = v;
        }
    }
}

// ---------------------------------------------------------------------------
// Elementwise / reduction kernels
// ---------------------------------------------------------------------------
__device__ __forceinline__ float blk_reduce(float v, bool ismax) {
    __shared__ float red[9];
    #pragma unroll
    for (int o = 16; o; o >>= 1) {
        float u = __shfl_xor_sync(0xffffffffu, v, o);
        v = ismax ? fmaxf(v, u) : (v + u);
    }
    if ((threadIdx.x & 31) == 0) red[threadIdx.x >> 5] = v;
    __syncthreads();
    if (threadIdx.x == 0) {
        float r = red[0];
        int nw = blockDim.x >> 5;
        for (int w = 1; w < nw; w++) r = ismax ? fmaxf(r, red[w]) : (r + red[w]);
        red[8] = r;
    }
    __syncthreads();
    float r = red[8];
    __syncthreads();
    return r;
}

__device__ __forceinline__ int token_type(int j) {
    return j < 512 ? 0 : (j < 1024 ? 1 : 2);
}

__global__ void concat_kernel(const float4* __restrict__ m0,
                              const float4* __restrict__ m1,
                              const float4* __restrict__ fus,
                              float4* __restrict__ tokens) {
    int idx = blockIdx.x * blockDim.x + threadIdx.x;
    const int D4 = D_ / 4;
    int total = B_ * NTOK * D4;
    if (idx >= total) return;
    int d = idx % D4;
    int t = (idx / D4) % NTOK;
    int b = idx / (D4 * NTOK);
    float4 v;
    if (t < 512)       v = m0[((long)b * 512 + t) * D4 + d];
    else if (t < 1024) v = m1[((long)b * 512 + (t - 512)) * D4 + d];
    else               v = fus[(long)(t - 1024) * D4 + d];
    tokens[idx] = v;
}

__global__ void ln_kernel(const float* __restrict__ x,
                          const float* __restrict__ gamma,
                          float* __restrict__ out) {
    long row = blockIdx.x;
    const float4* xr = (const float4*)(x + row * D_);
    float4 v = xr[threadIdx.x];
    float s = v.x + v.y + v.z + v.w;
    float mean = blk_reduce(s, false) * (1.0f / D_);
    float dx = v.x - mean, dy = v.y - mean, dz = v.z - mean, dw = v.w - mean;
    float s2 = dx * dx + dy * dy + dz * dz + dw * dw;
    float var = blk_reduce(s2, false) * (1.0f / D_);
    float inv = rsqrtf(var + 1e-5f);
    float4 g = ((const float4*)gamma)[threadIdx.x];
    float4 o;
    o.x = dx * inv * g.x; o.y = dy * inv * g.y;
    o.z = dz * inv * g.z; o.w = dw * inv * g.w;
    ((float4*)(out + row * D_))[threadIdx.x] = o;
}

__global__ void softmax_self_kernel(float* __restrict__ sim) {
    long row = blockIdx.x;
    float* p = sim + row * NTOK;
    int i = (int)(row % NTOK);
    int ti = token_type(i);
    int tid = threadIdx.x;

    float vals[5];
    float mx = -3.4e38f;
    #pragma unroll
    for (int it = 0; it < 5; it++) {
        int j = tid + it * 256;
        float v = -3.4e38f;
        if (j < NTOK) {
            bool ok = (ti == 2) || (token_type(j) == ti);
            v = ok ? p[j] : -3.4e38f;
        }
        vals[it] = v;
        mx = fmaxf(mx, v);
    }
    mx = blk_reduce(mx, true);

    float e[5];
    float s = 0.0f;
    #pragma unroll
    for (int it = 0; it < 5; it++) {
        float ex = __expf(vals[it] - mx);
        e[it] = ex;
        s += ex;
    }
    s = blk_reduce(s, false);
    float inv = 1.0f / s;
    #pragma unroll
    for (int it = 0; it < 5; it++) {
        int j = tid + it * 256;
        if (j < NTOK) p[j] = e[it] * inv;
    }
}

__global__ void softmax_pool_kernel(float* __restrict__ sim) {
    long row = blockIdx.x;
    float* p = sim + row * NTOK;
    int r = (int)(row % 4);
    int tid = threadIdx.x;

    float vals[5];
    float mx = -3.4e38f;
    #pragma unroll
    for (int it = 0; it < 5; it++) {
        int j = tid + it * 256;
        float v = -3.4e38f;
        if (j < NTOK) {
            bool ok = (r == 3) || (token_type(j) == r);
            v = ok ? p[j] : -3.4e38f;
        }
        vals[it] = v;
        mx = fmaxf(mx, v);
    }
    mx = blk_reduce(mx, true);

    float e[5];
    float s = 0.0f;
    #pragma unroll
    for (int it = 0; it < 5; it++) {
        float ex = __expf(vals[it] - mx);
        e[it] = ex;
        s += ex;
    }
    s = blk_reduce(s, false);
    float inv = 1.0f / s;
    #pragma unroll
    for (int it = 0; it < 5; it++) {
        int j = tid + it * 256;
        if (j < NTOK) p[j] = e[it] * inv;
    }
}

__global__ void geglu_kernel(const float* __restrict__ ff1,
                             float* __restrict__ act) {
    long idx = (long)blockIdx.x * blockDim.x + threadIdx.x;
    long total = (long)ROWS * FF_;
    if (idx >= total) return;
    long row = idx / FF_;
    int f = (int)(idx - row * FF_);
    const float* p = ff1 + row * FF2_;
    float val = p[f];
    float gate = p[FF_ + f];
    float g = 0.5f * gate * (1.0f + erff(gate * 0.70710678118654752f));
    act[idx] = g * val;
}

// ---------------------------------------------------------------------------
// Host side
// ---------------------------------------------------------------------------
static constexpr int A_WORDS = 32 * 136;
static constexpr int SMEM_MMA128 = (2 * A_WORDS + 2 * 32 * 136) * 4;  // 69632
static constexpr int SMEM_MMA64  = (2 * A_WORDS + 2 * 32 * 72) * 4;   // 53248

static inline void tcw(const float* A, const float* B, float* C, const float* Res,
                       int M, int Nn, int K, int lda, int ldb, int ldc, float alpha,
                       int resRowMod = 0, int ldres = 0) {
    dim3 grid((Nn + 127) / 128, (M + 127) / 128, 1);
    mma_gemm<128, 64, 32, true><<<grid, 256, SMEM_MMA128>>>(
        A, B, C, Res, M, Nn, K, lda, ldb, ldc,
        0, 0, 0, 0, 0, 0, 1, alpha, resRowMod, ldres);
}

static inline void gemm_small(const float* A, const float* B, float* C,
                              const float* Res, int M, int Nn, int K,
                              int lda, int ldb, int ldc, float alpha,
                              int resRowMod = 0, int ldres = 0) {
    dim3 grid((Nn + 63) / 64, (M + 63) / 64, 1);
    gemm_kernel<64, 64, 16, 4, 4, false><<<grid, 256>>>(
        A, B, C, Res, M, Nn, K, lda, ldb, ldc,
        0, 0, 0, 0, 0, 0, 1, alpha, resRowMod, ldres);
}

extern "C" void kernel_launch(void* const* d_in, const int* in_sizes, int n_in,
                              void* d_out, int out_size) {
    const float* m0        = (const float*)d_in[0];
    const float* m1        = (const float*)d_in[1];
    const float* fusion    = (const float*)d_in[2];
    const float* ret_tok   = (const float*)d_in[3];
    const float* ln_gamma  = (const float*)d_in[4];
    const float* wq        = (const float*)d_in[5];
    const float* wkv       = (const float*)d_in[6];
    const float* wo        = (const float*)d_in[7];
    const float* ff_w1     = (const float*)d_in[8];
    const float* ff_w2     = (const float*)d_in[9];
    const float* pool_wq   = (const float*)d_in[10];
    const float* pool_wkv  = (const float*)d_in[11];
    const float* pool_wo   = (const float*)d_in[12];
    const float* final_g   = (const float*)d_in[13];
    float* out = (float*)d_out;

    cudaFuncSetAttribute(mma_gemm<128, 64, 32, true>,
                         cudaFuncAttributeMaxDynamicSharedMemorySize, SMEM_MMA128);
    cudaFuncSetAttribute(mma_gemm<128, 64, 32, false>,
                         cudaFuncAttributeMaxDynamicSharedMemorySize, SMEM_MMA128);
    cudaFuncSetAttribute(mma_gemm<64, 32, 32, true>,
                         cudaFuncAttributeMaxDynamicSharedMemorySize, SMEM_MMA64);

    float *tokens, *hbuf, *qbuf, *kvbuf, *simbuf, *aobuf, *ff1buf, *actbuf;
    cudaGetSymbolAddress((void**)&tokens, g_tokens);
    cudaGetSymbolAddress((void**)&hbuf,   g_h);
    cudaGetSymbolAddress((void**)&qbuf,   g_q);
    cudaGetSymbolAddress((void**)&kvbuf,  g_kv);
    cudaGetSymbolAddress((void**)&simbuf, g_sim);
    cudaGetSymbolAddress((void**)&aobuf,  g_ao);
    cudaGetSymbolAddress((void**)&ff1buf, g_ff1);
    cudaGetSymbolAddress((void**)&actbuf, g_act);

    {
        int total = B_ * NTOK * (D_ / 4);
        concat_kernel<<<(total + 255) / 256, 256>>>(
            (const float4*)m0, (const float4*)m1, (const float4*)fusion,
            (float4*)tokens);
    }

    const float scale = 0.125f;

    for (int l = 0; l < L_; l++) {
        const float* wq_l  = wq    + (long)l * D_ * D_;
        const float* wkv_l = wkv   + (long)l * D_ * 2 * D_;
        const float* wo_l  = wo    + (long)l * D_ * D_;
        const float* w1_l  = ff_w1 + (long)l * D_ * FF2_;
        const float* w2_l  = ff_w2 + (long)l * FF_ * D_;
        const float* g_l   = ln_gamma + (long)l * D_;

        ln_kernel<<<ROWS, 256>>>(tokens, g_l, hbuf);
        tcw(hbuf, wq_l,  qbuf,  nullptr, ROWS, D_,     D_, D_, D_,     D_,     scale);
        tcw(hbuf, wkv_l, kvbuf, nullptr, ROWS, 2 * D_, D_, D_, 2 * D_, 2 * D_, 1.0f);

        // sim[b,h,i,j] = q . k   (B is [N,K] with K contiguous -> TRANSW=false)
        {
            dim3 grid((NTOK + 127) / 128, (NTOK + 127) / 128, B_ * H_);
            mma_gemm<128, 64, 32, false><<<grid, 256, SMEM_MMA128>>>(
                qbuf, kvbuf, simbuf, nullptr,
                NTOK, NTOK, DH_, D_, 2 * D_, NTOK,
                (long)NTOK * D_, DH_,
                (long)NTOK * 2 * D_, DH_,
                (long)H_ * NTOK * NTOK, (long)NTOK * NTOK, H_,
                1.0f, 0, 0);
        }

        softmax_self_kernel<<<B_ * H_ * NTOK, 256>>>(simbuf);

        // ao[b,i,h*64+d] = attn @ v   (V is [K,N] -> TRANSW=true, BN=64)
        {
            dim3 grid(1, (NTOK + 127) / 128, B_ * H_);
            mma_gemm<64, 32, 32, true><<<grid, 256, SMEM_MMA64>>>(
                simbuf, kvbuf + D_, aobuf, nullptr,
                NTOK, DH_, NTOK, NTOK, 2 * D_, D_,
                (long)H_ * NTOK * NTOK, (long)NTOK * NTOK,
                (long)NTOK * 2 * D_, DH_,
                (long)NTOK * D_, DH_, H_,
                1.0f, 0, 0);
        }

        tcw(aobuf, wo_l, tokens, tokens, ROWS, D_, D_, D_, D_, D_, 1.0f, 0, D_);

        ln_kernel<<<ROWS, 256>>>(tokens, g_l, hbuf);
        tcw(hbuf, w1_l, ff1buf, nullptr, ROWS, FF2_, D_, D_, FF2_, FF2_, 1.0f);
        {
            long total = (long)ROWS * FF_;
            geglu_kernel<<<(int)((total + 255) / 256), 256>>>(ff1buf, actbuf);
        }
        tcw(actbuf, w2_l, tokens, tokens, ROWS, D_, FF_, FF_, D_, D_, 1.0f, 0, D_);
    }

    // --- final LN + attention pooling ---
    ln_kernel<<<ROWS, 256>>>(tokens, final_g, hbuf);

    gemm_small(ret_tok, pool_wq, qbuf, nullptr, 4, D_, D_, D_, D_, D_, scale);
    tcw(hbuf, pool_wkv, kvbuf, nullptr, ROWS, 2 * D_, D_, D_, 2 * D_, 2 * D_, 1.0f);

    // pool sim [b,h,r,j]
    {
        dim3 grid((NTOK + 63) / 64, 1, B_ * H_);
        gemm_kernel<64, 64, 16, 4, 4, true><<<grid, 256>>>(
            qbuf, kvbuf, simbuf, nullptr,
            4, NTOK, DH_, D_, 2 * D_, NTOK,
            0L, DH_,
            (long)NTOK * 2 * D_, DH_,
            (long)H_ * 4 * NTOK, (long)4 * NTOK, H_,
            1.0f, 0, 0);
    }

    softmax_pool_kernel<<<B_ * H_ * 4, 256>>>(simbuf);

    // pool out [b,r,h*64+d] = attn @ v
    {
        dim3 grid(1, 1, B_ * H_);
        gemm_kernel<64, 64, 16, 4, 4, false><<<grid, 256>>>(
            simbuf, kvbuf + D_, aobuf, nullptr,
            4, DH_, NTOK, NTOK, 2 * D_, D_,
            (long)H_ * 4 * NTOK, (long)4 * NTOK,
            (long)NTOK * 2 * D_, DH_,
            (long)4 * D_, DH_, H_,
            1.0f, 0, 0);
    }

    gemm_small(aobuf, pool_wo, out, ret_tok, B_ * 4, D_, D_, D_, D_, D_, 1.0f,
               /*resRowMod=*/4, /*ldres=*/D_);
}

// round 4
// speedup vs baseline: 3.5892x; 1.7115x over previous
#include <cuda_runtime.h>
#include <math.h>
#include <stdint.h>

// ---------------------------------------------------------------------------
// Problem constants
// ---------------------------------------------------------------------------
static constexpr int B_    = 4;
static constexpr int NTOK  = 1040;   // 512 + 512 + 16
static constexpr int D_    = 1024;
static constexpr int H_    = 16;
static constexpr int DH_   = 64;
static constexpr int L_    = 4;
static constexpr int FF_   = 2730;
static constexpr int FF2_  = 5460;
static constexpr int ROWS  = B_ * NTOK;   // 4160
static constexpr int ACTLD = 2732;        // padded act row stride (16B-aligned rows)

// ---------------------------------------------------------------------------
// Device scratch
// ---------------------------------------------------------------------------
__device__ float g_tokens[B_ * NTOK * D_];
__device__ float g_h     [B_ * NTOK * D_];
__device__ float g_q     [B_ * NTOK * D_];
__device__ float g_kv    [B_ * NTOK * 2 * D_];
__device__ float g_sim   [(long long)B_ * H_ * NTOK * NTOK];
__device__ float g_ao    [B_ * NTOK * D_];
__device__ float g_ff1   [(long long)ROWS * FF2_];
__device__ float g_act   [(long long)ROWS * ACTLD];

// ---------------------------------------------------------------------------
// Helpers
// ---------------------------------------------------------------------------
__device__ __forceinline__ uint32_t smem_u32(const void* p) {
    uint32_t a;
    asm("{ .reg .u64 t; cvta.to.shared.u64 t, %1; cvt.u32.u64 %0, t; }"
        : "=r"(a) : "l"(p));
    return a;
}

__device__ __forceinline__ void mma_tf32(float* c, const uint32_t* a, const uint32_t* b) {
    asm volatile(
        "mma.sync.aligned.m16n8k8.row.col.f32.tf32.tf32.f32 "
        "{%0,%1,%2,%3}, {%4,%5,%6,%7}, {%8,%9}, {%0,%1,%2,%3};"
        : "+f"(c[0]), "+f"(c[1]), "+f"(c[2]), "+f"(c[3])
        : "r"(a[0]), "r"(a[1]), "r"(a[2]), "r"(a[3]), "r"(b[0]), "r"(b[1]));
}

__device__ __forceinline__ void cp16(uint32_t dst, const float* src, int bytes) {
    asm volatile("cp.async.cg.shared.global [%0], [%1], 16, %2;"
                 :: "r"(dst), "l"(src), "r"(bytes));
}
#define CP_COMMIT() asm volatile("cp.async.commit_group;" ::: "memory")
#define CP_WAIT1()  asm volatile("cp.async.wait_group 1;" ::: "memory")

// ---------------------------------------------------------------------------
// tf32 mma.sync GEMM with 3-stage cp.async pipeline.
//   C[M,N] = alpha * A[M,K] @ B (+Res)
//   TRANSW=true : B global is [K,N] row-major (weights, V)
//   TRANSW=false: B global is [N,K] row-major (QK: C = A @ B^T)
// BM=128, BK=32, 256 threads. fp32 fed directly to tf32 MMA (HW truncates).
// Batched via z = zb*Hdiv + zh.
// ---------------------------------------------------------------------------
template<int BN, int WTM, int WTN, bool TRANSW>
__global__ void __launch_bounds__(256)
mma_gemm(const float* __restrict__ A, const float* __restrict__ Bm,
         float* __restrict__ C, const float* __restrict__ Res,
         int M, int N, int K, int lda, int ldb, int ldc,
         long sAb, long sAh, long sBb, long sBh, long sCb, long sCh, int Hdiv,
         float alpha, int resRowMod, int ldres) {
    constexpr int WN = BN / WTN;
    constexpr int MT = WTM / 16;
    constexpr int NT = WTN / 8;
    constexpr int A_ST_W = 128 * 36;                       // A stage words
    constexpr int B_ST_W = TRANSW ? 32 * (BN + 8) : BN * 36;
    constexpr int ST_W   = A_ST_W + B_ST_W;
    constexpr int BE     = TRANSW ? (BN / 32) : 4;          // B chunks / thread

    extern __shared__ __align__(16) float smem[];
    const uint32_t sb = smem_u32(smem);

    const int tid = threadIdx.x;
    const int wid = tid >> 5, lane = tid & 31;
    const int g = lane >> 2, t4 = lane & 3;
    const int wm = wid / WN, wn = wid % WN;

    int z = blockIdx.z;
    int zb = z / Hdiv, zh = z - zb * Hdiv;
    A  += (long)zb * sAb + (long)zh * sAh;
    Bm += (long)zb * sBb + (long)zh * sBh;
    C  += (long)zb * sCb + (long)zh * sCh;

    const int rowBase = blockIdx.y * 128;
    const int colBase = blockIdx.x * BN;
    const int KC = (K + 31) >> 5;

    // ---- A producer state: 4 chunks/thread, fixed 16B-column, 4 rows ----
    const int chA = tid & 7;
    const float* aSrc[4];
    uint32_t aOff[4];
    bool aOk[4];
    #pragma unroll
    for (int e = 0; e < 4; e++) {
        int m = (tid >> 3) + 32 * e;
        int gr = rowBase + m;
        aOk[e] = gr < M;
        aSrc[e] = A + (long)(aOk[e] ? gr : 0) * lda + chA * 4;
        aOff[e] = (uint32_t)(m * 144 + chA * 16);
    }

    // ---- B producer state ----
    const float* bSrc[BE];
    uint32_t bOff[BE];
    int bCB[BE];     // TRANSW: column bytes; !TRANSW: row-ok flag
    int bKK[BE];     // TRANSW: k-row within chunk
    if (TRANSW) {
        const int chB = tid & (BN / 4 - 1);
        #pragma unroll
        for (int e = 0; e < BE; e++) {
            int kk = tid / (BN / 4) + (256 / (BN / 4)) * e;
            int gn = colBase + chB * 4;
            int cb = (N - gn) * 4;
            cb = cb < 0 ? 0 : (cb > 16 ? 16 : cb);
            bCB[e] = cb;
            bKK[e] = kk;
            bSrc[e] = Bm + (long)kk * ldb + (cb ? gn : 0);
            bOff[e] = (uint32_t)(kk * (BN + 8) * 4 + chB * 16);
        }
    } else {
        #pragma unroll
        for (int e = 0; e < BE; e++) {
            int n = (tid >> 3) + 32 * e;
            int gn = colBase + n;
            bCB[e] = (gn < N) ? 1 : 0;
            bSrc[e] = Bm + (long)(bCB[e] ? gn : 0) * ldb + chA * 4;
            bOff[e] = (uint32_t)(n * 144 + chA * 16);
        }
    }

    auto issue = [&](int c, int st) {
        const uint32_t stb = sb + (uint32_t)(st * ST_W * 4);
        int krem = K - (c << 5);
        int kb = (krem - chA * 4) * 4;
        kb = kb < 0 ? 0 : (kb > 16 ? 16 : kb);
        #pragma unroll
        for (int e = 0; e < 4; e++) {
            int bytes = aOk[e] ? kb : 0;
            cp16(stb + aOff[e], bytes ? aSrc[e] : A, bytes);
            aSrc[e] += 32;
        }
        const uint32_t bstb = stb + (uint32_t)(A_ST_W * 4);
        if (TRANSW) {
            #pragma unroll
            for (int e = 0; e < BE; e++) {
                int bytes = (bKK[e] < krem) ? bCB[e] : 0;
                cp16(bstb + bOff[e], bytes ? bSrc[e] : Bm, bytes);
                bSrc[e] += (long)32 * ldb;
            }
        } else {
            #pragma unroll
            for (int e = 0; e < BE; e++) {
                int bytes = bCB[e] ? kb : 0;
                cp16(bstb + bOff[e], bytes ? bSrc[e] : Bm, bytes);
                bSrc[e] += 32;
            }
        }
        CP_COMMIT();
    };

    float acc[MT][NT][4];
    #pragma unroll
    for (int i = 0; i < MT; i++)
        #pragma unroll
        for (int j = 0; j < NT; j++)
            #pragma unroll
            for (int q = 0; q < 4; q++) acc[i][j][q] = 0.0f;

    // fragment smem bases (word indices)
    const int aB = (wm * WTM + g) * 36 + t4;
    const int bB = TRANSW ? (t4 * (BN + 8) + wn * WTN + g)
                          : ((wn * WTN + g) * 36 + t4);

    issue(0, 0);
    issue(1, 1);

    int st = 0;
    for (int c = 0; c < KC; c++) {
        CP_WAIT1();
        __syncthreads();
        if (c + 2 < KC) issue(c + 2, (st + 2) % 3);
        else CP_COMMIT();

        const uint32_t* Aw = (const uint32_t*)smem + st * ST_W;
        const uint32_t* Bw = Aw + A_ST_W;

        #pragma unroll
        for (int ks = 0; ks < 4; ks++) {
            uint32_t af[MT][4], bf[NT][2];
            #pragma unroll
            for (int mt = 0; mt < MT; mt++) {
                int base = aB + mt * 576 + ks * 8;
                af[mt][0] = Aw[base];
                af[mt][1] = Aw[base + 288];
                af[mt][2] = Aw[base + 4];
                af[mt][3] = Aw[base + 292];
            }
            #pragma unroll
            for (int nt = 0; nt < NT; nt++) {
                if (TRANSW) {
                    int base = bB + ks * 8 * (BN + 8) + nt * 8;
                    bf[nt][0] = Bw[base];
                    bf[nt][1] = Bw[base + 4 * (BN + 8)];
                } else {
                    int base = bB + nt * 8 * 36 + ks * 8;
                    bf[nt][0] = Bw[base];
                    bf[nt][1] = Bw[base + 4];
                }
            }
            #pragma unroll
            for (int mt = 0; mt < MT; mt++)
                #pragma unroll
                for (int nt = 0; nt < NT; nt++)
                    mma_tf32(acc[mt][nt], af[mt], bf[nt]);
        }
        st++; if (st == 3) st = 0;
    }

    // Epilogue: direct float2 stores
    #pragma unroll
    for (int mt = 0; mt < MT; mt++) {
        int r0 = rowBase + wm * WTM + mt * 16 + g;
        #pragma unroll
        for (int nt = 0; nt < NT; nt++) {
            int col = colBase + wn * WTN + nt * 8 + t4 * 2;
            if (col >= N) continue;
            #pragma unroll
            for (int hh = 0; hh < 2; hh++) {
                int rr = r0 + hh * 8;
                if (rr >= M) continue;
                float2 v;
                v.x = alpha * acc[mt][nt][hh * 2];
                v.y = alpha * acc[mt][nt][hh * 2 + 1];
                if (Res) {
                    int rx = resRowMod ? (rr % resRowMod) : rr;
                    float2 rv = *(const float2*)(Res + (long)rx * ldres + col);
                    v.x += rv.x; v.y += rv.y;
                }
                *(float2*)(C + (long)rr * ldc + col) = v;
            }
        }
    }
}

// ---------------------------------------------------------------------------
// Small SIMT GEMM (tiny pool launches)
// ---------------------------------------------------------------------------
template<int BM, int BN, int BK, int TM, int TN, bool TB>
__global__ void __launch_bounds__((BM / TM) * (BN / TN))
gemm_kernel(const float* __restrict__ A, const float* __restrict__ Bm,
            float* __restrict__ C, const float* __restrict__ Res,
            int M, int Nn, int K,
            int lda, int ldb, int ldc,
            long sAb, long sAh, long sBb, long sBh, long sCb, long sCh, int Hdiv,
            float alpha, int resRowMod, int ldres) {
    constexpr int THREADS = (BM / TM) * (BN / TN);
    constexpr int AELEM = BM * BK / THREADS;
    constexpr int BELEM = BK * BN / THREADS;

    int z = blockIdx.z;
    int zb = z / Hdiv, zh = z - zb * Hdiv;
    A  += (long)zb * sAb + (long)zh * sAh;
    Bm += (long)zb * sBb + (long)zh * sBh;
    C  += (long)zb * sCb + (long)zh * sCh;

    __shared__ __align__(16) float As[BK][BM + 4];
    __shared__ __align__(16) float Bs[BK][BN + 4];

    int tid = threadIdx.x;
    int tcol = tid % (BN / TN);
    int trow = tid / (BN / TN);
    int rowBase = blockIdx.y * BM;
    int colBase = blockIdx.x * BN;

    float acc[TM][TN] = {};

    for (int k0 = 0; k0 < K; k0 += BK) {
        #pragma unroll
        for (int e = 0; e < AELEM; e++) {
            int idx = tid + e * THREADS;
            int m = idx / BK, kk = idx % BK;
            int gr = rowBase + m, gc = k0 + kk;
            As[kk][m] = (gr < M && gc < K) ? A[(long)gr * lda + gc] : 0.0f;
        }
        #pragma unroll
        for (int e = 0; e < BELEM; e++) {
            int idx = tid + e * THREADS;
            int kk, n;
            if (!TB) { kk = idx / BN; n = idx % BN; }
            else     { n = idx / BK;  kk = idx % BK; }
            int gc = colBase + n, gk = k0 + kk;
            float v = 0.0f;
            if (gc < Nn && gk < K)
                v = TB ? Bm[(long)gc * ldb + gk] : Bm[(long)gk * ldb + gc];
            Bs[kk][n] = v;
        }
        __syncthreads();

        #pragma unroll
        for (int kk = 0; kk < BK; kk++) {
            float a[TM], bb[TN];
            #pragma unroll
            for (int i = 0; i < TM; i++) a[i] = As[kk][trow * TM + i];
            #pragma unroll
            for (int j = 0; j < TN; j++) bb[j] = Bs[kk][tcol * TN + j];
            #pragma unroll
            for (int i = 0; i < TM; i++)
                #pragma unroll
                for (int j = 0; j < TN; j++)
                    acc[i][j] += a[i] * bb[j];
        }
        __syncthreads();
    }

    #pragma unroll
    for (int i = 0; i < TM; i++) {
        int r = rowBase + trow * TM + i;
        if (r >= M) continue;
        #pragma unroll
        for (int j = 0; j < TN; j++) {
            int c = colBase + tcol * TN + j;
            if (c >= Nn) continue;
            float v = alpha * acc[i][j];
            if (Res) {
                int rr = resRowMod ? (r % resRowMod) : r;
                v += Res[(long)rr * ldres + c];
            }
            C[(long)r * ldc + c] = v;
        }
    }
}

// ---------------------------------------------------------------------------
// Elementwise / reduction kernels
// ---------------------------------------------------------------------------
__device__ __forceinline__ float blk_reduce(float v, bool ismax) {
    __shared__ float red[9];
    #pragma unroll
    for (int o = 16; o; o >>= 1) {
        float u = __shfl_xor_sync(0xffffffffu, v, o);
        v = ismax ? fmaxf(v, u) : (v + u);
    }
    if ((threadIdx.x & 31) == 0) red[threadIdx.x >> 5] = v;
    __syncthreads();
    if (threadIdx.x == 0) {
        float r = red[0];
        int nw = blockDim.x >> 5;
        for (int w = 1; w < nw; w++) r = ismax ? fmaxf(r, red[w]) : (r + red[w]);
        red[8] = r;
    }
    __syncthreads();
    float r = red[8];
    __syncthreads();
    return r;
}

__device__ __forceinline__ int token_type(int j) {
    return j < 512 ? 0 : (j < 1024 ? 1 : 2);
}

__global__ void concat_kernel(const float4* __restrict__ m0,
                              const float4* __restrict__ m1,
                              const float4* __restrict__ fus,
                              float4* __restrict__ tokens) {
    int idx = blockIdx.x * blockDim.x + threadIdx.x;
    const int D4 = D_ / 4;
    int total = B_ * NTOK * D4;
    if (idx >= total) return;
    int d = idx % D4;
    int t = (idx / D4) % NTOK;
    int b = idx / (D4 * NTOK);
    float4 v;
    if (t < 512)       v = m0[((long)b * 512 + t) * D4 + d];
    else if (t < 1024) v = m1[((long)b * 512 + (t - 512)) * D4 + d];
    else               v = fus[(long)(t - 1024) * D4 + d];
    tokens[idx] = v;
}

__global__ void ln_kernel(const float* __restrict__ x,
                          const float* __restrict__ gamma,
                          float* __restrict__ out) {
    long row = blockIdx.x;
    const float4* xr = (const float4*)(x + row * D_);
    float4 v = xr[threadIdx.x];
    float s = v.x + v.y + v.z + v.w;
    float mean = blk_reduce(s, false) * (1.0f / D_);
    float dx = v.x - mean, dy = v.y - mean, dz = v.z - mean, dw = v.w - mean;
    float s2 = dx * dx + dy * dy + dz * dz + dw * dw;
    float var = blk_reduce(s2, false) * (1.0f / D_);
    float inv = rsqrtf(var + 1e-5f);
    float4 g = ((const float4*)gamma)[threadIdx.x];
    float4 o;
    o.x = dx * inv * g.x; o.y = dy * inv * g.y;
    o.z = dz * inv * g.z; o.w = dw * inv * g.w;
    ((float4*)(out + row * D_))[threadIdx.x] = o;
}

// Range-limited self softmax: row of type t only attends its contiguous range,
// which QK wrote fresh; no masking needed inside the range.
__global__ void softmax_self_kernel(float* __restrict__ sim) {
    long row = blockIdx.x;
    int i = (int)(row % NTOK);
    int ti = token_type(i);
    int c0  = (ti == 1) ? 512 : 0;
    int len = (ti == 2) ? NTOK : 512;
    float* p = sim + row * NTOK + c0;
    int tid = threadIdx.x;

    float vals[5];
    float mx = -3.4e38f;
    #pragma unroll
    for (int it = 0; it < 5; it++) {
        int j = tid + it * 256;
        float v = (j < len) ? p[j] : -3.4e38f;
        vals[it] = v;
        mx = fmaxf(mx, v);
    }
    mx = blk_reduce(mx, true);

    float e[5];
    float s = 0.0f;
    #pragma unroll
    for (int it = 0; it < 5; it++) {
        float ex = __expf(vals[it] - mx);
        e[it] = ex;
        s += ex;
    }
    s = blk_reduce(s, false);
    float inv = 1.0f / s;
    #pragma unroll
    for (int it = 0; it < 5; it++) {
        int j = tid + it * 256;
        if (j < len) p[j] = e[it] * inv;
    }
}

// Pool softmax keeps full-row masked form (pool PV reads all columns).
__global__ void softmax_pool_kernel(float* __restrict__ sim) {
    long row = blockIdx.x;
    float* p = sim + row * NTOK;
    int r = (int)(row % 4);
    int tid = threadIdx.x;

    float vals[5];
    float mx = -3.4e38f;
    #pragma unroll
    for (int it = 0; it < 5; it++) {
        int j = tid + it * 256;
        float v = -3.4e38f;
        if (j < NTOK) {
            bool ok = (r == 3) || (token_type(j) == r);
            v = ok ? p[j] : -3.4e38f;
        }
        vals[it] = v;
        mx = fmaxf(mx, v);
    }
    mx = blk_reduce(mx, true);

    float e[5];
    float s = 0.0f;
    #pragma unroll
    for (int it = 0; it < 5; it++) {
        float ex = __expf(vals[it] - mx);
        e[it] = ex;
        s += ex;
    }
    s = blk_reduce(s, false);
    float inv = 1.0f / s;
    #pragma unroll
    for (int it = 0; it < 5; it++) {
        int j = tid + it * 256;
        if (j < NTOK) p[j] = e[it] * inv;
    }
}

__global__ void geglu_kernel(const float* __restrict__ ff1,
                             float* __restrict__ act) {
    long idx = (long)blockIdx.x * blockDim.x + threadIdx.x;
    long total = (long)ROWS * FF_;
    if (idx >= total) return;
    long row = idx / FF_;
    int f = (int)(idx - row * FF_);
    const float* p = ff1 + row * FF2_;
    float val = p[f];
    float gate = p[FF_ + f];
    float g = 0.5f * gate * (1.0f + erff(gate * 0.70710678118654752f));
    act[row * ACTLD + f] = g * val;
}

// ---------------------------------------------------------------------------
// Host side
// ---------------------------------------------------------------------------
static constexpr int SM_T128 = 3 * (128 * 36 + 32 * 136) * 4;  // 107520
static constexpr int SM_N128 = 3 * (128 * 36 + 128 * 36) * 4;  // 110592
static constexpr int SM_T64  = 3 * (128 * 36 + 32 * 72) * 4;   //  82944

static inline void tcw(const float* A, const float* B, float* C, const float* Res,
                       int M, int Nn, int K, int lda, int ldb, int ldc, float alpha,
                       int resRowMod = 0, int ldres = 0) {
    dim3 grid((Nn + 127) / 128, (M + 127) / 128, 1);
    mma_gemm<128, 64, 32, true><<<grid, 256, SM_T128>>>(
        A, B, C, Res, M, Nn, K, lda, ldb, ldc,
        0, 0, 0, 0, 0, 0, 1, alpha, resRowMod, ldres);
}

static inline void gemm_small(const float* A, const float* B, float* C,
                              const float* Res, int M, int Nn, int K,
                              int lda, int ldb, int ldc, float alpha,
                              int resRowMod = 0, int ldres = 0) {
    dim3 grid((Nn + 63) / 64, (M + 63) / 64, 1);
    gemm_kernel<64, 64, 16, 4, 4, false><<<grid, 256>>>(
        A, B, C, Res, M, Nn, K, lda, ldb, ldc,
        0, 0, 0, 0, 0, 0, 1, alpha, resRowMod, ldres);
}

extern "C" void kernel_launch(void* const* d_in, const int* in_sizes, int n_in,
                              void* d_out, int out_size) {
    const float* m0        = (const float*)d_in[0];
    const float* m1        = (const float*)d_in[1];
    const float* fusion    = (const float*)d_in[2];
    const float* ret_tok   = (const float*)d_in[3];
    const float* ln_gamma  = (const float*)d_in[4];
    const float* wq        = (const float*)d_in[5];
    const float* wkv       = (const float*)d_in[6];
    const float* wo        = (const float*)d_in[7];
    const float* ff_w1     = (const float*)d_in[8];
    const float* ff_w2     = (const float*)d_in[9];
    const float* pool_wq   = (const float*)d_in[10];
    const float* pool_wkv  = (const float*)d_in[11];
    const float* pool_wo   = (const float*)d_in[12];
    const float* final_g   = (const float*)d_in[13];
    float* out = (float*)d_out;

    cudaFuncSetAttribute(mma_gemm<128, 64, 32, true>,
                         cudaFuncAttributeMaxDynamicSharedMemorySize, SM_T128);
    cudaFuncSetAttribute(mma_gemm<128, 64, 32, false>,
                         cudaFuncAttributeMaxDynamicSharedMemorySize, SM_N128);
    cudaFuncSetAttribute(mma_gemm<64, 32, 32, true>,
                         cudaFuncAttributeMaxDynamicSharedMemorySize, SM_T64);

    float *tokens, *hbuf, *qbuf, *kvbuf, *simbuf, *aobuf, *ff1buf, *actbuf;
    cudaGetSymbolAddress((void**)&tokens, g_tokens);
    cudaGetSymbolAddress((void**)&hbuf,   g_h);
    cudaGetSymbolAddress((void**)&qbuf,   g_q);
    cudaGetSymbolAddress((void**)&kvbuf,  g_kv);
    cudaGetSymbolAddress((void**)&simbuf, g_sim);
    cudaGetSymbolAddress((void**)&aobuf,  g_ao);
    cudaGetSymbolAddress((void**)&ff1buf, g_ff1);
    cudaGetSymbolAddress((void**)&actbuf, g_act);

    {
        int total = B_ * NTOK * (D_ / 4);
        concat_kernel<<<(total + 255) / 256, 256>>>(
            (const float4*)m0, (const float4*)m1, (const float4*)fusion,
            (float4*)tokens);
    }

    const float scale = 0.125f;
    const long sSimB = (long)H_ * NTOK * NTOK;
    const long sSimH = (long)NTOK * NTOK;
    const long sQB   = (long)NTOK * D_;
    const long sKVB  = (long)NTOK * 2 * D_;
    const long sAoB  = (long)NTOK * D_;

    for (int l = 0; l < L_; l++) {
        const float* wq_l  = wq    + (long)l * D_ * D_;
        const float* wkv_l = wkv   + (long)l * D_ * 2 * D_;
        const float* wo_l  = wo    + (long)l * D_ * D_;
        const float* w1_l  = ff_w1 + (long)l * D_ * FF2_;
        const float* w2_l  = ff_w2 + (long)l * FF_ * D_;
        const float* g_l   = ln_gamma + (long)l * D_;

        ln_kernel<<<ROWS, 256>>>(tokens, g_l, hbuf);
        tcw(hbuf, wq_l,  qbuf,  nullptr, ROWS, D_,     D_, D_, D_,     D_,     scale);
        tcw(hbuf, wkv_l, kvbuf, nullptr, ROWS, 2 * D_, D_, D_, 2 * D_, 2 * D_, 1.0f);

        // --- QK: 3 restricted launches (block-structured mask) ---
        // rows 0-511 x cols 0-511
        mma_gemm<128, 64, 32, false><<<dim3(4, 4, B_ * H_), 256, SM_N128>>>(
            qbuf, kvbuf, simbuf, nullptr,
            512, 512, DH_, D_, 2 * D_, NTOK,
            sQB, DH_, sKVB, DH_, sSimB, sSimH, H_, 1.0f, 0, 0);
        // rows 512-1023 x cols 512-1023
        mma_gemm<128, 64, 32, false><<<dim3(4, 4, B_ * H_), 256, SM_N128>>>(
            qbuf + (long)512 * D_, kvbuf + (long)512 * 2 * D_,
            simbuf + (long)512 * NTOK + 512, nullptr,
            512, 512, DH_, D_, 2 * D_, NTOK,
            sQB, DH_, sKVB, DH_, sSimB, sSimH, H_, 1.0f, 0, 0);
        // fusion rows 1024-1039 x all cols
        mma_gemm<128, 64, 32, false><<<dim3(9, 1, B_ * H_), 256, SM_N128>>>(
            qbuf + (long)1024 * D_, kvbuf,
            simbuf + (long)1024 * NTOK, nullptr,
            16, NTOK, DH_, D_, 2 * D_, NTOK,
            sQB, DH_, sKVB, DH_, sSimB, sSimH, H_, 1.0f, 0, 0);

        softmax_self_kernel<<<B_ * H_ * NTOK, 256>>>(simbuf);

        // --- PV: 3 restricted launches ---
        mma_gemm<64, 32, 32, true><<<dim3(1, 4, B_ * H_), 256, SM_T64>>>(
            simbuf, kvbuf + D_, aobuf, nullptr,
            512, DH_, 512, NTOK, 2 * D_, D_,
            sSimB, sSimH, sKVB, DH_, sAoB, DH_, H_, 1.0f, 0, 0);
        mma_gemm<64, 32, 32, true><<<dim3(1, 4, B_ * H_), 256, SM_T64>>>(
            simbuf + (long)512 * NTOK + 512, kvbuf + D_ + (long)512 * 2 * D_,
            aobuf + (long)512 * D_, nullptr,
            512, DH_, 512, NTOK, 2 * D_, D_,
            sSimB, sSimH, sKVB, DH_, sAoB, DH_, H_, 1.0f, 0, 0);
        mma_gemm<64, 32, 32, true><<<dim3(1, 1, B_ * H_), 256, SM_T64>>>(
            simbuf + (long)1024 * NTOK, kvbuf + D_,
            aobuf + (long)1024 * D_, nullptr,
            16, DH_, NTOK, NTOK, 2 * D_, D_,
            sSimB, sSimH, sKVB, DH_, sAoB, DH_, H_, 1.0f, 0, 0);

        tcw(aobuf, wo_l, tokens, tokens, ROWS, D_, D_, D_, D_, D_, 1.0f, 0, D_);

        ln_kernel<<<ROWS, 256>>>(tokens, g_l, hbuf);
        tcw(hbuf, w1_l, ff1buf, nullptr, ROWS, FF2_, D_, D_, FF2_, FF2_, 1.0f);
        {
            long total = (long)ROWS * FF_;
            geglu_kernel<<<(int)((total + 255) / 256), 256>>>(ff1buf, actbuf);
        }
        tcw(actbuf, w2_l, tokens, tokens, ROWS, D_, FF_, ACTLD, D_, D_, 1.0f, 0, D_);
    }

    // --- final LN + attention pooling ---
    ln_kernel<<<ROWS, 256>>>(tokens, final_g, hbuf);

    gemm_small(ret_tok, pool_wq, qbuf, nullptr, 4, D_, D_, D_, D_, D_, scale);
    tcw(hbuf, pool_wkv, kvbuf, nullptr, ROWS, 2 * D_, D_, D_, 2 * D_, 2 * D_, 1.0f);

    // pool sim [b,h,r,j]
    {
        dim3 grid((NTOK + 63) / 64, 1, B_ * H_);
        gemm_kernel<64, 64, 16, 4, 4, true><<<grid, 256>>>(
            qbuf, kvbuf, simbuf, nullptr,
            4, NTOK, DH_, D_, 2 * D_, NTOK,
            0L, DH_, sKVB, DH_,
            (long)H_ * 4 * NTOK, (long)4 * NTOK, H_,
            1.0f, 0, 0);
    }

    softmax_pool_kernel<<<B_ * H_ * 4, 256>>>(simbuf);

    // pool out [b,r,h*64+d] = attn @ v
    {
        dim3 grid(1, 1, B_ * H_);
        gemm_kernel<64, 64, 16, 4, 4, false><<<grid, 256>>>(
            simbuf, kvbuf + D_, aobuf, nullptr,
            4, DH_, NTOK, NTOK, 2 * D_, D_,
            (long)H_ * 4 * NTOK, (long)4 * NTOK,
            sKVB, DH_,
            (long)4 * D_, DH_, H_,
            1.0f, 0, 0);
    }

    gemm_small(aobuf, pool_wo, out, ret_tok, B_ * 4, D_, D_, D_, D_, D_, 1.0f,
               /*resRowMod=*/4, /*ldres=*/D_);
}

// round 5
// speedup vs baseline: 3.6437x; 1.0152x over previous
#include <cuda_runtime.h>
#include <math.h>
#include <stdint.h>

// ---------------------------------------------------------------------------
// Problem constants
// ---------------------------------------------------------------------------
static constexpr int B_    = 4;
static constexpr int NTOK  = 1040;   // 512 + 512 + 16
static constexpr int D_    = 1024;
static constexpr int H_    = 16;
static constexpr int DH_   = 64;
static constexpr int L_    = 4;
static constexpr int FF_   = 2730;
static constexpr int FF2_  = 5460;
static constexpr int ROWS  = B_ * NTOK;   // 4160
static constexpr int ACTLD = 2732;        // padded act row stride (16B-aligned rows)
static constexpr int FF2TLD = 2732;       // padded ff2T row stride

// ---------------------------------------------------------------------------
// Device scratch
// ---------------------------------------------------------------------------
__device__ float g_tokens[B_ * NTOK * D_];
__device__ float g_h     [B_ * NTOK * D_];
__device__ float g_q     [B_ * NTOK * D_];
__device__ float g_kv    [B_ * NTOK * 2 * D_];
__device__ float g_sim   [(long long)B_ * H_ * NTOK * NTOK];
__device__ float g_ao    [B_ * NTOK * D_];
__device__ float g_ff1   [(long long)ROWS * FF2_];
__device__ float g_act   [(long long)ROWS * ACTLD];
// transposed weights
__device__ float g_wqT [L_ * D_ * D_];
__device__ float g_wkvT[L_ * 2 * D_ * D_];
__device__ float g_woT [L_ * D_ * D_];
__device__ float g_ff1T[(long long)L_ * FF2_ * D_];
__device__ float g_ff2T[(long long)L_ * D_ * FF2TLD];
__device__ float g_pkvT[2 * D_ * D_];

// ---------------------------------------------------------------------------
// Helpers
// ---------------------------------------------------------------------------
__device__ __forceinline__ uint32_t smem_u32(const void* p) {
    uint32_t a;
    asm("{ .reg .u64 t; cvta.to.shared.u64 t, %1; cvt.u32.u64 %0, t; }"
        : "=r"(a) : "l"(p));
    return a;
}

__device__ __forceinline__ void mma_tf32(float* c, const uint32_t* a, const uint32_t* b) {
    asm volatile(
        "mma.sync.aligned.m16n8k8.row.col.f32.tf32.tf32.f32 "
        "{%0,%1,%2,%3}, {%4,%5,%6,%7}, {%8,%9}, {%0,%1,%2,%3};"
        : "+f"(c[0]), "+f"(c[1]), "+f"(c[2]), "+f"(c[3])
        : "r"(a[0]), "r"(a[1]), "r"(a[2]), "r"(a[3]), "r"(b[0]), "r"(b[1]));
}

#define LDSM4(d, addr)                                                         \
    asm volatile("ldmatrix.sync.aligned.m8n8.x4.shared.b16 {%0,%1,%2,%3}, [%4];" \
        : "=r"((d)[0]), "=r"((d)[1]), "=r"((d)[2]), "=r"((d)[3]) : "r"(addr))

__device__ __forceinline__ void cp16(uint32_t dst, const float* src, int bytes) {
    asm volatile("cp.async.cg.shared.global [%0], [%1], 16, %2;"
                 :: "r"(dst), "l"(src), "r"(bytes));
}
#define CP_COMMIT() asm volatile("cp.async.commit_group;" ::: "memory")
#define CP_WAIT1()  asm volatile("cp.async.wait_group 1;" ::: "memory")

// ---------------------------------------------------------------------------
// tf32 mma.sync GEMM, 3-stage cp.async pipeline, ldmatrix fragment loads.
//   C[M,N] = alpha * A[M,K] @ B (+Res)
//   TRANSW=false: B global is [N,K] row-major (ldmatrix B path)
//   TRANSW=true : B global is [K,N] row-major (PV; scalar B frag loads)
// BM=128, BK=32, 256 threads. fp32 fed directly to tf32 MMA (HW truncates).
// ---------------------------------------------------------------------------
template<int BN, int WTM, int WTN, bool TRANSW>
__global__ void __launch_bounds__(256)
mma_gemm(const float* __restrict__ A, const float* __restrict__ Bm,
         float* __restrict__ C, const float* __restrict__ Res,
         int M, int N, int K, int lda, int ldb, int ldc,
         long sAb, long sAh, long sBb, long sBh, long sCb, long sCh, int Hdiv,
         float alpha, int resRowMod, int ldres) {
    constexpr int WN = BN / WTN;
    constexpr int MT = WTM / 16;
    constexpr int NT = WTN / 8;
    constexpr int A_ST_W = 128 * 36;
    constexpr int B_ST_W = TRANSW ? 32 * (BN + 8) : BN * 36;
    constexpr int ST_W   = A_ST_W + B_ST_W;
    constexpr int BE     = TRANSW ? (BN / 32) : (BN / 32);

    extern __shared__ __align__(16) float smem[];
    const uint32_t sb = smem_u32(smem);

    const int tid = threadIdx.x;
    const int wid = tid >> 5, lane = tid & 31;
    const int g = lane >> 2, t4 = lane & 3;
    const int wm = wid / WN, wn = wid % WN;
    const int q8 = lane >> 3, r8 = lane & 7;

    int z = blockIdx.z;
    int zb = z / Hdiv, zh = z - zb * Hdiv;
    A  += (long)zb * sAb + (long)zh * sAh;
    Bm += (long)zb * sBb + (long)zh * sBh;
    C  += (long)zb * sCb + (long)zh * sCh;

    const int rowBase = blockIdx.y * 128;
    const int colBase = blockIdx.x * BN;
    const int KC = (K + 31) >> 5;

    // ---- A producer state ----
    const int chA = tid & 7;
    const float* aSrc[4];
    uint32_t aOff[4];
    bool aOk[4];
    #pragma unroll
    for (int e = 0; e < 4; e++) {
        int m = (tid >> 3) + 32 * e;
        int gr = rowBase + m;
        aOk[e] = gr < M;
        aSrc[e] = A + (long)(aOk[e] ? gr : 0) * lda + chA * 4;
        aOff[e] = (uint32_t)(m * 144 + chA * 16);
    }

    // ---- B producer state ----
    const float* bSrc[BE];
    uint32_t bOff[BE];
    int bCB[BE];
    int bKK[BE];
    if (TRANSW) {
        const int chB = tid & (BN / 4 - 1);
        #pragma unroll
        for (int e = 0; e < BE; e++) {
            int kk = tid / (BN / 4) + (256 / (BN / 4)) * e;
            int gn = colBase + chB * 4;
            int cb = (N - gn) * 4;
            cb = cb < 0 ? 0 : (cb > 16 ? 16 : cb);
            bCB[e] = cb;
            bKK[e] = kk;
            bSrc[e] = Bm + (long)kk * ldb + (cb ? gn : 0);
            bOff[e] = (uint32_t)(kk * (BN + 8) * 4 + chB * 16);
        }
    } else {
        #pragma unroll
        for (int e = 0; e < BE; e++) {
            int n = (tid >> 3) + 32 * e;
            int gn = colBase + n;
            bCB[e] = (gn < N) ? 1 : 0;
            bSrc[e] = Bm + (long)(bCB[e] ? gn : 0) * ldb + chA * 4;
            bOff[e] = (uint32_t)(n * 144 + chA * 16);
        }
    }

    auto issue = [&](int c, int st) {
        const uint32_t stb = sb + (uint32_t)(st * ST_W * 4);
        int krem = K - (c << 5);
        int kb = (krem - chA * 4) * 4;
        kb = kb < 0 ? 0 : (kb > 16 ? 16 : kb);
        #pragma unroll
        for (int e = 0; e < 4; e++) {
            int bytes = aOk[e] ? kb : 0;
            cp16(stb + aOff[e], bytes ? aSrc[e] : A, bytes);
            aSrc[e] += 32;
        }
        const uint32_t bstb = stb + (uint32_t)(A_ST_W * 4);
        if (TRANSW) {
            #pragma unroll
            for (int e = 0; e < BE; e++) {
                int bytes = (bKK[e] < krem) ? bCB[e] : 0;
                cp16(bstb + bOff[e], bytes ? bSrc[e] : Bm, bytes);
                bSrc[e] += (long)32 * ldb;
            }
        } else {
            #pragma unroll
            for (int e = 0; e < BE; e++) {
                int bytes = bCB[e] ? kb : 0;
                cp16(bstb + bOff[e], bytes ? bSrc[e] : Bm, bytes);
                bSrc[e] += 32;
            }
        }
        CP_COMMIT();
    };

    float acc[MT][NT][4];
    #pragma unroll
    for (int i = 0; i < MT; i++)
        #pragma unroll
        for (int j = 0; j < NT; j++)
            #pragma unroll
            for (int q = 0; q < 4; q++) acc[i][j][q] = 0.0f;

    // ldmatrix base word indices
    const int aIdx0 = (wm * WTM + (q8 & 1) * 8 + r8) * 36 + (q8 >> 1) * 4;
    const int bIdx0 = (wn * WTN + (q8 >> 1) * 8 + r8) * 36 + (q8 & 1) * 4;
    // scalar B base (TRANSW)
    const int bBw = t4 * (BN + 8) + wn * WTN + g;

    issue(0, 0);
    issue(1, 1);

    int st = 0;
    for (int c = 0; c < KC; c++) {
        CP_WAIT1();
        __syncthreads();
        if (c + 2 < KC) issue(c + 2, (st + 2) % 3);
        else CP_COMMIT();

        const uint32_t aStB = sb + (uint32_t)(st * ST_W * 4);
        const uint32_t bStB = aStB + (uint32_t)(A_ST_W * 4);
        const uint32_t* Bw = (const uint32_t*)smem + st * ST_W + A_ST_W;

        #pragma unroll
        for (int ks = 0; ks < 4; ks++) {
            uint32_t af[MT][4], bf[NT][2];
            #pragma unroll
            for (int mt = 0; mt < MT; mt++)
                LDSM4(af[mt], aStB + (uint32_t)((aIdx0 + mt * 576 + ks * 8) * 4));
            if (!TRANSW) {
                #pragma unroll
                for (int p = 0; p < NT / 2; p++) {
                    uint32_t d[4];
                    LDSM4(d, bStB + (uint32_t)((bIdx0 + p * 576 + ks * 8) * 4));
                    bf[2 * p][0] = d[0]; bf[2 * p][1] = d[1];
                    bf[2 * p + 1][0] = d[2]; bf[2 * p + 1][1] = d[3];
                }
            } else {
                #pragma unroll
                for (int nt = 0; nt < NT; nt++) {
                    bf[nt][0] = Bw[bBw + ks * 8 * (BN + 8) + nt * 8];
                    bf[nt][1] = Bw[bBw + (ks * 8 + 4) * (BN + 8) + nt * 8];
                }
            }
            #pragma unroll
            for (int mt = 0; mt < MT; mt++)
                #pragma unroll
                for (int nt = 0; nt < NT; nt++)
                    mma_tf32(acc[mt][nt], af[mt], bf[nt]);
        }
        st++; if (st == 3) st = 0;
    }

    // Epilogue: direct float2 stores
    #pragma unroll
    for (int mt = 0; mt < MT; mt++) {
        int r0 = rowBase + wm * WTM + mt * 16 + g;
        #pragma unroll
        for (int nt = 0; nt < NT; nt++) {
            int col = colBase + wn * WTN + nt * 8 + t4 * 2;
            if (col >= N) continue;
            #pragma unroll
            for (int hh = 0; hh < 2; hh++) {
                int rr = r0 + hh * 8;
                if (rr >= M) continue;
                float2 v;
                v.x = alpha * acc[mt][nt][hh * 2];
                v.y = alpha * acc[mt][nt][hh * 2 + 1];
                if (Res) {
                    int rx = resRowMod ? (rr % resRowMod) : rr;
                    float2 rv = *(const float2*)(Res + (long)rx * ldres + col);
                    v.x += rv.x; v.y += rv.y;
                }
                *(float2*)(C + (long)rr * ldc + col) = v;
            }
        }
    }
}

// ---------------------------------------------------------------------------
// Weight transpose: dst[z][n][k] = src[z][k][n]
// ---------------------------------------------------------------------------
__global__ void transpose_kernel(const float* __restrict__ src,
                                 float* __restrict__ dst,
                                 int K, int N, int ldd) {
    __shared__ float tile[32][33];
    int k0 = blockIdx.y * 32, n0 = blockIdx.x * 32;
    long zS = (long)blockIdx.z * K * N;
    long zD = (long)blockIdx.z * N * ldd;
    int tx = threadIdx.x, ty = threadIdx.y;   // 32 x 8
    #pragma unroll
    for (int i = ty; i < 32; i += 8) {
        int k = k0 + i, n = n0 + tx;
        if (k < K && n < N) tile[i][tx] = src[zS + (long)k * N + n];
    }
    __syncthreads();
    #pragma unroll
    for (int i = ty; i < 32; i += 8) {
        int n = n0 + i, k = k0 + tx;
        if (n < N && k < K) dst[zD + (long)n * ldd + k] = tile[tx][i];
    }
}

// ---------------------------------------------------------------------------
// Small SIMT GEMM (tiny pool launches)
// ---------------------------------------------------------------------------
template<int BM, int BN, int BK, int TM, int TN, bool TB>
__global__ void __launch_bounds__((BM / TM) * (BN / TN))
gemm_kernel(const float* __restrict__ A, const float* __restrict__ Bm,
            float* __restrict__ C, const float* __restrict__ Res,
            int M, int Nn, int K,
            int lda, int ldb, int ldc,
            long sAb, long sAh, long sBb, long sBh, long sCb, long sCh, int Hdiv,
            float alpha, int resRowMod, int ldres) {
    constexpr int THREADS = (BM / TM) * (BN / TN);
    constexpr int AELEM = BM * BK / THREADS;
    constexpr int BELEM = BK * BN / THREADS;

    int z = blockIdx.z;
    int zb = z / Hdiv, zh = z - zb * Hdiv;
    A  += (long)zb * sAb + (long)zh * sAh;
    Bm += (long)zb * sBb + (long)zh * sBh;
    C  += (long)zb * sCb + (long)zh * sCh;

    __shared__ __align__(16) float As[BK][BM + 4];
    __shared__ __align__(16) float Bs[BK][BN + 4];

    int tid = threadIdx.x;
    int tcol = tid % (BN / TN);
    int trow = tid / (BN / TN);
    int rowBase = blockIdx.y * BM;
    int colBase = blockIdx.x * BN;

    float acc[TM][TN] = {};

    for (int k0 = 0; k0 < K; k0 += BK) {
        #pragma unroll
        for (int e = 0; e < AELEM; e++) {
            int idx = tid + e * THREADS;
            int m = idx / BK, kk = idx % BK;
            int gr = rowBase + m, gc = k0 + kk;
            As[kk][m] = (gr < M && gc < K) ? A[(long)gr * lda + gc] : 0.0f;
        }
        #pragma unroll
        for (int e = 0; e < BELEM; e++) {
            int idx = tid + e * THREADS;
            int kk, n;
            if (!TB) { kk = idx / BN; n = idx % BN; }
            else     { n = idx / BK;  kk = idx % BK; }
            int gc = colBase + n, gk = k0 + kk;
            float v = 0.0f;
            if (gc < Nn && gk < K)
                v = TB ? Bm[(long)gc * ldb + gk] : Bm[(long)gk * ldb + gc];
            Bs[kk][n] = v;
        }
        __syncthreads();

        #pragma unroll
        for (int kk = 0; kk < BK; kk++) {
            float a[TM], bb[TN];
            #pragma unroll
            for (int i = 0; i < TM; i++) a[i] = As[kk][trow * TM + i];
            #pragma unroll
            for (int j = 0; j < TN; j++) bb[j] = Bs[kk][tcol * TN + j];
            #pragma unroll
            for (int i = 0; i < TM; i++)
                #pragma unroll
                for (int j = 0; j < TN; j++)
                    acc[i][j] += a[i] * bb[j];
        }
        __syncthreads();
    }

    #pragma unroll
    for (int i = 0; i < TM; i++) {
        int r = rowBase + trow * TM + i;
        if (r >= M) continue;
        #pragma unroll
        for (int j = 0; j < TN; j++) {
            int c = colBase + tcol * TN + j;
            if (c >= Nn) continue;
            float v = alpha * acc[i][j];
            if (Res) {
                int rr = resRowMod ? (r % resRowMod) : r;
                v += Res[(long)rr * ldres + c];
            }
            C[(long)r * ldc + c] = v;
        }
    }
}

// ---------------------------------------------------------------------------
// Elementwise / reduction kernels
// ---------------------------------------------------------------------------
__device__ __forceinline__ float blk_reduce(float v, bool ismax) {
    __shared__ float red[9];
    #pragma unroll
    for (int o = 16; o; o >>= 1) {
        float u = __shfl_xor_sync(0xffffffffu, v, o);
        v = ismax ? fmaxf(v, u) : (v + u);
    }
    if ((threadIdx.x & 31) == 0) red[threadIdx.x >> 5] = v;
    __syncthreads();
    if (threadIdx.x == 0) {
        float r = red[0];
        int nw = blockDim.x >> 5;
        for (int w = 1; w < nw; w++) r = ismax ? fmaxf(r, red[w]) : (r + red[w]);
        red[8] = r;
    }
    __syncthreads();
    float r = red[8];
    __syncthreads();
    return r;
}

__device__ __forceinline__ int token_type(int j) {
    return j < 512 ? 0 : (j < 1024 ? 1 : 2);
}

__global__ void concat_kernel(const float4* __restrict__ m0,
                              const float4* __restrict__ m1,
                              const float4* __restrict__ fus,
                              float4* __restrict__ tokens) {
    int idx = blockIdx.x * blockDim.x + threadIdx.x;
    const int D4 = D_ / 4;
    int total = B_ * NTOK * D4;
    if (idx >= total) return;
    int d = idx % D4;
    int t = (idx / D4) % NTOK;
    int b = idx / (D4 * NTOK);
    float4 v;
    if (t < 512)       v = m0[((long)b * 512 + t) * D4 + d];
    else if (t < 1024) v = m1[((long)b * 512 + (t - 512)) * D4 + d];
    else               v = fus[(long)(t - 1024) * D4 + d];
    tokens[idx] = v;
}

__global__ void ln_kernel(const float* __restrict__ x,
                          const float* __restrict__ gamma,
                          float* __restrict__ out) {
    long row = blockIdx.x;
    const float4* xr = (const float4*)(x + row * D_);
    float4 v = xr[threadIdx.x];
    float s = v.x + v.y + v.z + v.w;
    float mean = blk_reduce(s, false) * (1.0f / D_);
    float dx = v.x - mean, dy = v.y - mean, dz = v.z - mean, dw = v.w - mean;
    float s2 = dx * dx + dy * dy + dz * dz + dw * dw;
    float var = blk_reduce(s2, false) * (1.0f / D_);
    float inv = rsqrtf(var + 1e-5f);
    float4 g = ((const float4*)gamma)[threadIdx.x];
    float4 o;
    o.x = dx * inv * g.x; o.y = dy * inv * g.y;
    o.z = dz * inv * g.z; o.w = dw * inv * g.w;
    ((float4*)(out + row * D_))[threadIdx.x] = o;
}

// Range-limited self softmax
__global__ void softmax_self_kernel(float* __restrict__ sim) {
    long row = blockIdx.x;
    int i = (int)(row % NTOK);
    int ti = token_type(i);
    int c0  = (ti == 1) ? 512 : 0;
    int len = (ti == 2) ? NTOK : 512;
    float* p = sim + row * NTOK + c0;
    int tid = threadIdx.x;

    float vals[5];
    float mx = -3.4e38f;
    #pragma unroll
    for (int it = 0; it < 5; it++) {
        int j = tid + it * 256;
        float v = (j < len) ? p[j] : -3.4e38f;
        vals[it] = v;
        mx = fmaxf(mx, v);
    }
    mx = blk_reduce(mx, true);

    float e[5];
    float s = 0.0f;
    #pragma unroll
    for (int it = 0; it < 5; it++) {
        float ex = __expf(vals[it] - mx);
        e[it] = ex;
        s += ex;
    }
    s = blk_reduce(s, false);
    float inv = 1.0f / s;
    #pragma unroll
    for (int it = 0; it < 5; it++) {
        int j = tid + it * 256;
        if (j < len) p[j] = e[it] * inv;
    }
}

__global__ void softmax_pool_kernel(float* __restrict__ sim) {
    long row = blockIdx.x;
    float* p = sim + row * NTOK;
    int r = (int)(row % 4);
    int tid = threadIdx.x;

    float vals[5];
    float mx = -3.4e38f;
    #pragma unroll
    for (int it = 0; it < 5; it++) {
        int j = tid + it * 256;
        float v = -3.4e38f;
        if (j < NTOK) {
            bool ok = (r == 3) || (token_type(j) == r);
            v = ok ? p[j] : -3.4e38f;
        }
        vals[it] = v;
        mx = fmaxf(mx, v);
    }
    mx = blk_reduce(mx, true);

    float e[5];
    float s = 0.0f;
    #pragma unroll
    for (int it = 0; it < 5; it++) {
        float ex = __expf(vals[it] - mx);
        e[it] = ex;
        s += ex;
    }
    s = blk_reduce(s, false);
    float inv = 1.0f / s;
    #pragma unroll
    for (int it = 0; it < 5; it++) {
        int j = tid + it * 256;
        if (j < NTOK) p[j] = e[it] * inv;
    }
}

__global__ void geglu_kernel(const float* __restrict__ ff1,
                             float* __restrict__ act) {
    long idx = (long)blockIdx.x * blockDim.x + threadIdx.x;
    long total = (long)ROWS * FF_;
    if (idx >= total) return;
    long row = idx / FF_;
    int f = (int)(idx - row * FF_);
    const float* p = ff1 + row * FF2_;
    float val = p[f];
    float gate = p[FF_ + f];
    float g = 0.5f * gate * (1.0f + erff(gate * 0.70710678118654752f));
    act[row * ACTLD + f] = g * val;
}

// ---------------------------------------------------------------------------
// Host side
// ---------------------------------------------------------------------------
static constexpr int SM_N128 = 3 * (128 * 36 + 128 * 36) * 4;  // 110592
static constexpr int SM_T64  = 3 * (128 * 36 + 32 * 72) * 4;   //  82944

static inline void tcn(const float* A, const float* Bt, float* C, const float* Res,
                       int M, int Nn, int K, int lda, int ldbT, int ldc, float alpha,
                       int resRowMod = 0, int ldres = 0) {
    dim3 grid((Nn + 127) / 128, (M + 127) / 128, 1);
    mma_gemm<128, 64, 32, false><<<grid, 256, SM_N128>>>(
        A, Bt, C, Res, M, Nn, K, lda, ldbT, ldc,
        0, 0, 0, 0, 0, 0, 1, alpha, resRowMod, ldres);
}

static inline void gemm_small(const float* A, const float* B, float* C,
                              const float* Res, int M, int Nn, int K,
                              int lda, int ldb, int ldc, float alpha,
                              int resRowMod = 0, int ldres = 0) {
    dim3 grid((Nn + 63) / 64, (M + 63) / 64, 1);
    gemm_kernel<64, 64, 16, 4, 4, false><<<grid, 256>>>(
        A, B, C, Res, M, Nn, K, lda, ldb, ldc,
        0, 0, 0, 0, 0, 0, 1, alpha, resRowMod, ldres);
}

extern "C" void kernel_launch(void* const* d_in, const int* in_sizes, int n_in,
                              void* d_out, int out_size) {
    const float* m0        = (const float*)d_in[0];
    const float* m1        = (const float*)d_in[1];
    const float* fusion    = (const float*)d_in[2];
    const float* ret_tok   = (const float*)d_in[3];
    const float* ln_gamma  = (const float*)d_in[4];
    const float* wq        = (const float*)d_in[5];
    const float* wkv       = (const float*)d_in[6];
    const float* wo        = (const float*)d_in[7];
    const float* ff_w1     = (const float*)d_in[8];
    const float* ff_w2     = (const float*)d_in[9];
    const float* pool_wq   = (const float*)d_in[10];
    const float* pool_wkv  = (const float*)d_in[11];
    const float* pool_wo   = (const float*)d_in[12];
    const float* final_g   = (const float*)d_in[13];
    float* out = (float*)d_out;

    cudaFuncSetAttribute(mma_gemm<128, 64, 32, false>,
                         cudaFuncAttributeMaxDynamicSharedMemorySize, SM_N128);
    cudaFuncSetAttribute(mma_gemm<64, 32, 32, true>,
                         cudaFuncAttributeMaxDynamicSharedMemorySize, SM_T64);

    float *tokens, *hbuf, *qbuf, *kvbuf, *simbuf, *aobuf, *ff1buf, *actbuf;
    float *wqT, *wkvT, *woT, *ff1T, *ff2T, *pkvT;
    cudaGetSymbolAddress((void**)&tokens, g_tokens);
    cudaGetSymbolAddress((void**)&hbuf,   g_h);
    cudaGetSymbolAddress((void**)&qbuf,   g_q);
    cudaGetSymbolAddress((void**)&kvbuf,  g_kv);
    cudaGetSymbolAddress((void**)&simbuf, g_sim);
    cudaGetSymbolAddress((void**)&aobuf,  g_ao);
    cudaGetSymbolAddress((void**)&ff1buf, g_ff1);
    cudaGetSymbolAddress((void**)&actbuf, g_act);
    cudaGetSymbolAddress((void**)&wqT,    g_wqT);
    cudaGetSymbolAddress((void**)&wkvT,   g_wkvT);
    cudaGetSymbolAddress((void**)&woT,    g_woT);
    cudaGetSymbolAddress((void**)&ff1T,   g_ff1T);
    cudaGetSymbolAddress((void**)&ff2T,   g_ff2T);
    cudaGetSymbolAddress((void**)&pkvT,   g_pkvT);

    // --- weight pre-transposes (graph-captured, amortized) ---
    {
        dim3 thr(32, 8);
        transpose_kernel<<<dim3(32, 32, 4),  thr>>>(wq,       wqT,  1024, 1024, 1024);
        transpose_kernel<<<dim3(64, 32, 4),  thr>>>(wkv,      wkvT, 1024, 2048, 1024);
        transpose_kernel<<<dim3(32, 32, 4),  thr>>>(wo,       woT,  1024, 1024, 1024);
        transpose_kernel<<<dim3(171, 32, 4), thr>>>(ff_w1,    ff1T, 1024, 5460, 1024);
        transpose_kernel<<<dim3(32, 86, 4),  thr>>>(ff_w2,    ff2T, 2730, 1024, FF2TLD);
        transpose_kernel<<<dim3(64, 32, 1),  thr>>>(pool_wkv, pkvT, 1024, 2048, 1024);
    }

    {
        int total = B_ * NTOK * (D_ / 4);
        concat_kernel<<<(total + 255) / 256, 256>>>(
            (const float4*)m0, (const float4*)m1, (const float4*)fusion,
            (float4*)tokens);
    }

    const float scale = 0.125f;
    const long sSimB = (long)H_ * NTOK * NTOK;
    const long sSimH = (long)NTOK * NTOK;
    const long sQB   = (long)NTOK * D_;
    const long sKVB  = (long)NTOK * 2 * D_;
    const long sAoB  = (long)NTOK * D_;

    for (int l = 0; l < L_; l++) {
        const float* wqT_l  = wqT  + (long)l * D_ * D_;
        const float* wkvT_l = wkvT + (long)l * 2 * D_ * D_;
        const float* woT_l  = woT  + (long)l * D_ * D_;
        const float* w1T_l  = ff1T + (long)l * FF2_ * D_;
        const float* w2T_l  = ff2T + (long)l * D_ * FF2TLD;
        const float* g_l    = ln_gamma + (long)l * D_;

        ln_kernel<<<ROWS, 256>>>(tokens, g_l, hbuf);
        tcn(hbuf, wqT_l,  qbuf,  nullptr, ROWS, D_,     D_, D_, D_, D_,     scale);
        tcn(hbuf, wkvT_l, kvbuf, nullptr, ROWS, 2 * D_, D_, D_, D_, 2 * D_, 1.0f);

        // --- QK: 3 restricted launches (block-structured mask) ---
        mma_gemm<128, 64, 32, false><<<dim3(4, 4, B_ * H_), 256, SM_N128>>>(
            qbuf, kvbuf, simbuf, nullptr,
            512, 512, DH_, D_, 2 * D_, NTOK,
            sQB, DH_, sKVB, DH_, sSimB, sSimH, H_, 1.0f, 0, 0);
        mma_gemm<128, 64, 32, false><<<dim3(4, 4, B_ * H_), 256, SM_N128>>>(
            qbuf + (long)512 * D_, kvbuf + (long)512 * 2 * D_,
            simbuf + (long)512 * NTOK + 512, nullptr,
            512, 512, DH_, D_, 2 * D_, NTOK,
            sQB, DH_, sKVB, DH_, sSimB, sSimH, H_, 1.0f, 0, 0);
        mma_gemm<128, 64, 32, false><<<dim3(9, 1, B_ * H_), 256, SM_N128>>>(
            qbuf + (long)1024 * D_, kvbuf,
            simbuf + (long)1024 * NTOK, nullptr,
            16, NTOK, DH_, D_, 2 * D_, NTOK,
            sQB, DH_, sKVB, DH_, sSimB, sSimH, H_, 1.0f, 0, 0);

        softmax_self_kernel<<<B_ * H_ * NTOK, 256>>>(simbuf);

        // --- PV: 3 restricted launches (scalar-B variant) ---
        mma_gemm<64, 32, 32, true><<<dim3(1, 4, B_ * H_), 256, SM_T64>>>(
            simbuf, kvbuf + D_, aobuf, nullptr,
            512, DH_, 512, NTOK, 2 * D_, D_,
            sSimB, sSimH, sKVB, DH_, sAoB, DH_, H_, 1.0f, 0, 0);
        mma_gemm<64, 32, 32, true><<<dim3(1, 4, B_ * H_), 256, SM_T64>>>(
            simbuf + (long)512 * NTOK + 512, kvbuf + D_ + (long)512 * 2 * D_,
            aobuf + (long)512 * D_, nullptr,
            512, DH_, 512, NTOK, 2 * D_, D_,
            sSimB, sSimH, sKVB, DH_, sAoB, DH_, H_, 1.0f, 0, 0);
        mma_gemm<64, 32, 32, true><<<dim3(1, 1, B_ * H_), 256, SM_T64>>>(
            simbuf + (long)1024 * NTOK, kvbuf + D_,
            aobuf + (long)1024 * D_, nullptr,
            16, DH_, NTOK, NTOK, 2 * D_, D_,
            sSimB, sSimH, sKVB, DH_, sAoB, DH_, H_, 1.0f, 0, 0);

        tcn(aobuf, woT_l, tokens, tokens, ROWS, D_, D_, D_, D_, D_, 1.0f, 0, D_);

        ln_kernel<<<ROWS, 256>>>(tokens, g_l, hbuf);
        tcn(hbuf, w1T_l, ff1buf, nullptr, ROWS, FF2_, D_, D_, D_, FF2_, 1.0f);
        {
            long total = (long)ROWS * FF_;
            geglu_kernel<<<(int)((total + 255) / 256), 256>>>(ff1buf, actbuf);
        }
        tcn(actbuf, w2T_l, tokens, tokens, ROWS, D_, FF_, ACTLD, FF2TLD, D_, 1.0f, 0, D_);
    }

    // --- final LN + attention pooling ---
    ln_kernel<<<ROWS, 256>>>(tokens, final_g, hbuf);

    gemm_small(ret_tok, pool_wq, qbuf, nullptr, 4, D_, D_, D_, D_, D_, scale);
    tcn(hbuf, pkvT, kvbuf, nullptr, ROWS, 2 * D_, D_, D_, D_, 2 * D_, 1.0f);

    // pool sim [b,h,r,j]
    {
        dim3 grid((NTOK + 63) / 64, 1, B_ * H_);
        gemm_kernel<64, 64, 16, 4, 4, true><<<grid, 256>>>(
            qbuf, kvbuf, simbuf, nullptr,
            4, NTOK, DH_, D_, 2 * D_, NTOK,
            0L, DH_, sKVB, DH_,
            (long)H_ * 4 * NTOK, (long)4 * NTOK, H_,
            1.0f, 0, 0);
    }

    softmax_pool_kernel<<<B_ * H_ * 4, 256>>>(simbuf);

    // pool out [b,r,h*64+d] = attn @ v
    {
        dim3 grid(1, 1, B_ * H_);
        gemm_kernel<64, 64, 16, 4, 4, false><<<grid, 256>>>(
            simbuf, kvbuf + D_, aobuf, nullptr,
            4, DH_, NTOK, NTOK, 2 * D_, D_,
            (long)H_ * 4 * NTOK, (long)4 * NTOK,
            sKVB, DH_,
            (long)4 * D_, DH_, H_,
            1.0f, 0, 0);
    }

    gemm_small(aobuf, pool_wo, out, ret_tok, B_ * 4, D_, D_, D_, D_, D_, 1.0f,
               /*resRowMod=*/4, /*ldres=*/D_);
}

// round 6
// speedup vs baseline: 4.9374x; 1.3550x over previous
#include <cuda_runtime.h>
#include <cuda_fp16.h>
#include <math.h>
#include <stdint.h>

// ---------------------------------------------------------------------------
// Problem constants
// ---------------------------------------------------------------------------
static constexpr int B_    = 4;
static constexpr int NTOK  = 1040;   // 512 + 512 + 16
static constexpr int D_    = 1024;
static constexpr int H_    = 16;
static constexpr int DH_   = 64;
static constexpr int L_    = 4;
static constexpr int FF_   = 2730;
static constexpr int FF2_  = 5460;
static constexpr int ROWS  = B_ * NTOK;   // 4160
static constexpr int ACTLD = 2736;        // padded act row stride (halves, 16B-mult)

// ---------------------------------------------------------------------------
// Device scratch
// ---------------------------------------------------------------------------
__device__ float  g_tokens[B_ * NTOK * D_];
__device__ float  g_sim   [(long long)B_ * H_ * NTOK * NTOK];   // QK out (fp32)
__device__ float  g_poolq [4 * D_];
__device__ float  g_poolao[B_ * 4 * D_];
__device__ __half h_h     [ROWS * D_];
__device__ __half h_q     [ROWS * D_];
__device__ __half h_kv    [ROWS * 2 * D_];
__device__ __half h_simP  [(long long)B_ * H_ * NTOK * NTOK];   // probs (fp16)
__device__ __half h_ao    [ROWS * D_];
__device__ __half h_ff1   [(long long)ROWS * FF2_];
__device__ __half h_act   [(long long)ROWS * ACTLD];
// transposed fp16 weights
__device__ __half h_wqT [L_ * D_ * D_];
__device__ __half h_wkvT[L_ * 2 * D_ * D_];
__device__ __half h_woT [L_ * D_ * D_];
__device__ __half h_ff1T[(long long)L_ * FF2_ * D_];
__device__ __half h_ff2T[(long long)L_ * D_ * ACTLD];
__device__ __half h_pkvT[2 * D_ * D_];

// ---------------------------------------------------------------------------
// Helpers
// ---------------------------------------------------------------------------
__device__ __forceinline__ uint32_t smem_u32(const void* p) {
    uint32_t a;
    asm("{ .reg .u64 t; cvta.to.shared.u64 t, %1; cvt.u32.u64 %0, t; }"
        : "=r"(a) : "l"(p));
    return a;
}

__device__ __forceinline__ void mma_f16(float* c, const uint32_t* a, const uint32_t* b) {
    asm volatile(
        "mma.sync.aligned.m16n8k16.row.col.f32.f16.f16.f32 "
        "{%0,%1,%2,%3}, {%4,%5,%6,%7}, {%8,%9}, {%0,%1,%2,%3};"
        : "+f"(c[0]), "+f"(c[1]), "+f"(c[2]), "+f"(c[3])
        : "r"(a[0]), "r"(a[1]), "r"(a[2]), "r"(a[3]), "r"(b[0]), "r"(b[1]));
}

#define LDSM4(d, addr)                                                         \
    asm volatile("ldmatrix.sync.aligned.m8n8.x4.shared.b16 {%0,%1,%2,%3}, [%4];" \
        : "=r"((d)[0]), "=r"((d)[1]), "=r"((d)[2]), "=r"((d)[3]) : "r"(addr))
#define LDSM4T(d, addr)                                                        \
    asm volatile("ldmatrix.sync.aligned.m8n8.x4.trans.shared.b16 {%0,%1,%2,%3}, [%4];" \
        : "=r"((d)[0]), "=r"((d)[1]), "=r"((d)[2]), "=r"((d)[3]) : "r"(addr))

__device__ __forceinline__ void cp16h(uint32_t dst, const __half* src, int bytes) {
    asm volatile("cp.async.cg.shared.global [%0], [%1], 16, %2;"
                 :: "r"(dst), "l"(src), "r"(bytes));
}
#define CP_COMMIT() asm volatile("cp.async.commit_group;" ::: "memory")
#define CP_WAIT1()  asm volatile("cp.async.wait_group 1;" ::: "memory")

// ---------------------------------------------------------------------------
// fp16 mma.sync GEMM, 3-stage cp.async pipeline, ldmatrix fragments.
//   C[M,N] = alpha * A[M,K] @ B (+Res)
//   TRANSB=false: B global is [N,K] row-major (k contiguous)   -> ldmatrix
//   TRANSB=true : B global is [K,N] row-major (n contiguous)   -> ldmatrix.trans
//   OUTH: write __half C, else float C (Res always float).
// BM=128, BK=32 (2 x k16 steps), 256 threads.
// ---------------------------------------------------------------------------
template<int BN, int WTM, int WTN, bool TRANSB, bool OUTH>
__global__ void __launch_bounds__(256, 2)
hgemm(const __half* __restrict__ A, const __half* __restrict__ Bm,
      void* __restrict__ Cv, const float* __restrict__ Res,
      int M, int N, int K, int lda, int ldb, int ldc,
      long sAb, long sAh, long sBb, long sBh, long sCb, long sCh, int Hdiv,
      float alpha, int resRowMod, int ldres) {
    constexpr int WN = BN / WTN;
    constexpr int MT = WTM / 16;
    constexpr int NT = WTN / 8;
    constexpr int A_ST_H = 128 * 40;
    constexpr int B_ST_H = TRANSB ? 32 * (BN + 8) : BN * 40;
    constexpr int ST_H   = A_ST_H + B_ST_H;       // halves per stage
    constexpr int BE     = TRANSB ? 1 : BN / 64;  // B chunks per thread

    extern __shared__ __align__(16) __half smem[];
    const uint32_t sb = smem_u32(smem);

    const int tid = threadIdx.x;
    const int wid = tid >> 5, lane = tid & 31;
    const int g = lane >> 2, t4 = lane & 3;
    const int wm = wid / WN, wn = wid % WN;
    const int q8 = lane >> 3, r8 = lane & 7;

    int z = blockIdx.z;
    int zb = z / Hdiv, zh = z - zb * Hdiv;
    A  += (long)zb * sAb + (long)zh * sAh;
    Bm += (long)zb * sBb + (long)zh * sBh;

    const int rowBase = blockIdx.y * 128;
    const int colBase = blockIdx.x * BN;
    const int KC = (K + 31) >> 5;

    // ---- A producer: 2 chunks/thread ----
    const int chA = tid & 3;                 // 8-half chunk within 32-half row
    const float kdummy = 0.0f; (void)kdummy;
    const __half* aSrc[2];
    uint32_t aOff[2];
    bool aOk[2];
    #pragma unroll
    for (int e = 0; e < 2; e++) {
        int m = (tid >> 2) + 64 * e;
        int gr = rowBase + m;
        aOk[e] = gr < M;
        aSrc[e] = A + (long)(aOk[e] ? gr : 0) * lda + chA * 8;
        aOff[e] = (uint32_t)((m * 40 + chA * 8) * 2);
    }

    // ---- B producer ----
    const __half* bSrc[BE ? BE : 1];
    uint32_t bOff[BE ? BE : 1];
    int bGuard[BE ? BE : 1];     // !TRANSB: row-ok; TRANSB: n-bytes
    int bKK = 0;
    if (TRANSB) {
        const int chB = tid & 7;
        bKK = tid >> 3;          // k row 0..31
        int gn = colBase + chB * 8;
        int nb = (N - gn) * 2;
        nb = nb < 0 ? 0 : (nb > 16 ? 16 : nb);
        bGuard[0] = nb;
        bSrc[0] = Bm + (long)bKK * ldb + (nb ? gn : 0);
        bOff[0] = (uint32_t)((bKK * (BN + 8) + chB * 8) * 2);
    } else {
        #pragma unroll
        for (int e = 0; e < BE; e++) {
            int n = (tid >> 2) + 64 * e;
            int gn = colBase + n;
            bGuard[e] = (gn < N) ? 1 : 0;
            bSrc[e] = Bm + (long)(bGuard[e] ? gn : 0) * ldb + chA * 8;
            bOff[e] = (uint32_t)((n * 40 + chA * 8) * 2);
        }
    }

    auto issue = [&](int c, int st) {
        const uint32_t stb = sb + (uint32_t)(st * ST_H * 2);
        int krem = K - (c << 5);
        int kb = (krem - chA * 8) * 2;
        kb = kb < 0 ? 0 : (kb > 16 ? 16 : kb);
        #pragma unroll
        for (int e = 0; e < 2; e++) {
            int bytes = aOk[e] ? kb : 0;
            cp16h(stb + aOff[e], bytes ? aSrc[e] : A, bytes);
            aSrc[e] += 32;
        }
        const uint32_t bstb = stb + (uint32_t)(A_ST_H * 2);
        if (TRANSB) {
            int bytes = (bKK < krem) ? bGuard[0] : 0;
            cp16h(bstb + bOff[0], bytes ? bSrc[0] : Bm, bytes);
            bSrc[0] += (long)32 * ldb;
        } else {
            #pragma unroll
            for (int e = 0; e < BE; e++) {
                int bytes = bGuard[e] ? kb : 0;
                cp16h(bstb + bOff[e], bytes ? bSrc[e] : Bm, bytes);
                bSrc[e] += 32;
            }
        }
        CP_COMMIT();
    };

    float acc[MT][NT][4];
    #pragma unroll
    for (int i = 0; i < MT; i++)
        #pragma unroll
        for (int j = 0; j < NT; j++)
            #pragma unroll
            for (int q = 0; q < 4; q++) acc[i][j][q] = 0.0f;

    // fragment half-index bases
    const int aIdx0 = (wm * WTM + (q8 & 1) * 8 + r8) * 40 + (q8 >> 1) * 8;
    const int bIdx0 = TRANSB
        ? ((q8 & 1) * 8 + r8) * (BN + 8) + wn * WTN + (q8 >> 1) * 8
        : (wn * WTN + (q8 >> 1) * 8 + r8) * 40 + (q8 & 1) * 8;

    issue(0, 0);
    issue(1, 1);

    int st = 0;
    for (int c = 0; c < KC; c++) {
        CP_WAIT1();
        __syncthreads();
        if (c + 2 < KC) issue(c + 2, (st + 2) % 3);
        else CP_COMMIT();

        const uint32_t aStB = sb + (uint32_t)(st * ST_H * 2);
        const uint32_t bStB = aStB + (uint32_t)(A_ST_H * 2);

        #pragma unroll
        for (int ks = 0; ks < 2; ks++) {
            uint32_t af[MT][4], bf[NT][2];
            #pragma unroll
            for (int mt = 0; mt < MT; mt++)
                LDSM4(af[mt], aStB + (uint32_t)((aIdx0 + mt * 16 * 40 + ks * 16) * 2));
            #pragma unroll
            for (int p = 0; p < NT / 2; p++) {
                uint32_t d[4];
                if (TRANSB)
                    LDSM4T(d, bStB + (uint32_t)((bIdx0 + ks * 16 * (BN + 8) + p * 16) * 2));
                else
                    LDSM4(d, bStB + (uint32_t)((bIdx0 + p * 16 * 40 + ks * 16) * 2));
                bf[2 * p][0] = d[0]; bf[2 * p][1] = d[1];
                bf[2 * p + 1][0] = d[2]; bf[2 * p + 1][1] = d[3];
            }
            #pragma unroll
            for (int mt = 0; mt < MT; mt++)
                #pragma unroll
                for (int nt = 0; nt < NT; nt++)
                    mma_f16(acc[mt][nt], af[mt], bf[nt]);
        }
        st++; if (st == 3) st = 0;
    }

    // Epilogue
    #pragma unroll
    for (int mt = 0; mt < MT; mt++) {
        int r0 = rowBase + wm * WTM + mt * 16 + g;
        #pragma unroll
        for (int nt = 0; nt < NT; nt++) {
            int col = colBase + wn * WTN + nt * 8 + t4 * 2;
            if (col >= N) continue;
            #pragma unroll
            for (int hh = 0; hh < 2; hh++) {
                int rr = r0 + hh * 8;
                if (rr >= M) continue;
                float vx = alpha * acc[mt][nt][hh * 2];
                float vy = alpha * acc[mt][nt][hh * 2 + 1];
                if (Res) {
                    int rx = resRowMod ? (rr % resRowMod) : rr;
                    float2 rv = *(const float2*)(Res + (long)rx * ldres + col);
                    vx += rv.x; vy += rv.y;
                }
                if (OUTH) {
                    __half* Ch = (__half*)Cv + (long)zb * sCb + (long)zh * sCh;
                    *(__half2*)(Ch + (long)rr * ldc + col) = __floats2half2_rn(vx, vy);
                } else {
                    float* Cf = (float*)Cv + (long)zb * sCb + (long)zh * sCh;
                    float2 v; v.x = vx; v.y = vy;
                    *(float2*)(Cf + (long)rr * ldc + col) = v;
                }
            }
        }
    }
}

// ---------------------------------------------------------------------------
// Weight transpose: dst[z][n][k] = (half) src[z][k][n]
// ---------------------------------------------------------------------------
__global__ void transpose_kernel(const float* __restrict__ src,
                                 __half* __restrict__ dst,
                                 int K, int N, int ldd) {
    __shared__ float tile[32][33];
    int k0 = blockIdx.y * 32, n0 = blockIdx.x * 32;
    long zS = (long)blockIdx.z * K * N;
    long zD = (long)blockIdx.z * N * ldd;
    int tx = threadIdx.x, ty = threadIdx.y;   // 32 x 8
    #pragma unroll
    for (int i = ty; i < 32; i += 8) {
        int k = k0 + i, n = n0 + tx;
        if (k < K && n < N) tile[i][tx] = src[zS + (long)k * N + n];
    }
    __syncthreads();
    #pragma unroll
    for (int i = ty; i < 32; i += 8) {
        int n = n0 + i, k = k0 + tx;
        if (n < N && k < K) dst[zD + (long)n * ldd + k] = __float2half(tile[tx][i]);
    }
}

// ---------------------------------------------------------------------------
// Small SIMT GEMM (tiny pool launches), mixed input types
// ---------------------------------------------------------------------------
template<typename T>
__device__ __forceinline__ float ldf(const T* p) { return (float)*p; }
template<>
__device__ __forceinline__ float ldf<__half>(const __half* p) { return __half2float(*p); }

template<int BM, int BN, int BK, int TM, int TN, bool TB, typename TAT, typename TBT>
__global__ void __launch_bounds__((BM / TM) * (BN / TN))
gemm_kernel(const TAT* __restrict__ A, const TBT* __restrict__ Bm,
            float* __restrict__ C, const float* __restrict__ Res,
            int M, int Nn, int K,
            int lda, int ldb, int ldc,
            long sAb, long sAh, long sBb, long sBh, long sCb, long sCh, int Hdiv,
            float alpha, int resRowMod, int ldres) {
    constexpr int THREADS = (BM / TM) * (BN / TN);
    constexpr int AELEM = BM * BK / THREADS;
    constexpr int BELEM = BK * BN / THREADS;

    int z = blockIdx.z;
    int zb = z / Hdiv, zh = z - zb * Hdiv;
    A  += (long)zb * sAb + (long)zh * sAh;
    Bm += (long)zb * sBb + (long)zh * sBh;
    C  += (long)zb * sCb + (long)zh * sCh;

    __shared__ __align__(16) float As[BK][BM + 4];
    __shared__ __align__(16) float Bs[BK][BN + 4];

    int tid = threadIdx.x;
    int tcol = tid % (BN / TN);
    int trow = tid / (BN / TN);
    int rowBase = blockIdx.y * BM;
    int colBase = blockIdx.x * BN;

    float acc[TM][TN] = {};

    for (int k0 = 0; k0 < K; k0 += BK) {
        #pragma unroll
        for (int e = 0; e < AELEM; e++) {
            int idx = tid + e * THREADS;
            int m = idx / BK, kk = idx % BK;
            int gr = rowBase + m, gc = k0 + kk;
            As[kk][m] = (gr < M && gc < K) ? ldf(A + (long)gr * lda + gc) : 0.0f;
        }
        #pragma unroll
        for (int e = 0; e < BELEM; e++) {
            int idx = tid + e * THREADS;
            int kk, n;
            if (!TB) { kk = idx / BN; n = idx % BN; }
            else     { n = idx / BK;  kk = idx % BK; }
            int gc = colBase + n, gk = k0 + kk;
            float v = 0.0f;
            if (gc < Nn && gk < K)
                v = TB ? ldf(Bm + (long)gc * ldb + gk) : ldf(Bm + (long)gk * ldb + gc);
            Bs[kk][n] = v;
        }
        __syncthreads();

        #pragma unroll
        for (int kk = 0; kk < BK; kk++) {
            float a[TM], bb[TN];
            #pragma unroll
            for (int i = 0; i < TM; i++) a[i] = As[kk][trow * TM + i];
            #pragma unroll
            for (int j = 0; j < TN; j++) bb[j] = Bs[kk][tcol * TN + j];
            #pragma unroll
            for (int i = 0; i < TM; i++)
                #pragma unroll
                for (int j = 0; j < TN; j++)
                    acc[i][j] += a[i] * bb[j];
        }
        __syncthreads();
    }

    #pragma unroll
    for (int i = 0; i < TM; i++) {
        int r = rowBase + trow * TM + i;
        if (r >= M) continue;
        #pragma unroll
        for (int j = 0; j < TN; j++) {
            int c = colBase + tcol * TN + j;
            if (c >= Nn) continue;
            float v = alpha * acc[i][j];
            if (Res) {
                int rr = resRowMod ? (r % resRowMod) : r;
                v += Res[(long)rr * ldres + c];
            }
            C[(long)r * ldc + c] = v;
        }
    }
}

// ---------------------------------------------------------------------------
// Elementwise / reduction kernels
// ---------------------------------------------------------------------------
__device__ __forceinline__ float blk_reduce(float v, bool ismax) {
    __shared__ float red[9];
    #pragma unroll
    for (int o = 16; o; o >>= 1) {
        float u = __shfl_xor_sync(0xffffffffu, v, o);
        v = ismax ? fmaxf(v, u) : (v + u);
    }
    if ((threadIdx.x & 31) == 0) red[threadIdx.x >> 5] = v;
    __syncthreads();
    if (threadIdx.x == 0) {
        float r = red[0];
        int nw = blockDim.x >> 5;
        for (int w = 1; w < nw; w++) r = ismax ? fmaxf(r, red[w]) : (r + red[w]);
        red[8] = r;
    }
    __syncthreads();
    float r = red[8];
    __syncthreads();
    return r;
}

__device__ __forceinline__ int token_type(int j) {
    return j < 512 ? 0 : (j < 1024 ? 1 : 2);
}

__global__ void concat_kernel(const float4* __restrict__ m0,
                              const float4* __restrict__ m1,
                              const float4* __restrict__ fus,
                              float4* __restrict__ tokens) {
    int idx = blockIdx.x * blockDim.x + threadIdx.x;
    const int D4 = D_ / 4;
    int total = B_ * NTOK * D4;
    if (idx >= total) return;
    int d = idx % D4;
    int t = (idx / D4) % NTOK;
    int b = idx / (D4 * NTOK);
    float4 v;
    if (t < 512)       v = m0[((long)b * 512 + t) * D4 + d];
    else if (t < 1024) v = m1[((long)b * 512 + (t - 512)) * D4 + d];
    else               v = fus[(long)(t - 1024) * D4 + d];
    tokens[idx] = v;
}

// LayerNorm: fp32 in -> fp16 out
__global__ void ln_kernel(const float* __restrict__ x,
                          const float* __restrict__ gamma,
                          __half* __restrict__ out) {
    long row = blockIdx.x;
    const float4* xr = (const float4*)(x + row * D_);
    float4 v = xr[threadIdx.x];
    float s = v.x + v.y + v.z + v.w;
    float mean = blk_reduce(s, false) * (1.0f / D_);
    float dx = v.x - mean, dy = v.y - mean, dz = v.z - mean, dw = v.w - mean;
    float s2 = dx * dx + dy * dy + dz * dz + dw * dw;
    float var = blk_reduce(s2, false) * (1.0f / D_);
    float inv = rsqrtf(var + 1e-5f);
    float4 g = ((const float4*)gamma)[threadIdx.x];
    __half2* o = (__half2*)(out + row * D_);
    o[2 * threadIdx.x]     = __floats2half2_rn(dx * inv * g.x, dy * inv * g.y);
    o[2 * threadIdx.x + 1] = __floats2half2_rn(dz * inv * g.z, dw * inv * g.w);
}

// Range-limited self softmax: fp32 sim in -> fp16 probs out
__global__ void softmax_self_kernel(const float* __restrict__ sim,
                                    __half* __restrict__ probs) {
    long row = blockIdx.x;
    int i = (int)(row % NTOK);
    int ti = token_type(i);
    int c0  = (ti == 1) ? 512 : 0;
    int len = (ti == 2) ? NTOK : 512;
    const float* p = sim + row * NTOK + c0;
    __half* ph = probs + row * NTOK + c0;
    int tid = threadIdx.x;

    float vals[5];
    float mx = -3.4e38f;
    #pragma unroll
    for (int it = 0; it < 5; it++) {
        int j = tid + it * 256;
        float v = (j < len) ? p[j] : -3.4e38f;
        vals[it] = v;
        mx = fmaxf(mx, v);
    }
    mx = blk_reduce(mx, true);

    float e[5];
    float s = 0.0f;
    #pragma unroll
    for (int it = 0; it < 5; it++) {
        float ex = __expf(vals[it] - mx);
        e[it] = ex;
        s += ex;
    }
    s = blk_reduce(s, false);
    float inv = 1.0f / s;
    #pragma unroll
    for (int it = 0; it < 5; it++) {
        int j = tid + it * 256;
        if (j < len) ph[j] = __float2half(e[it] * inv);
    }
}

// Pool softmax: fp32 in/out, masked full row
__global__ void softmax_pool_kernel(float* __restrict__ sim) {
    long row = blockIdx.x;
    float* p = sim + row * NTOK;
    int r = (int)(row % 4);
    int tid = threadIdx.x;

    float vals[5];
    float mx = -3.4e38f;
    #pragma unroll
    for (int it = 0; it < 5; it++) {
        int j = tid + it * 256;
        float v = -3.4e38f;
        if (j < NTOK) {
            bool ok = (r == 3) || (token_type(j) == r);
            v = ok ? p[j] : -3.4e38f;
        }
        vals[it] = v;
        mx = fmaxf(mx, v);
    }
    mx = blk_reduce(mx, true);

    float e[5];
    float s = 0.0f;
    #pragma unroll
    for (int it = 0; it < 5; it++) {
        float ex = __expf(vals[it] - mx);
        e[it] = ex;
        s += ex;
    }
    s = blk_reduce(s, false);
    float inv = 1.0f / s;
    #pragma unroll
    for (int it = 0; it < 5; it++) {
        int j = tid + it * 256;
        if (j < NTOK) p[j] = e[it] * inv;
    }
}

// GEGLU: fp16 ff1 in -> fp16 act out
__global__ void geglu_kernel(const __half* __restrict__ ff1,
                             __half* __restrict__ act) {
    long idx = (long)blockIdx.x * blockDim.x + threadIdx.x;
    long total = (long)ROWS * FF_;
    if (idx >= total) return;
    long row = idx / FF_;
    int f = (int)(idx - row * FF_);
    const __half* p = ff1 + row * FF2_;
    float val = __half2float(p[f]);
    float gate = __half2float(p[FF_ + f]);
    float g = 0.5f * gate * (1.0f + erff(gate * 0.70710678118654752f));
    act[row * (long)ACTLD + f] = __float2half(g * val);
}

// ---------------------------------------------------------------------------
// Host side
// ---------------------------------------------------------------------------
static constexpr int SM_H128 = 3 * (128 * 40 + 128 * 40) * 2;       // 61440
static constexpr int SM_HPV  = 3 * (128 * 40 + 32 * 72) * 2;        // 44544

static inline void hg(const __half* A, const __half* Bt, void* C, const float* Res,
                      int M, int Nn, int K, int lda, int ldbT, int ldc, float alpha,
                      bool outh, int resRowMod = 0, int ldres = 0) {
    dim3 grid((Nn + 127) / 128, (M + 127) / 128, 1);
    if (outh)
        hgemm<128, 64, 32, false, true><<<grid, 256, SM_H128>>>(
            A, Bt, C, Res, M, Nn, K, lda, ldbT, ldc,
            0, 0, 0, 0, 0, 0, 1, alpha, resRowMod, ldres);
    else
        hgemm<128, 64, 32, false, false><<<grid, 256, SM_H128>>>(
            A, Bt, C, Res, M, Nn, K, lda, ldbT, ldc,
            0, 0, 0, 0, 0, 0, 1, alpha, resRowMod, ldres);
}

extern "C" void kernel_launch(void* const* d_in, const int* in_sizes, int n_in,
                              void* d_out, int out_size) {
    const float* m0        = (const float*)d_in[0];
    const float* m1        = (const float*)d_in[1];
    const float* fusion    = (const float*)d_in[2];
    const float* ret_tok   = (const float*)d_in[3];
    const float* ln_gamma  = (const float*)d_in[4];
    const float* wq        = (const float*)d_in[5];
    const float* wkv       = (const float*)d_in[6];
    const float* wo        = (const float*)d_in[7];
    const float* ff_w1     = (const float*)d_in[8];
    const float* ff_w2     = (const float*)d_in[9];
    const float* pool_wq   = (const float*)d_in[10];
    const float* pool_wkv  = (const float*)d_in[11];
    const float* pool_wo   = (const float*)d_in[12];
    const float* final_g   = (const float*)d_in[13];
    float* out = (float*)d_out;

    cudaFuncSetAttribute(hgemm<128, 64, 32, false, true>,
                         cudaFuncAttributeMaxDynamicSharedMemorySize, SM_H128);
    cudaFuncSetAttribute(hgemm<128, 64, 32, false, false>,
                         cudaFuncAttributeMaxDynamicSharedMemorySize, SM_H128);
    cudaFuncSetAttribute(hgemm<64, 32, 32, true, true>,
                         cudaFuncAttributeMaxDynamicSharedMemorySize, SM_HPV);

    float *tokens, *simbuf, *poolq, *poolao;
    __half *hbuf, *qbuf, *kvbuf, *simP, *aobuf, *ff1buf, *actbuf;
    __half *wqT, *wkvT, *woT, *ff1T, *ff2T, *pkvT;
    cudaGetSymbolAddress((void**)&tokens, g_tokens);
    cudaGetSymbolAddress((void**)&simbuf, g_sim);
    cudaGetSymbolAddress((void**)&poolq,  g_poolq);
    cudaGetSymbolAddress((void**)&poolao, g_poolao);
    cudaGetSymbolAddress((void**)&hbuf,   h_h);
    cudaGetSymbolAddress((void**)&qbuf,   h_q);
    cudaGetSymbolAddress((void**)&kvbuf,  h_kv);
    cudaGetSymbolAddress((void**)&simP,   h_simP);
    cudaGetSymbolAddress((void**)&aobuf,  h_ao);
    cudaGetSymbolAddress((void**)&ff1buf, h_ff1);
    cudaGetSymbolAddress((void**)&actbuf, h_act);
    cudaGetSymbolAddress((void**)&wqT,    h_wqT);
    cudaGetSymbolAddress((void**)&wkvT,   h_wkvT);
    cudaGetSymbolAddress((void**)&woT,    h_woT);
    cudaGetSymbolAddress((void**)&ff1T,   h_ff1T);
    cudaGetSymbolAddress((void**)&ff2T,   h_ff2T);
    cudaGetSymbolAddress((void**)&pkvT,   h_pkvT);

    // --- weight pre-transposes (fp32 -> fp16, graph-captured) ---
    {
        dim3 thr(32, 8);
        transpose_kernel<<<dim3(32, 32, 4),  thr>>>(wq,       wqT,  1024, 1024, 1024);
        transpose_kernel<<<dim3(64, 32, 4),  thr>>>(wkv,      wkvT, 1024, 2048, 1024);
        transpose_kernel<<<dim3(32, 32, 4),  thr>>>(wo,       woT,  1024, 1024, 1024);
        transpose_kernel<<<dim3(171, 32, 4), thr>>>(ff_w1,    ff1T, 1024, 5460, 1024);
        transpose_kernel<<<dim3(32, 86, 4),  thr>>>(ff_w2,    ff2T, 2730, 1024, ACTLD);
        transpose_kernel<<<dim3(64, 32, 1),  thr>>>(pool_wkv, pkvT, 1024, 2048, 1024);
    }

    {
        int total = B_ * NTOK * (D_ / 4);
        concat_kernel<<<(total + 255) / 256, 256>>>(
            (const float4*)m0, (const float4*)m1, (const float4*)fusion,
            (float4*)tokens);
    }

    const float scale = 0.125f;
    const long sSimB = (long)H_ * NTOK * NTOK;
    const long sSimH = (long)NTOK * NTOK;
    const long sQB   = (long)NTOK * D_;
    const long sKVB  = (long)NTOK * 2 * D_;
    const long sAoB  = (long)NTOK * D_;

    for (int l = 0; l < L_; l++) {
        const __half* wqT_l  = wqT  + (long)l * D_ * D_;
        const __half* wkvT_l = wkvT + (long)l * 2 * D_ * D_;
        const __half* woT_l  = woT  + (long)l * D_ * D_;
        const __half* w1T_l  = ff1T + (long)l * FF2_ * D_;
        const __half* w2T_l  = ff2T + (long)l * D_ * ACTLD;
        const float*  g_l    = ln_gamma + (long)l * D_;

        ln_kernel<<<ROWS, 256>>>(tokens, g_l, hbuf);
        hg(hbuf, wqT_l,  qbuf,  nullptr, ROWS, D_,     D_, D_, D_, D_,     scale, true);
        hg(hbuf, wkvT_l, kvbuf, nullptr, ROWS, 2 * D_, D_, D_, D_, 2 * D_, 1.0f,  true);

        // --- QK: 3 restricted launches, fp32 out ---
        hgemm<128, 64, 32, false, false><<<dim3(4, 4, B_ * H_), 256, SM_H128>>>(
            qbuf, kvbuf, simbuf, nullptr,
            512, 512, DH_, D_, 2 * D_, NTOK,
            sQB, DH_, sKVB, DH_, sSimB, sSimH, H_, 1.0f, 0, 0);
        hgemm<128, 64, 32, false, false><<<dim3(4, 4, B_ * H_), 256, SM_H128>>>(
            qbuf + (long)512 * D_, kvbuf + (long)512 * 2 * D_,
            simbuf + (long)512 * NTOK + 512, nullptr,
            512, 512, DH_, D_, 2 * D_, NTOK,
            sQB, DH_, sKVB, DH_, sSimB, sSimH, H_, 1.0f, 0, 0);
        hgemm<128, 64, 32, false, false><<<dim3(9, 1, B_ * H_), 256, SM_H128>>>(
            qbuf + (long)1024 * D_, kvbuf,
            simbuf + (long)1024 * NTOK, nullptr,
            16, NTOK, DH_, D_, 2 * D_, NTOK,
            sQB, DH_, sKVB, DH_, sSimB, sSimH, H_, 1.0f, 0, 0);

        softmax_self_kernel<<<B_ * H_ * NTOK, 256>>>(simbuf, simP);

        // --- PV: probs(fp16) @ V(fp16, [K][N] via ldmatrix.trans), fp16 out ---
        hgemm<64, 32, 32, true, true><<<dim3(1, 4, B_ * H_), 256, SM_HPV>>>(
            simP, kvbuf + D_, aobuf, nullptr,
            512, DH_, 512, NTOK, 2 * D_, D_,
            sSimB, sSimH, sKVB, DH_, sAoB, DH_, H_, 1.0f, 0, 0);
        hgemm<64, 32, 32, true, true><<<dim3(1, 4, B_ * H_), 256, SM_HPV>>>(
            simP + (long)512 * NTOK + 512, kvbuf + D_ + (long)512 * 2 * D_,
            aobuf + (long)512 * D_, nullptr,
            512, DH_, 512, NTOK, 2 * D_, D_,
            sSimB, sSimH, sKVB, DH_, sAoB, DH_, H_, 1.0f, 0, 0);
        hgemm<64, 32, 32, true, true><<<dim3(1, 1, B_ * H_), 256, SM_HPV>>>(
            simP + (long)1024 * NTOK, kvbuf + D_,
            aobuf + (long)1024 * D_, nullptr,
            16, DH_, NTOK, NTOK, 2 * D_, D_,
            sSimB, sSimH, sKVB, DH_, sAoB, DH_, H_, 1.0f, 0, 0);

        hg(aobuf, woT_l, tokens, tokens, ROWS, D_, D_, D_, D_, D_, 1.0f, false, 0, D_);

        ln_kernel<<<ROWS, 256>>>(tokens, g_l, hbuf);
        hg(hbuf, w1T_l, ff1buf, nullptr, ROWS, FF2_, D_, D_, D_, FF2_, 1.0f, true);
        {
            long total = (long)ROWS * FF_;
            geglu_kernel<<<(int)((total + 255) / 256), 256>>>(ff1buf, actbuf);
        }
        hg(actbuf, w2T_l, tokens, tokens, ROWS, D_, FF_, ACTLD, ACTLD, D_, 1.0f, false, 0, D_);
    }

    // --- final LN + attention pooling ---
    ln_kernel<<<ROWS, 256>>>(tokens, final_g, hbuf);

    gemm_kernel<64, 64, 16, 4, 4, false, float, float>
        <<<dim3(16, 1, 1), 256>>>(
        ret_tok, pool_wq, poolq, nullptr, 4, D_, D_, D_, D_, D_,
        0, 0, 0, 0, 0, 0, 1, scale, 0, 0);

    hg(hbuf, pkvT, kvbuf, nullptr, ROWS, 2 * D_, D_, D_, D_, 2 * D_, 1.0f, true);

    // pool sim [b,h,r,j] fp32
    gemm_kernel<64, 64, 16, 4, 4, true, float, __half>
        <<<dim3((NTOK + 63) / 64, 1, B_ * H_), 256>>>(
        poolq, kvbuf, simbuf, nullptr,
        4, NTOK, DH_, D_, 2 * D_, NTOK,
        0L, DH_, sKVB, DH_,
        (long)H_ * 4 * NTOK, (long)4 * NTOK, H_,
        1.0f, 0, 0);

    softmax_pool_kernel<<<B_ * H_ * 4, 256>>>(simbuf);

    // pool out [b,r,h*64+d] = attn(fp32) @ v(fp16)
    gemm_kernel<64, 64, 16, 4, 4, false, float, __half>
        <<<dim3(1, 1, B_ * H_), 256>>>(
        simbuf, kvbuf + D_, poolao, nullptr,
        4, DH_, NTOK, NTOK, 2 * D_, D_,
        (long)H_ * 4 * NTOK, (long)4 * NTOK,
        sKVB, DH_,
        (long)4 * D_, DH_, H_,
        1.0f, 0, 0);

    gemm_kernel<64, 64, 16, 4, 4, false, float, float>
        <<<dim3(16, 1, 1), 256>>>(
        poolao, pool_wo, out, ret_tok, B_ * 4, D_, D_, D_, D_, D_,
        0, 0, 0, 0, 0, 0, 1, 1.0f, /*resRowMod=*/4, /*ldres=*/D_);
}

// round 7
// speedup vs baseline: 6.2140x; 1.2586x over previous
#include <cuda_runtime.h>
#include <cuda_fp16.h>
#include <math.h>
#include <stdint.h>

// ---------------------------------------------------------------------------
// Problem constants
// ---------------------------------------------------------------------------
static constexpr int B_    = 4;
static constexpr int NTOK  = 1040;   // 512 + 512 + 16
static constexpr int D_    = 1024;
static constexpr int H_    = 16;
static constexpr int DH_   = 64;
static constexpr int L_    = 4;
static constexpr int FF_   = 2730;
static constexpr int FF2_  = 5460;
static constexpr int ROWS  = B_ * NTOK;   // 4160
static constexpr int ACTLD = 2736;        // padded act row stride

// ---------------------------------------------------------------------------
// Device scratch
// ---------------------------------------------------------------------------
__device__ float  g_tokens[B_ * NTOK * D_];
__device__ float  g_sim   [B_ * H_ * 4 * NTOK];   // pool sim only
__device__ float  g_poolq [4 * D_];
__device__ float  g_poolao[B_ * 4 * D_];
__device__ __half h_h     [ROWS * D_];
__device__ __half h_qkv   [ROWS * 3 * D_];
__device__ __half h_kv    [ROWS * 2 * D_];        // pool kv
__device__ __half h_ao    [ROWS * D_];
__device__ __half h_ff1   [(long long)ROWS * FF2_];
__device__ __half h_act   [(long long)ROWS * ACTLD];
// transposed fp16 weights
__device__ __half h_wqkvT[(long long)L_ * 3 * D_ * D_];
__device__ __half h_woT  [L_ * D_ * D_];
__device__ __half h_ff1T [(long long)L_ * FF2_ * D_];
__device__ __half h_ff2T [(long long)L_ * D_ * ACTLD];
__device__ __half h_pkvT [2 * D_ * D_];

// ---------------------------------------------------------------------------
// Helpers
// ---------------------------------------------------------------------------
__device__ __forceinline__ uint32_t smem_u32(const void* p) {
    uint32_t a;
    asm("{ .reg .u64 t; cvta.to.shared.u64 t, %1; cvt.u32.u64 %0, t; }"
        : "=r"(a) : "l"(p));
    return a;
}

__device__ __forceinline__ void mma_f16(float* c, const uint32_t* a, const uint32_t* b) {
    asm volatile(
        "mma.sync.aligned.m16n8k16.row.col.f32.f16.f16.f32 "
        "{%0,%1,%2,%3}, {%4,%5,%6,%7}, {%8,%9}, {%0,%1,%2,%3};"
        : "+f"(c[0]), "+f"(c[1]), "+f"(c[2]), "+f"(c[3])
        : "r"(a[0]), "r"(a[1]), "r"(a[2]), "r"(a[3]), "r"(b[0]), "r"(b[1]));
}

#define LDSM4(d, addr)                                                         \
    asm volatile("ldmatrix.sync.aligned.m8n8.x4.shared.b16 {%0,%1,%2,%3}, [%4];" \
        : "=r"((d)[0]), "=r"((d)[1]), "=r"((d)[2]), "=r"((d)[3]) : "r"(addr))
#define LDSM4T(d, addr)                                                        \
    asm volatile("ldmatrix.sync.aligned.m8n8.x4.trans.shared.b16 {%0,%1,%2,%3}, [%4];" \
        : "=r"((d)[0]), "=r"((d)[1]), "=r"((d)[2]), "=r"((d)[3]) : "r"(addr))

__device__ __forceinline__ void cp16h(uint32_t dst, const __half* src, int bytes) {
    asm volatile("cp.async.cg.shared.global [%0], [%1], 16, %2;"
                 :: "r"(dst), "l"(src), "r"(bytes));
}
#define CP_COMMIT() asm volatile("cp.async.commit_group;" ::: "memory")
#define CP_WAIT1()  asm volatile("cp.async.wait_group 1;" ::: "memory")
#define CP_WAIT0()  asm volatile("cp.async.wait_group 0;" ::: "memory")

__device__ __forceinline__ uint32_t packh2(float x, float y) {
    __half2 h = __floats2half2_rn(x, y);
    return *(uint32_t*)&h;
}

// ---------------------------------------------------------------------------
// Flash attention (block-masked).  qkv: [B*NTOK][3072] fp16 (q pre-scaled),
// ao: [B*NTOK][1024] fp16.  grid (17, 1, B*H), 128 threads.
// ---------------------------------------------------------------------------
__global__ void __launch_bounds__(128, 2)
flash_kernel(const __half* __restrict__ qkv, __half* __restrict__ ao) {
    constexpr int LDS_ = 72;
    constexpr int QOFF = 0;                 // 64*72 halves
    constexpr int KOFF = 64 * LDS_;
    constexpr int VOFF = KOFF + 2 * 128 * LDS_;
    extern __shared__ __half sm[];
    const uint32_t sb = smem_u32(sm);

    const int tid = threadIdx.x;
    const int w = tid >> 5, lane = tid & 31;
    const int g = lane >> 2, t4 = lane & 3;
    const int q8 = lane >> 3, r8 = lane & 7;

    const int bh = blockIdx.z;
    const int b = bh >> 4, h = bh & 15;
    const int qb = blockIdx.x;
    int q0, c0, clen, qrows;
    if (qb < 16) { q0 = qb * 64; c0 = (qb < 8) ? 0 : 512; clen = 512; qrows = 64; }
    else         { q0 = 1024;  c0 = 0;  clen = NTOK;  qrows = 16; }

    const __half* qb_g = qkv + ((long)b * NTOK) * 3072 + h * 64;
    const __half* kb_g = qkv + ((long)b * NTOK) * 3072 + 1024 + h * 64;
    const __half* vb_g = qkv + ((long)b * NTOK) * 3072 + 2048 + h * 64;

    // Q load (group 0, together with KV tile 0)
    {
        int row = tid >> 1;
        int gr = q0 + row;
        int bytes = (row < qrows) ? 16 : 0;
        const __half* src = qb_g + (long)(bytes ? gr : 0) * 3072 + (tid & 1) * 32;
        uint32_t dst = sb + (QOFF + row * LDS_ + (tid & 1) * 32) * 2;
        #pragma unroll
        for (int e = 0; e < 4; e++)
            cp16h(dst + e * 16, src + e * 8, bytes);
    }

    const int T = (clen + 127) >> 7;
    int issued = 0;
    auto issueKV = [&](int t) {
        int buf = t & 1;
        int j = c0 + t * 128 + tid;
        int bytes = (j < c0 + clen) ? 16 : 0;
        const __half* ks = kb_g + (long)(bytes ? j : 0) * 3072;
        const __half* vs = vb_g + (long)(bytes ? j : 0) * 3072;
        uint32_t kd = sb + (KOFF + buf * 128 * LDS_ + tid * LDS_) * 2;
        uint32_t vd = sb + (VOFF + buf * 128 * LDS_ + tid * LDS_) * 2;
        #pragma unroll
        for (int ch = 0; ch < 8; ch++) cp16h(kd + ch * 16, ks + ch * 8, bytes);
        #pragma unroll
        for (int ch = 0; ch < 8; ch++) cp16h(vd + ch * 16, vs + ch * 8, bytes);
        CP_COMMIT();
        issued++;
    };
    issueKV(0);
    if (T > 1) issueKV(1);

    float m0 = -1e30f, m1 = -1e30f, l0 = 0.f, l1 = 0.f;
    float o[8][4];
    #pragma unroll
    for (int i = 0; i < 8; i++)
        #pragma unroll
        for (int q = 0; q < 4; q++) o[i][q] = 0.f;

    const int aIdx = (w * 16 + (q8 & 1) * 8 + r8) * LDS_ + (q8 >> 1) * 8;
    const int kIdx = ((q8 >> 1) * 8 + r8) * LDS_ + (q8 & 1) * 8;
    const int vIdx = ((q8 & 1) * 8 + r8) * LDS_ + (q8 >> 1) * 8;

    for (int t = 0; t < T; t++) {
        if (issued - (t + 1) >= 1) { CP_WAIT1(); } else { CP_WAIT0(); }
        __syncthreads();

        const uint32_t kb_s = sb + (KOFF + (t & 1) * 128 * LDS_) * 2;
        const uint32_t vb_s = sb + (VOFF + (t & 1) * 128 * LDS_) * 2;
        const uint32_t qs = sb + QOFF * 2;

        // S = Q @ K^T  (64 x 128)
        float s[16][4];
        #pragma unroll
        for (int i = 0; i < 16; i++)
            #pragma unroll
            for (int q = 0; q < 4; q++) s[i][q] = 0.f;

        #pragma unroll
        for (int ks = 0; ks < 4; ks++) {
            uint32_t af[4];
            LDSM4(af, qs + (aIdx + ks * 16) * 2);
            #pragma unroll
            for (int p = 0; p < 8; p++) {
                uint32_t d[4];
                LDSM4(d, kb_s + (kIdx + p * 16 * LDS_ + ks * 16) * 2);
                mma_f16(s[2 * p], af, d);
                mma_f16(s[2 * p + 1], af, d + 2);
            }
        }

        // tail mask (fusion block last tile only)
        int lim = clen - t * 128;
        if (lim < 128) {
            #pragma unroll
            for (int nt = 0; nt < 16; nt++) {
                int cc = nt * 8 + 2 * t4;
                if (cc >= lim)     { s[nt][0] = -1e30f; s[nt][2] = -1e30f; }
                if (cc + 1 >= lim) { s[nt][1] = -1e30f; s[nt][3] = -1e30f; }
            }
        }

        // online softmax stats
        float tm0 = -1e30f, tm1 = -1e30f;
        #pragma unroll
        for (int nt = 0; nt < 16; nt++) {
            tm0 = fmaxf(tm0, fmaxf(s[nt][0], s[nt][1]));
            tm1 = fmaxf(tm1, fmaxf(s[nt][2], s[nt][3]));
        }
        tm0 = fmaxf(tm0, __shfl_xor_sync(0xffffffffu, tm0, 1));
        tm0 = fmaxf(tm0, __shfl_xor_sync(0xffffffffu, tm0, 2));
        tm1 = fmaxf(tm1, __shfl_xor_sync(0xffffffffu, tm1, 1));
        tm1 = fmaxf(tm1, __shfl_xor_sync(0xffffffffu, tm1, 2));

        float nm0 = fmaxf(m0, tm0), nm1 = fmaxf(m1, tm1);
        float sc0 = __expf(m0 - nm0), sc1 = __expf(m1 - nm1);
        m0 = nm0; m1 = nm1;
        l0 *= sc0; l1 *= sc1;
        #pragma unroll
        for (int nt = 0; nt < 8; nt++) {
            o[nt][0] *= sc0; o[nt][1] *= sc0;
            o[nt][2] *= sc1; o[nt][3] *= sc1;
        }

        // P = exp(S - m), pack to fp16 A-fragments
        uint32_t pf[16][2];
        #pragma unroll
        for (int nt = 0; nt < 16; nt++) {
            float p0 = __expf(s[nt][0] - m0);
            float p1 = __expf(s[nt][1] - m0);
            float p2 = __expf(s[nt][2] - m1);
            float p3 = __expf(s[nt][3] - m1);
            l0 += p0 + p1; l1 += p2 + p3;
            pf[nt][0] = packh2(p0, p1);
            pf[nt][1] = packh2(p2, p3);
        }

        // O += P @ V  (64 x 64, k = 128)
        #pragma unroll
        for (int kv = 0; kv < 8; kv++) {
            uint32_t a[4] = { pf[2 * kv][0], pf[2 * kv][1],
                              pf[2 * kv + 1][0], pf[2 * kv + 1][1] };
            #pragma unroll
            for (int p = 0; p < 4; p++) {
                uint32_t d[4];
                LDSM4T(d, vb_s + (vIdx + kv * 16 * LDS_ + p * 16) * 2);
                mma_f16(o[2 * p], a, d);
                mma_f16(o[2 * p + 1], a, d + 2);
            }
        }

        __syncthreads();
        if (t + 2 < T) issueKV(t + 2);
    }

    // final normalize + store
    l0 += __shfl_xor_sync(0xffffffffu, l0, 1);
    l0 += __shfl_xor_sync(0xffffffffu, l0, 2);
    l1 += __shfl_xor_sync(0xffffffffu, l1, 1);
    l1 += __shfl_xor_sync(0xffffffffu, l1, 2);
    float inv0 = 1.0f / l0, inv1 = 1.0f / l1;

    int lr0 = w * 16 + g, lr1 = lr0 + 8;
    __half* aob = ao + ((long)b * NTOK) * 1024 + h * 64;
    if (lr0 < qrows) {
        __half* rp = aob + (long)(q0 + lr0) * 1024 + 2 * t4;
        #pragma unroll
        for (int nt = 0; nt < 8; nt++)
            *(__half2*)(rp + nt * 8) = __floats2half2_rn(o[nt][0] * inv0, o[nt][1] * inv0);
    }
    if (lr1 < qrows) {
        __half* rp = aob + (long)(q0 + lr1) * 1024 + 2 * t4;
        #pragma unroll
        for (int nt = 0; nt < 8; nt++)
            *(__half2*)(rp + nt * 8) = __floats2half2_rn(o[nt][2] * inv1, o[nt][3] * inv1);
    }
}

// ---------------------------------------------------------------------------
// fp16 mma.sync GEMM (linear layers), 3-stage cp.async + ldmatrix.
// ---------------------------------------------------------------------------
template<int BN, int WTM, int WTN, bool OUTH>
__global__ void __launch_bounds__(256, 2)
hgemm(const __half* __restrict__ A, const __half* __restrict__ Bm,
      void* __restrict__ Cv, const float* __restrict__ Res,
      int M, int N, int K, int lda, int ldb, int ldc,
      float alpha, int resRowMod, int ldres) {
    constexpr int WN = BN / WTN;
    constexpr int MT = WTM / 16;
    constexpr int NT = WTN / 8;
    constexpr int A_ST_H = 128 * 40;
    constexpr int B_ST_H = BN * 40;
    constexpr int ST_H   = A_ST_H + B_ST_H;
    constexpr int BE     = BN / 64;

    extern __shared__ __align__(16) __half smem[];
    const uint32_t sb = smem_u32(smem);

    const int tid = threadIdx.x;
    const int wid = tid >> 5, lane = tid & 31;
    const int g = lane >> 2, t4 = lane & 3;
    const int wm = wid / WN, wn = wid % WN;
    const int q8 = lane >> 3, r8 = lane & 7;

    const int rowBase = blockIdx.y * 128;
    const int colBase = blockIdx.x * BN;
    const int KC = (K + 31) >> 5;

    const int chA = tid & 3;
    const __half* aSrc[2];
    uint32_t aOff[2];
    bool aOk[2];
    #pragma unroll
    for (int e = 0; e < 2; e++) {
        int m = (tid >> 2) + 64 * e;
        int gr = rowBase + m;
        aOk[e] = gr < M;
        aSrc[e] = A + (long)(aOk[e] ? gr : 0) * lda + chA * 8;
        aOff[e] = (uint32_t)((m * 40 + chA * 8) * 2);
    }
    const __half* bSrc[BE];
    uint32_t bOff[BE];
    int bOkA[BE];
    #pragma unroll
    for (int e = 0; e < BE; e++) {
        int n = (tid >> 2) + 64 * e;
        int gn = colBase + n;
        bOkA[e] = (gn < N) ? 1 : 0;
        bSrc[e] = Bm + (long)(bOkA[e] ? gn : 0) * ldb + chA * 8;
        bOff[e] = (uint32_t)((n * 40 + chA * 8) * 2);
    }

    auto issue = [&](int c, int st) {
        const uint32_t stb = sb + (uint32_t)(st * ST_H * 2);
        int krem = K - (c << 5);
        int kb = (krem - chA * 8) * 2;
        kb = kb < 0 ? 0 : (kb > 16 ? 16 : kb);
        #pragma unroll
        for (int e = 0; e < 2; e++) {
            int bytes = aOk[e] ? kb : 0;
            cp16h(stb + aOff[e], bytes ? aSrc[e] : A, bytes);
            aSrc[e] += 32;
        }
        const uint32_t bstb = stb + (uint32_t)(A_ST_H * 2);
        #pragma unroll
        for (int e = 0; e < BE; e++) {
            int bytes = bOkA[e] ? kb : 0;
            cp16h(bstb + bOff[e], bytes ? bSrc[e] : Bm, bytes);
            bSrc[e] += 32;
        }
        CP_COMMIT();
    };

    float acc[MT][NT][4];
    #pragma unroll
    for (int i = 0; i < MT; i++)
        #pragma unroll
        for (int j = 0; j < NT; j++)
            #pragma unroll
            for (int q = 0; q < 4; q++) acc[i][j][q] = 0.0f;

    const int aIdx0 = (wm * WTM + (q8 & 1) * 8 + r8) * 40 + (q8 >> 1) * 8;
    const int bIdx0 = (wn * WTN + (q8 >> 1) * 8 + r8) * 40 + (q8 & 1) * 8;

    issue(0, 0);
    issue(1, 1);

    int st = 0;
    for (int c = 0; c < KC; c++) {
        CP_WAIT1();
        __syncthreads();
        if (c + 2 < KC) issue(c + 2, (st + 2) % 3);
        else CP_COMMIT();

        const uint32_t aStB = sb + (uint32_t)(st * ST_H * 2);
        const uint32_t bStB = aStB + (uint32_t)(A_ST_H * 2);

        #pragma unroll
        for (int ks = 0; ks < 2; ks++) {
            uint32_t af[MT][4], bf[NT][2];
            #pragma unroll
            for (int mt = 0; mt < MT; mt++)
                LDSM4(af[mt], aStB + (uint32_t)((aIdx0 + mt * 16 * 40 + ks * 16) * 2));
            #pragma unroll
            for (int p = 0; p < NT / 2; p++) {
                uint32_t d[4];
                LDSM4(d, bStB + (uint32_t)((bIdx0 + p * 16 * 40 + ks * 16) * 2));
                bf[2 * p][0] = d[0]; bf[2 * p][1] = d[1];
                bf[2 * p + 1][0] = d[2]; bf[2 * p + 1][1] = d[3];
            }
            #pragma unroll
            for (int mt = 0; mt < MT; mt++)
                #pragma unroll
                for (int nt = 0; nt < NT; nt++)
                    mma_f16(acc[mt][nt], af[mt], bf[nt]);
        }
        st++; if (st == 3) st = 0;
    }

    #pragma unroll
    for (int mt = 0; mt < MT; mt++) {
        int r0 = rowBase + wm * WTM + mt * 16 + g;
        #pragma unroll
        for (int nt = 0; nt < NT; nt++) {
            int col = colBase + wn * WTN + nt * 8 + t4 * 2;
            if (col >= N) continue;
            #pragma unroll
            for (int hh = 0; hh < 2; hh++) {
                int rr = r0 + hh * 8;
                if (rr >= M) continue;
                float vx = alpha * acc[mt][nt][hh * 2];
                float vy = alpha * acc[mt][nt][hh * 2 + 1];
                if (Res) {
                    int rx = resRowMod ? (rr % resRowMod) : rr;
                    float2 rv = *(const float2*)(Res + (long)rx * ldres + col);
                    vx += rv.x; vy += rv.y;
                }
                if (OUTH) {
                    *(__half2*)((__half*)Cv + (long)rr * ldc + col) = __floats2half2_rn(vx, vy);
                } else {
                    float2 v; v.x = vx; v.y = vy;
                    *(float2*)((float*)Cv + (long)rr * ldc + col) = v;
                }
            }
        }
    }
}

// ---------------------------------------------------------------------------
// Weight transpose: dst[z][n][k] = (half)(scale * src[z][k][n])
// ---------------------------------------------------------------------------
__global__ void transpose_kernel(const float* __restrict__ src,
                                 __half* __restrict__ dst,
                                 int K, int N, int ldd,
                                 long srcZ, long dstZ, float scale) {
    __shared__ float tile[32][33];
    int k0 = blockIdx.y * 32, n0 = blockIdx.x * 32;
    long zS = (long)blockIdx.z * srcZ;
    long zD = (long)blockIdx.z * dstZ;
    int tx = threadIdx.x, ty = threadIdx.y;
    #pragma unroll
    for (int i = ty; i < 32; i += 8) {
        int k = k0 + i, n = n0 + tx;
        if (k < K && n < N) tile[i][tx] = src[zS + (long)k * N + n];
    }
    __syncthreads();
    #pragma unroll
    for (int i = ty; i < 32; i += 8) {
        int n = n0 + i, k = k0 + tx;
        if (n < N && k < K) dst[zD + (long)n * ldd + k] = __float2half(scale * tile[tx][i]);
    }
}

// ---------------------------------------------------------------------------
// Small SIMT GEMM (pool)
// ---------------------------------------------------------------------------
template<typename T>
__device__ __forceinline__ float ldf(const T* p) { return (float)*p; }
template<>
__device__ __forceinline__ float ldf<__half>(const __half* p) { return __half2float(*p); }

template<int BM, int BN, int BK, int TM, int TN, bool TB, typename TAT, typename TBT>
__global__ void __launch_bounds__((BM / TM) * (BN / TN))
gemm_kernel(const TAT* __restrict__ A, const TBT* __restrict__ Bm,
            float* __restrict__ C, const float* __restrict__ Res,
            int M, int Nn, int K,
            int lda, int ldb, int ldc,
            long sAb, long sAh, long sBb, long sBh, long sCb, long sCh, int Hdiv,
            float alpha, int resRowMod, int ldres) {
    constexpr int THREADS = (BM / TM) * (BN / TN);
    constexpr int AELEM = BM * BK / THREADS;
    constexpr int BELEM = BK * BN / THREADS;

    int z = blockIdx.z;
    int zb = z / Hdiv, zh = z - zb * Hdiv;
    A  += (long)zb * sAb + (long)zh * sAh;
    Bm += (long)zb * sBb + (long)zh * sBh;
    C  += (long)zb * sCb + (long)zh * sCh;

    __shared__ __align__(16) float As[BK][BM + 4];
    __shared__ __align__(16) float Bs[BK][BN + 4];

    int tid = threadIdx.x;
    int tcol = tid % (BN / TN);
    int trow = tid / (BN / TN);
    int rowBase = blockIdx.y * BM;
    int colBase = blockIdx.x * BN;

    float acc[TM][TN] = {};

    for (int k0 = 0; k0 < K; k0 += BK) {
        #pragma unroll
        for (int e = 0; e < AELEM; e++) {
            int idx = tid + e * THREADS;
            int m = idx / BK, kk = idx % BK;
            int gr = rowBase + m, gc = k0 + kk;
            As[kk][m] = (gr < M && gc < K) ? ldf(A + (long)gr * lda + gc) : 0.0f;
        }
        #pragma unroll
        for (int e = 0; e < BELEM; e++) {
            int idx = tid + e * THREADS;
            int kk, n;
            if (!TB) { kk = idx / BN; n = idx % BN; }
            else     { n = idx / BK;  kk = idx % BK; }
            int gc = colBase + n, gk = k0 + kk;
            float v = 0.0f;
            if (gc < Nn && gk < K)
                v = TB ? ldf(Bm + (long)gc * ldb + gk) : ldf(Bm + (long)gk * ldb + gc);
            Bs[kk][n] = v;
        }
        __syncthreads();

        #pragma unroll
        for (int kk = 0; kk < BK; kk++) {
            float a[TM], bb[TN];
            #pragma unroll
            for (int i = 0; i < TM; i++) a[i] = As[kk][trow * TM + i];
            #pragma unroll
            for (int j = 0; j < TN; j++) bb[j] = Bs[kk][tcol * TN + j];
            #pragma unroll
            for (int i = 0; i < TM; i++)
                #pragma unroll
                for (int j = 0; j < TN; j++)
                    acc[i][j] += a[i] * bb[j];
        }
        __syncthreads();
    }

    #pragma unroll
    for (int i = 0; i < TM; i++) {
        int r = rowBase + trow * TM + i;
        if (r >= M) continue;
        #pragma unroll
        for (int j = 0; j < TN; j++) {
            int c = colBase + tcol * TN + j;
            if (c >= Nn) continue;
            float v = alpha * acc[i][j];
            if (Res) {
                int rr = resRowMod ? (r % resRowMod) : r;
                v += Res[(long)rr * ldres + c];
            }
            C[(long)r * ldc + c] = v;
        }
    }
}

// ---------------------------------------------------------------------------
// Elementwise / reduction kernels
// ---------------------------------------------------------------------------
__device__ __forceinline__ float blk_reduce(float v, bool ismax) {
    __shared__ float red[9];
    #pragma unroll
    for (int o = 16; o; o >>= 1) {
        float u = __shfl_xor_sync(0xffffffffu, v, o);
        v = ismax ? fmaxf(v, u) : (v + u);
    }
    if ((threadIdx.x & 31) == 0) red[threadIdx.x >> 5] = v;
    __syncthreads();
    if (threadIdx.x == 0) {
        float r = red[0];
        int nw = blockDim.x >> 5;
        for (int w = 1; w < nw; w++) r = ismax ? fmaxf(r, red[w]) : (r + red[w]);
        red[8] = r;
    }
    __syncthreads();
    float r = red[8];
    __syncthreads();
    return r;
}

__device__ __forceinline__ int token_type(int j) {
    return j < 512 ? 0 : (j < 1024 ? 1 : 2);
}

__global__ void concat_kernel(const float4* __restrict__ m0,
                              const float4* __restrict__ m1,
                              const float4* __restrict__ fus,
                              float4* __restrict__ tokens) {
    int idx = blockIdx.x * blockDim.x + threadIdx.x;
    const int D4 = D_ / 4;
    int total = B_ * NTOK * D4;
    if (idx >= total) return;
    int d = idx % D4;
    int t = (idx / D4) % NTOK;
    int b = idx / (D4 * NTOK);
    float4 v;
    if (t < 512)       v = m0[((long)b * 512 + t) * D4 + d];
    else if (t < 1024) v = m1[((long)b * 512 + (t - 512)) * D4 + d];
    else               v = fus[(long)(t - 1024) * D4 + d];
    tokens[idx] = v;
}

__global__ void ln_kernel(const float* __restrict__ x,
                          const float* __restrict__ gamma,
                          __half* __restrict__ out) {
    long row = blockIdx.x;
    const float4* xr = (const float4*)(x + row * D_);
    float4 v = xr[threadIdx.x];
    float s = v.x + v.y + v.z + v.w;
    float mean = blk_reduce(s, false) * (1.0f / D_);
    float dx = v.x - mean, dy = v.y - mean, dz = v.z - mean, dw = v.w - mean;
    float s2 = dx * dx + dy * dy + dz * dz + dw * dw;
    float var = blk_reduce(s2, false) * (1.0f / D_);
    float inv = rsqrtf(var + 1e-5f);
    float4 g = ((const float4*)gamma)[threadIdx.x];
    __half2* o = (__half2*)(out + row * D_);
    o[2 * threadIdx.x]     = __floats2half2_rn(dx * inv * g.x, dy * inv * g.y);
    o[2 * threadIdx.x + 1] = __floats2half2_rn(dz * inv * g.z, dw * inv * g.w);
}

__global__ void softmax_pool_kernel(float* __restrict__ sim) {
    long row = blockIdx.x;
    float* p = sim + row * NTOK;
    int r = (int)(row % 4);
    int tid = threadIdx.x;

    float vals[5];
    float mx = -3.4e38f;
    #pragma unroll
    for (int it = 0; it < 5; it++) {
        int j = tid + it * 256;
        float v = -3.4e38f;
        if (j < NTOK) {
            bool ok = (r == 3) || (token_type(j) == r);
            v = ok ? p[j] : -3.4e38f;
        }
        vals[it] = v;
        mx = fmaxf(mx, v);
    }
    mx = blk_reduce(mx, true);

    float e[5];
    float s = 0.0f;
    #pragma unroll
    for (int it = 0; it < 5; it++) {
        float ex = __expf(vals[it] - mx);
        e[it] = ex;
        s += ex;
    }
    s = blk_reduce(s, false);
    float inv = 1.0f / s;
    #pragma unroll
    for (int it = 0; it < 5; it++) {
        int j = tid + it * 256;
        if (j < NTOK) p[j] = e[it] * inv;
    }
}

__global__ void geglu_kernel(const __half* __restrict__ ff1,
                             __half* __restrict__ act) {
    long idx = (long)blockIdx.x * blockDim.x + threadIdx.x;
    long total = (long)ROWS * FF_;
    if (idx >= total) return;
    long row = idx / FF_;
    int f = (int)(idx - row * FF_);
    const __half* p = ff1 + row * FF2_;
    float val = __half2float(p[f]);
    float gate = __half2float(p[FF_ + f]);
    float g = 0.5f * gate * (1.0f + erff(gate * 0.70710678118654752f));
    act[row * (long)ACTLD + f] = __float2half(g * val);
}

// ---------------------------------------------------------------------------
// Host side
// ---------------------------------------------------------------------------
static constexpr int SM_H128  = 3 * (128 * 40 + 128 * 40) * 2;   // 61440
static constexpr int SM_FLASH = (64 * 72 + 4 * 128 * 72) * 2;    // 82944

static inline void hg(const __half* A, const __half* Bt, void* C, const float* Res,
                      int M, int Nn, int K, int lda, int ldbT, int ldc, float alpha,
                      bool outh, int resRowMod = 0, int ldres = 0) {
    dim3 grid((Nn + 127) / 128, (M + 127) / 128, 1);
    if (outh)
        hgemm<128, 64, 32, true><<<grid, 256, SM_H128>>>(
            A, Bt, C, Res, M, Nn, K, lda, ldbT, ldc, alpha, resRowMod, ldres);
    else
        hgemm<128, 64, 32, false><<<grid, 256, SM_H128>>>(
            A, Bt, C, Res, M, Nn, K, lda, ldbT, ldc, alpha, resRowMod, ldres);
}

extern "C" void kernel_launch(void* const* d_in, const int* in_sizes, int n_in,
                              void* d_out, int out_size) {
    const float* m0        = (const float*)d_in[0];
    const float* m1        = (const float*)d_in[1];
    const float* fusion    = (const float*)d_in[2];
    const float* ret_tok   = (const float*)d_in[3];
    const float* ln_gamma  = (const float*)d_in[4];
    const float* wq        = (const float*)d_in[5];
    const float* wkv       = (const float*)d_in[6];
    const float* wo        = (const float*)d_in[7];
    const float* ff_w1     = (const float*)d_in[8];
    const float* ff_w2     = (const float*)d_in[9];
    const float* pool_wq   = (const float*)d_in[10];
    const float* pool_wkv  = (const float*)d_in[11];
    const float* pool_wo   = (const float*)d_in[12];
    const float* final_g   = (const float*)d_in[13];
    float* out = (float*)d_out;

    cudaFuncSetAttribute(hgemm<128, 64, 32, true>,
                         cudaFuncAttributeMaxDynamicSharedMemorySize, SM_H128);
    cudaFuncSetAttribute(hgemm<128, 64, 32, false>,
                         cudaFuncAttributeMaxDynamicSharedMemorySize, SM_H128);
    cudaFuncSetAttribute(flash_kernel,
                         cudaFuncAttributeMaxDynamicSharedMemorySize, SM_FLASH);

    float *tokens, *simbuf, *poolq, *poolao;
    __half *hbuf, *qkvbuf, *kvbuf, *aobuf, *ff1buf, *actbuf;
    __half *wqkvT, *woT, *ff1T, *ff2T, *pkvT;
    cudaGetSymbolAddress((void**)&tokens, g_tokens);
    cudaGetSymbolAddress((void**)&simbuf, g_sim);
    cudaGetSymbolAddress((void**)&poolq,  g_poolq);
    cudaGetSymbolAddress((void**)&poolao, g_poolao);
    cudaGetSymbolAddress((void**)&hbuf,   h_h);
    cudaGetSymbolAddress((void**)&qkvbuf, h_qkv);
    cudaGetSymbolAddress((void**)&kvbuf,  h_kv);
    cudaGetSymbolAddress((void**)&aobuf,  h_ao);
    cudaGetSymbolAddress((void**)&ff1buf, h_ff1);
    cudaGetSymbolAddress((void**)&actbuf, h_act);
    cudaGetSymbolAddress((void**)&wqkvT,  h_wqkvT);
    cudaGetSymbolAddress((void**)&woT,    h_woT);
    cudaGetSymbolAddress((void**)&ff1T,   h_ff1T);
    cudaGetSymbolAddress((void**)&ff2T,   h_ff2T);
    cudaGetSymbolAddress((void**)&pkvT,   h_pkvT);

    const float scale = 0.125f;

    // --- weight pre-transposes (fp32 -> fp16; q-scale folded into wq) ---
    {
        dim3 thr(32, 8);
        const long zq = (long)3 * D_ * D_;
        transpose_kernel<<<dim3(32, 32, 4),  thr>>>(wq,  wqkvT, 1024, 1024, 1024,
                                                    (long)D_ * D_, zq, scale);
        transpose_kernel<<<dim3(64, 32, 4),  thr>>>(wkv, wqkvT + (long)D_ * D_,
                                                    1024, 2048, 1024,
                                                    (long)2 * D_ * D_, zq, 1.0f);
        transpose_kernel<<<dim3(32, 32, 4),  thr>>>(wo, woT, 1024, 1024, 1024,
                                                    (long)D_ * D_, (long)D_ * D_, 1.0f);
        transpose_kernel<<<dim3(171, 32, 4), thr>>>(ff_w1, ff1T, 1024, 5460, 1024,
                                                    (long)D_ * FF2_, (long)FF2_ * D_, 1.0f);
        transpose_kernel<<<dim3(32, 86, 4),  thr>>>(ff_w2, ff2T, 2730, 1024, ACTLD,
                                                    (long)FF_ * D_, (long)D_ * ACTLD, 1.0f);
        transpose_kernel<<<dim3(64, 32, 1),  thr>>>(pool_wkv, pkvT, 1024, 2048, 1024,
                                                    0, 0, 1.0f);
    }

    {
        int total = B_ * NTOK * (D_ / 4);
        concat_kernel<<<(total + 255) / 256, 256>>>(
            (const float4*)m0, (const float4*)m1, (const float4*)fusion,
            (float4*)tokens);
    }

    const long sKVB = (long)NTOK * 2 * D_;

    for (int l = 0; l < L_; l++) {
        const __half* wqkvT_l = wqkvT + (long)l * 3 * D_ * D_;
        const __half* woT_l   = woT   + (long)l * D_ * D_;
        const __half* w1T_l   = ff1T  + (long)l * FF2_ * D_;
        const __half* w2T_l   = ff2T  + (long)l * D_ * ACTLD;
        const float*  g_l     = ln_gamma + (long)l * D_;

        // attention block
        ln_kernel<<<ROWS, 256>>>(tokens, g_l, hbuf);
        hg(hbuf, wqkvT_l, qkvbuf, nullptr, ROWS, 3 * D_, D_, D_, D_, 3 * D_, 1.0f, true);
        flash_kernel<<<dim3(17, 1, B_ * H_), 128, SM_FLASH>>>(qkvbuf, aobuf);
        hg(aobuf, woT_l, tokens, tokens, ROWS, D_, D_, D_, D_, D_, 1.0f, false, 0, D_);

        // feed-forward block
        ln_kernel<<<ROWS, 256>>>(tokens, g_l, hbuf);
        hg(hbuf, w1T_l, ff1buf, nullptr, ROWS, FF2_, D_, D_, D_, FF2_, 1.0f, true);
        {
            long total = (long)ROWS * FF_;
            geglu_kernel<<<(int)((total + 255) / 256), 256>>>(ff1buf, actbuf);
        }
        hg(actbuf, w2T_l, tokens, tokens, ROWS, D_, FF_, ACTLD, ACTLD, D_, 1.0f, false, 0, D_);
    }

    // --- final LN + attention pooling ---
    ln_kernel<<<ROWS, 256>>>(tokens, final_g, hbuf);

    gemm_kernel<64, 64, 16, 4, 4, false, float, float>
        <<<dim3(16, 1, 1), 256>>>(
        ret_tok, pool_wq, poolq, nullptr, 4, D_, D_, D_, D_, D_,
        0, 0, 0, 0, 0, 0, 1, scale, 0, 0);

    hg(hbuf, pkvT, kvbuf, nullptr, ROWS, 2 * D_, D_, D_, D_, 2 * D_, 1.0f, true);

    gemm_kernel<64, 64, 16, 4, 4, true, float, __half>
        <<<dim3((NTOK + 63) / 64, 1, B_ * H_), 256>>>(
        poolq, kvbuf, simbuf, nullptr,
        4, NTOK, DH_, D_, 2 * D_, NTOK,
        0L, DH_, sKVB, DH_,
        (long)H_ * 4 * NTOK, (long)4 * NTOK, H_,
        1.0f, 0, 0);

    softmax_pool_kernel<<<B_ * H_ * 4, 256>>>(simbuf);

    gemm_kernel<64, 64, 16, 4, 4, false, float, __half>
        <<<dim3(1, 1, B_ * H_), 256>>>(
        simbuf, kvbuf + D_, poolao, nullptr,
        4, DH_, NTOK, NTOK, 2 * D_, D_,
        (long)H_ * 4 * NTOK, (long)4 * NTOK,
        sKVB, DH_,
        (long)4 * D_, DH_, H_,
        1.0f, 0, 0);

    gemm_kernel<64, 64, 16, 4, 4, false, float, float>
        <<<dim3(16, 1, 1), 256>>>(
        poolao, pool_wo, out, ret_tok, B_ * 4, D_, D_, D_, D_, D_,
        0, 0, 0, 0, 0, 0, 1, 1.0f, /*resRowMod=*/4, /*ldres=*/D_);
}

// round 8
// speedup vs baseline: 6.5614x; 1.0559x over previous
#include <cuda_runtime.h>
#include <cuda_fp16.h>
#include <math.h>
#include <stdint.h>

// ---------------------------------------------------------------------------
// Problem constants
// ---------------------------------------------------------------------------
static constexpr int B_    = 4;
static constexpr int NTOK  = 1040;   // 512 + 512 + 16
static constexpr int D_    = 1024;
static constexpr int H_    = 16;
static constexpr int DH_   = 64;
static constexpr int L_    = 4;
static constexpr int FF_   = 2730;
static constexpr int FF2_  = 5460;
static constexpr int ROWS  = B_ * NTOK;   // 4160
static constexpr int ACTLD = 2752;        // act cols (43 blocks x 64), padded

// ---------------------------------------------------------------------------
// Device scratch
// ---------------------------------------------------------------------------
__device__ float  g_tokens[B_ * NTOK * D_];
__device__ float  g_sim   [B_ * H_ * 4 * NTOK];   // pool sim only
__device__ float  g_poolq [4 * D_];
__device__ float  g_poolao[B_ * 4 * D_];
__device__ __half h_h     [ROWS * D_];
__device__ __half h_qkv   [ROWS * 3 * D_];
__device__ __half h_kv    [ROWS * 2 * D_];        // pool kv
__device__ __half h_ao    [ROWS * D_];
__device__ __half h_act   [(long long)ROWS * ACTLD];
// transposed fp16 weights
__device__ __half h_wqkvT[(long long)L_ * 3 * D_ * D_];
__device__ __half h_woT  [L_ * D_ * D_];
__device__ __half h_ff1T [(long long)L_ * FF2_ * D_];
__device__ __half h_ff2T [(long long)L_ * D_ * ACTLD];   // pad rows stay zero
__device__ __half h_pkvT [2 * D_ * D_];

// ---------------------------------------------------------------------------
// Helpers
// ---------------------------------------------------------------------------
__device__ __forceinline__ uint32_t smem_u32(const void* p) {
    uint32_t a;
    asm("{ .reg .u64 t; cvta.to.shared.u64 t, %1; cvt.u32.u64 %0, t; }"
        : "=r"(a) : "l"(p));
    return a;
}

__device__ __forceinline__ void mma_f16(float* c, const uint32_t* a, const uint32_t* b) {
    asm volatile(
        "mma.sync.aligned.m16n8k16.row.col.f32.f16.f16.f32 "
        "{%0,%1,%2,%3}, {%4,%5,%6,%7}, {%8,%9}, {%0,%1,%2,%3};"
        : "+f"(c[0]), "+f"(c[1]), "+f"(c[2]), "+f"(c[3])
        : "r"(a[0]), "r"(a[1]), "r"(a[2]), "r"(a[3]), "r"(b[0]), "r"(b[1]));
}

#define LDSM4(d, addr)                                                         \
    asm volatile("ldmatrix.sync.aligned.m8n8.x4.shared.b16 {%0,%1,%2,%3}, [%4];" \
        : "=r"((d)[0]), "=r"((d)[1]), "=r"((d)[2]), "=r"((d)[3]) : "r"(addr))
#define LDSM4T(d, addr)                                                        \
    asm volatile("ldmatrix.sync.aligned.m8n8.x4.trans.shared.b16 {%0,%1,%2,%3}, [%4];" \
        : "=r"((d)[0]), "=r"((d)[1]), "=r"((d)[2]), "=r"((d)[3]) : "r"(addr))

__device__ __forceinline__ void cp16h(uint32_t dst, const __half* src, int bytes) {
    asm volatile("cp.async.cg.shared.global [%0], [%1], 16, %2;"
                 :: "r"(dst), "l"(src), "r"(bytes));
}
#define CP_COMMIT() asm volatile("cp.async.commit_group;" ::: "memory")
#define CP_WAIT1()  asm volatile("cp.async.wait_group 1;" ::: "memory")
#define CP_WAIT0()  asm volatile("cp.async.wait_group 0;" ::: "memory")

__device__ __forceinline__ uint32_t packh2(float x, float y) {
    __half2 h = __floats2half2_rn(x, y);
    return *(uint32_t*)&h;
}
__device__ __forceinline__ float gelu_exact(float g) {
    return 0.5f * g * (1.0f + erff(g * 0.70710678118654752f));
}

// ---------------------------------------------------------------------------
// Flash attention (block-masked).  qkv: [B*NTOK][3072] fp16 (q pre-scaled),
// ao: [B*NTOK][1024] fp16.  grid (17, 1, B*H), 128 threads.
// ---------------------------------------------------------------------------
__global__ void __launch_bounds__(128, 2)
flash_kernel(const __half* __restrict__ qkv, __half* __restrict__ ao) {
    constexpr int LDS_ = 72;
    constexpr int QOFF = 0;
    constexpr int KOFF = 64 * LDS_;
    constexpr int VOFF = KOFF + 2 * 128 * LDS_;
    extern __shared__ __half sm[];
    const uint32_t sb = smem_u32(sm);

    const int tid = threadIdx.x;
    const int w = tid >> 5, lane = tid & 31;
    const int g = lane >> 2, t4 = lane & 3;
    const int q8 = lane >> 3, r8 = lane & 7;

    const int bh = blockIdx.z;
    const int b = bh >> 4, h = bh & 15;
    const int qb = blockIdx.x;
    int q0, c0, clen, qrows;
    if (qb < 16) { q0 = qb * 64; c0 = (qb < 8) ? 0 : 512; clen = 512; qrows = 64; }
    else         { q0 = 1024;  c0 = 0;  clen = NTOK;  qrows = 16; }

    const __half* qb_g = qkv + ((long)b * NTOK) * 3072 + h * 64;
    const __half* kb_g = qkv + ((long)b * NTOK) * 3072 + 1024 + h * 64;
    const __half* vb_g = qkv + ((long)b * NTOK) * 3072 + 2048 + h * 64;

    {
        int row = tid >> 1;
        int gr = q0 + row;
        int bytes = (row < qrows) ? 16 : 0;
        const __half* src = qb_g + (long)(bytes ? gr : 0) * 3072 + (tid & 1) * 32;
        uint32_t dst = sb + (QOFF + row * LDS_ + (tid & 1) * 32) * 2;
        #pragma unroll
        for (int e = 0; e < 4; e++)
            cp16h(dst + e * 16, src + e * 8, bytes);
    }

    const int T = (clen + 127) >> 7;
    int issued = 0;
    auto issueKV = [&](int t) {
        int buf = t & 1;
        int j = c0 + t * 128 + tid;
        int bytes = (j < c0 + clen) ? 16 : 0;
        const __half* ks = kb_g + (long)(bytes ? j : 0) * 3072;
        const __half* vs = vb_g + (long)(bytes ? j : 0) * 3072;
        uint32_t kd = sb + (KOFF + buf * 128 * LDS_ + tid * LDS_) * 2;
        uint32_t vd = sb + (VOFF + buf * 128 * LDS_ + tid * LDS_) * 2;
        #pragma unroll
        for (int ch = 0; ch < 8; ch++) cp16h(kd + ch * 16, ks + ch * 8, bytes);
        #pragma unroll
        for (int ch = 0; ch < 8; ch++) cp16h(vd + ch * 16, vs + ch * 8, bytes);
        CP_COMMIT();
        issued++;
    };
    issueKV(0);
    if (T > 1) issueKV(1);

    float m0 = -1e30f, m1 = -1e30f, l0 = 0.f, l1 = 0.f;
    float o[8][4];
    #pragma unroll
    for (int i = 0; i < 8; i++)
        #pragma unroll
        for (int q = 0; q < 4; q++) o[i][q] = 0.f;

    const int aIdx = (w * 16 + (q8 & 1) * 8 + r8) * LDS_ + (q8 >> 1) * 8;
    const int kIdx = ((q8 >> 1) * 8 + r8) * LDS_ + (q8 & 1) * 8;
    const int vIdx = ((q8 & 1) * 8 + r8) * LDS_ + (q8 >> 1) * 8;

    for (int t = 0; t < T; t++) {
        if (issued - (t + 1) >= 1) { CP_WAIT1(); } else { CP_WAIT0(); }
        __syncthreads();

        const uint32_t kb_s = sb + (KOFF + (t & 1) * 128 * LDS_) * 2;
        const uint32_t vb_s = sb + (VOFF + (t & 1) * 128 * LDS_) * 2;
        const uint32_t qs = sb + QOFF * 2;

        float s[16][4];
        #pragma unroll
        for (int i = 0; i < 16; i++)
            #pragma unroll
            for (int q = 0; q < 4; q++) s[i][q] = 0.f;

        #pragma unroll
        for (int ks = 0; ks < 4; ks++) {
            uint32_t af[4];
            LDSM4(af, qs + (aIdx + ks * 16) * 2);
            #pragma unroll
            for (int p = 0; p < 8; p++) {
                uint32_t d[4];
                LDSM4(d, kb_s + (kIdx + p * 16 * LDS_ + ks * 16) * 2);
                mma_f16(s[2 * p], af, d);
                mma_f16(s[2 * p + 1], af, d + 2);
            }
        }

        int lim = clen - t * 128;
        if (lim < 128) {
            #pragma unroll
            for (int nt = 0; nt < 16; nt++) {
                int cc = nt * 8 + 2 * t4;
                if (cc >= lim)     { s[nt][0] = -1e30f; s[nt][2] = -1e30f; }
                if (cc + 1 >= lim) { s[nt][1] = -1e30f; s[nt][3] = -1e30f; }
            }
        }

        float tm0 = -1e30f, tm1 = -1e30f;
        #pragma unroll
        for (int nt = 0; nt < 16; nt++) {
            tm0 = fmaxf(tm0, fmaxf(s[nt][0], s[nt][1]));
            tm1 = fmaxf(tm1, fmaxf(s[nt][2], s[nt][3]));
        }
        tm0 = fmaxf(tm0, __shfl_xor_sync(0xffffffffu, tm0, 1));
        tm0 = fmaxf(tm0, __shfl_xor_sync(0xffffffffu, tm0, 2));
        tm1 = fmaxf(tm1, __shfl_xor_sync(0xffffffffu, tm1, 1));
        tm1 = fmaxf(tm1, __shfl_xor_sync(0xffffffffu, tm1, 2));

        float nm0 = fmaxf(m0, tm0), nm1 = fmaxf(m1, tm1);
        float sc0 = __expf(m0 - nm0), sc1 = __expf(m1 - nm1);
        m0 = nm0; m1 = nm1;
        l0 *= sc0; l1 *= sc1;
        #pragma unroll
        for (int nt = 0; nt < 8; nt++) {
            o[nt][0] *= sc0; o[nt][1] *= sc0;
            o[nt][2] *= sc1; o[nt][3] *= sc1;
        }

        uint32_t pf[16][2];
        #pragma unroll
        for (int nt = 0; nt < 16; nt++) {
            float p0 = __expf(s[nt][0] - m0);
            float p1 = __expf(s[nt][1] - m0);
            float p2 = __expf(s[nt][2] - m1);
            float p3 = __expf(s[nt][3] - m1);
            l0 += p0 + p1; l1 += p2 + p3;
            pf[nt][0] = packh2(p0, p1);
            pf[nt][1] = packh2(p2, p3);
        }

        #pragma unroll
        for (int kv = 0; kv < 8; kv++) {
            uint32_t a[4] = { pf[2 * kv][0], pf[2 * kv][1],
                              pf[2 * kv + 1][0], pf[2 * kv + 1][1] };
            #pragma unroll
            for (int p = 0; p < 4; p++) {
                uint32_t d[4];
                LDSM4T(d, vb_s + (vIdx + kv * 16 * LDS_ + p * 16) * 2);
                mma_f16(o[2 * p], a, d);
                mma_f16(o[2 * p + 1], a, d + 2);
            }
        }

        __syncthreads();
        if (t + 2 < T) issueKV(t + 2);
    }

    l0 += __shfl_xor_sync(0xffffffffu, l0, 1);
    l0 += __shfl_xor_sync(0xffffffffu, l0, 2);
    l1 += __shfl_xor_sync(0xffffffffu, l1, 1);
    l1 += __shfl_xor_sync(0xffffffffu, l1, 2);
    float inv0 = 1.0f / l0, inv1 = 1.0f / l1;

    int lr0 = w * 16 + g, lr1 = lr0 + 8;
    __half* aob = ao + ((long)b * NTOK) * 1024 + h * 64;
    if (lr0 < qrows) {
        __half* rp = aob + (long)(q0 + lr0) * 1024 + 2 * t4;
        #pragma unroll
        for (int nt = 0; nt < 8; nt++)
            *(__half2*)(rp + nt * 8) = __floats2half2_rn(o[nt][0] * inv0, o[nt][1] * inv0);
    }
    if (lr1 < qrows) {
        __half* rp = aob + (long)(q0 + lr1) * 1024 + 2 * t4;
        #pragma unroll
        for (int nt = 0; nt < 8; nt++)
            *(__half2*)(rp + nt * 8) = __floats2half2_rn(o[nt][2] * inv1, o[nt][3] * inv1);
    }
}

// ---------------------------------------------------------------------------
// fp16 mma.sync GEMM, 3-stage cp.async + ldmatrix.
//   GEGLU=true: B rows remapped so 16-col blocks = (8 val | 8 gate) of the
//   same features; epilogue computes gelu(gate)*val and writes fp16 act
//   with ldc = ACTLD (N must cover gemm cols; act col = gemmcol/2 domain).
// ---------------------------------------------------------------------------
template<int BN, int WTM, int WTN, bool OUTH, bool GEGLU>
__global__ void __launch_bounds__(256, 2)
hgemm(const __half* __restrict__ A, const __half* __restrict__ Bm,
      void* __restrict__ Cv, const float* __restrict__ Res,
      int M, int N, int K, int lda, int ldb, int ldc,
      float alpha, int resRowMod, int ldres) {
    constexpr int WN = BN / WTN;
    constexpr int MT = WTM / 16;
    constexpr int NT = WTN / 8;
    constexpr int A_ST_H = 128 * 40;
    constexpr int B_ST_H = BN * 40;
    constexpr int ST_H   = A_ST_H + B_ST_H;
    constexpr int BE     = BN / 64;

    extern __shared__ __align__(16) __half smem[];
    const uint32_t sb = smem_u32(smem);

    const int tid = threadIdx.x;
    const int wid = tid >> 5, lane = tid & 31;
    const int g = lane >> 2, t4 = lane & 3;
    const int wm = wid / WN, wn = wid % WN;
    const int q8 = lane >> 3, r8 = lane & 7;

    const int rowBase = blockIdx.y * 128;
    const int colBase = blockIdx.x * BN;
    const int KC = (K + 31) >> 5;

    const int chA = tid & 3;
    const __half* aSrc[2];
    uint32_t aOff[2];
    bool aOk[2];
    #pragma unroll
    for (int e = 0; e < 2; e++) {
        int m = (tid >> 2) + 64 * e;
        int gr = rowBase + m;
        aOk[e] = gr < M;
        aSrc[e] = A + (long)(aOk[e] ? gr : 0) * lda + chA * 8;
        aOff[e] = (uint32_t)((m * 40 + chA * 8) * 2);
    }
    const __half* bSrc[BE];
    uint32_t bOff[BE];
    int bOkA[BE];
    #pragma unroll
    for (int e = 0; e < BE; e++) {
        int n = (tid >> 2) + 64 * e;
        int gn = colBase + n;
        int srcRow;
        if (GEGLU) {
            int j = gn >> 4, w = gn & 15;
            int f8 = j * 8 + (w & 7);
            bOkA[e] = (f8 < FF_) ? 1 : 0;
            srcRow = (w < 8) ? f8 : (FF_ + f8);
        } else {
            bOkA[e] = (gn < N) ? 1 : 0;
            srcRow = gn;
        }
        bSrc[e] = Bm + (long)(bOkA[e] ? srcRow : 0) * ldb + chA * 8;
        bOff[e] = (uint32_t)((n * 40 + chA * 8) * 2);
    }

    auto issue = [&](int c, int st) {
        const uint32_t stb = sb + (uint32_t)(st * ST_H * 2);
        int krem = K - (c << 5);
        int kb = (krem - chA * 8) * 2;
        kb = kb < 0 ? 0 : (kb > 16 ? 16 : kb);
        #pragma unroll
        for (int e = 0; e < 2; e++) {
            int bytes = aOk[e] ? kb : 0;
            cp16h(stb + aOff[e], bytes ? aSrc[e] : A, bytes);
            aSrc[e] += 32;
        }
        const uint32_t bstb = stb + (uint32_t)(A_ST_H * 2);
        #pragma unroll
        for (int e = 0; e < BE; e++) {
            int bytes = bOkA[e] ? kb : 0;
            cp16h(bstb + bOff[e], bytes ? bSrc[e] : Bm, bytes);
            bSrc[e] += 32;
        }
        CP_COMMIT();
    };

    float acc[MT][NT][4];
    #pragma unroll
    for (int i = 0; i < MT; i++)
        #pragma unroll
        for (int j = 0; j < NT; j++)
            #pragma unroll
            for (int q = 0; q < 4; q++) acc[i][j][q] = 0.0f;

    const int aIdx0 = (wm * WTM + (q8 & 1) * 8 + r8) * 40 + (q8 >> 1) * 8;
    const int bIdx0 = (wn * WTN + (q8 >> 1) * 8 + r8) * 40 + (q8 & 1) * 8;

    issue(0, 0);
    issue(1, 1);

    int st = 0;
    for (int c = 0; c < KC; c++) {
        CP_WAIT1();
        __syncthreads();
        if (c + 2 < KC) issue(c + 2, (st + 2) % 3);
        else CP_COMMIT();

        const uint32_t aStB = sb + (uint32_t)(st * ST_H * 2);
        const uint32_t bStB = aStB + (uint32_t)(A_ST_H * 2);

        #pragma unroll
        for (int ks = 0; ks < 2; ks++) {
            uint32_t af[MT][4], bf[NT][2];
            #pragma unroll
            for (int mt = 0; mt < MT; mt++)
                LDSM4(af[mt], aStB + (uint32_t)((aIdx0 + mt * 16 * 40 + ks * 16) * 2));
            #pragma unroll
            for (int p = 0; p < NT / 2; p++) {
                uint32_t d[4];
                LDSM4(d, bStB + (uint32_t)((bIdx0 + p * 16 * 40 + ks * 16) * 2));
                bf[2 * p][0] = d[0]; bf[2 * p][1] = d[1];
                bf[2 * p + 1][0] = d[2]; bf[2 * p + 1][1] = d[3];
            }
            #pragma unroll
            for (int mt = 0; mt < MT; mt++)
                #pragma unroll
                for (int nt = 0; nt < NT; nt++)
                    mma_f16(acc[mt][nt], af[mt], bf[nt]);
        }
        st++; if (st == 3) st = 0;
    }

    if (GEGLU) {
        // acc[mt][2p] = val features, acc[mt][2p+1] = matching gates
        __half* act = (__half*)Cv;
        const int actBase = (colBase >> 1) + wn * (WTN / 2);
        #pragma unroll
        for (int mt = 0; mt < MT; mt++) {
            int r0 = rowBase + wm * WTM + mt * 16 + g;
            #pragma unroll
            for (int p = 0; p < NT / 2; p++) {
                int col = actBase + p * 8 + t4 * 2;
                #pragma unroll
                for (int hh = 0; hh < 2; hh++) {
                    int rr = r0 + hh * 8;
                    if (rr >= M) continue;
                    float v0 = acc[mt][2 * p][hh * 2];
                    float v1 = acc[mt][2 * p][hh * 2 + 1];
                    float g0 = acc[mt][2 * p + 1][hh * 2];
                    float g1 = acc[mt][2 * p + 1][hh * 2 + 1];
                    *(__half2*)(act + (long)rr * ldc + col) =
                        __floats2half2_rn(gelu_exact(g0) * v0, gelu_exact(g1) * v1);
                }
            }
        }
        return;
    }

    #pragma unroll
    for (int mt = 0; mt < MT; mt++) {
        int r0 = rowBase + wm * WTM + mt * 16 + g;
        #pragma unroll
        for (int nt = 0; nt < NT; nt++) {
            int col = colBase + wn * WTN + nt * 8 + t4 * 2;
            if (col >= N) continue;
            #pragma unroll
            for (int hh = 0; hh < 2; hh++) {
                int rr = r0 + hh * 8;
                if (rr >= M) continue;
                float vx = alpha * acc[mt][nt][hh * 2];
                float vy = alpha * acc[mt][nt][hh * 2 + 1];
                if (Res) {
                    int rx = resRowMod ? (rr % resRowMod) : rr;
                    float2 rv = *(const float2*)(Res + (long)rx * ldres + col);
                    vx += rv.x; vy += rv.y;
                }
                if (OUTH) {
                    *(__half2*)((__half*)Cv + (long)rr * ldc + col) = __floats2half2_rn(vx, vy);
                } else {
                    float2 v; v.x = vx; v.y = vy;
                    *(float2*)((float*)Cv + (long)rr * ldc + col) = v;
                }
            }
        }
    }
}

// ---------------------------------------------------------------------------
// Weight transpose: dst[z][n][k] = (half)(scale * src[z][k][n])
// ---------------------------------------------------------------------------
__global__ void transpose_kernel(const float* __restrict__ src,
                                 __half* __restrict__ dst,
                                 int K, int N, int ldd,
                                 long srcZ, long dstZ, float scale) {
    __shared__ float tile[32][33];
    int k0 = blockIdx.y * 32, n0 = blockIdx.x * 32;
    long zS = (long)blockIdx.z * srcZ;
    long zD = (long)blockIdx.z * dstZ;
    int tx = threadIdx.x, ty = threadIdx.y;
    #pragma unroll
    for (int i = ty; i < 32; i += 8) {
        int k = k0 + i, n = n0 + tx;
        if (k < K && n < N) tile[i][tx] = src[zS + (long)k * N + n];
    }
    __syncthreads();
    #pragma unroll
    for (int i = ty; i < 32; i += 8) {
        int n = n0 + i, k = k0 + tx;
        if (n < N && k < K) dst[zD + (long)n * ldd + k] = __float2half(scale * tile[tx][i]);
    }
}

// ---------------------------------------------------------------------------
// Small SIMT GEMM (pool)
// ---------------------------------------------------------------------------
template<typename T>
__device__ __forceinline__ float ldf(const T* p) { return (float)*p; }
template<>
__device__ __forceinline__ float ldf<__half>(const __half* p) { return __half2float(*p); }

template<int BM, int BN, int BK, int TM, int TN, bool TB, typename TAT, typename TBT>
__global__ void __launch_bounds__((BM / TM) * (BN / TN))
gemm_kernel(const TAT* __restrict__ A, const TBT* __restrict__ Bm,
            float* __restrict__ C, const float* __restrict__ Res,
            int M, int Nn, int K,
            int lda, int ldb, int ldc,
            long sAb, long sAh, long sBb, long sBh, long sCb, long sCh, int Hdiv,
            float alpha, int resRowMod, int ldres) {
    constexpr int THREADS = (BM / TM) * (BN / TN);
    constexpr int AELEM = BM * BK / THREADS;
    constexpr int BELEM = BK * BN / THREADS;

    int z = blockIdx.z;
    int zb = z / Hdiv, zh = z - zb * Hdiv;
    A  += (long)zb * sAb + (long)zh * sAh;
    Bm += (long)zb * sBb + (long)zh * sBh;
    C  += (long)zb * sCb + (long)zh * sCh;

    __shared__ __align__(16) float As[BK][BM + 4];
    __shared__ __align__(16) float Bs[BK][BN + 4];

    int tid = threadIdx.x;
    int tcol = tid % (BN / TN);
    int trow = tid / (BN / TN);
    int rowBase = blockIdx.y * BM;
    int colBase = blockIdx.x * BN;

    float acc[TM][TN] = {};

    for (int k0 = 0; k0 < K; k0 += BK) {
        #pragma unroll
        for (int e = 0; e < AELEM; e++) {
            int idx = tid + e * THREADS;
            int m = idx / BK, kk = idx % BK;
            int gr = rowBase + m, gc = k0 + kk;
            As[kk][m] = (gr < M && gc < K) ? ldf(A + (long)gr * lda + gc) : 0.0f;
        }
        #pragma unroll
        for (int e = 0; e < BELEM; e++) {
            int idx = tid + e * THREADS;
            int kk, n;
            if (!TB) { kk = idx / BN; n = idx % BN; }
            else     { n = idx / BK;  kk = idx % BK; }
            int gc = colBase + n, gk = k0 + kk;
            float v = 0.0f;
            if (gc < Nn && gk < K)
                v = TB ? ldf(Bm + (long)gc * ldb + gk) : ldf(Bm + (long)gk * ldb + gc);
            Bs[kk][n] = v;
        }
        __syncthreads();

        #pragma unroll
        for (int kk = 0; kk < BK; kk++) {
            float a[TM], bb[TN];
            #pragma unroll
            for (int i = 0; i < TM; i++) a[i] = As[kk][trow * TM + i];
            #pragma unroll
            for (int j = 0; j < TN; j++) bb[j] = Bs[kk][tcol * TN + j];
            #pragma unroll
            for (int i = 0; i < TM; i++)
                #pragma unroll
                for (int j = 0; j < TN; j++)
                    acc[i][j] += a[i] * bb[j];
        }
        __syncthreads();
    }

    #pragma unroll
    for (int i = 0; i < TM; i++) {
        int r = rowBase + trow * TM + i;
        if (r >= M) continue;
        #pragma unroll
        for (int j = 0; j < TN; j++) {
            int c = colBase + tcol * TN + j;
            if (c >= Nn) continue;
            float v = alpha * acc[i][j];
            if (Res) {
                int rr = resRowMod ? (r % resRowMod) : r;
                v += Res[(long)rr * ldres + c];
            }
            C[(long)r * ldc + c] = v;
        }
    }
}

// ---------------------------------------------------------------------------
// Elementwise / reduction kernels
// ---------------------------------------------------------------------------
__device__ __forceinline__ float blk_reduce(float v, bool ismax) {
    __shared__ float red[9];
    #pragma unroll
    for (int o = 16; o; o >>= 1) {
        float u = __shfl_xor_sync(0xffffffffu, v, o);
        v = ismax ? fmaxf(v, u) : (v + u);
    }
    if ((threadIdx.x & 31) == 0) red[threadIdx.x >> 5] = v;
    __syncthreads();
    if (threadIdx.x == 0) {
        float r = red[0];
        int nw = blockDim.x >> 5;
        for (int w = 1; w < nw; w++) r = ismax ? fmaxf(r, red[w]) : (r + red[w]);
        red[8] = r;
    }
    __syncthreads();
    float r = red[8];
    __syncthreads();
    return r;
}

__device__ __forceinline__ int token_type(int j) {
    return j < 512 ? 0 : (j < 1024 ? 1 : 2);
}

__global__ void concat_kernel(const float4* __restrict__ m0,
                              const float4* __restrict__ m1,
                              const float4* __restrict__ fus,
                              float4* __restrict__ tokens) {
    int idx = blockIdx.x * blockDim.x + threadIdx.x;
    const int D4 = D_ / 4;
    int total = B_ * NTOK * D4;
    if (idx >= total) return;
    int d = idx % D4;
    int t = (idx / D4) % NTOK;
    int b = idx / (D4 * NTOK);
    float4 v;
    if (t < 512)       v = m0[((long)b * 512 + t) * D4 + d];
    else if (t < 1024) v = m1[((long)b * 512 + (t - 512)) * D4 + d];
    else               v = fus[(long)(t - 1024) * D4 + d];
    tokens[idx] = v;
}

__global__ void ln_kernel(const float* __restrict__ x,
                          const float* __restrict__ gamma,
                          __half* __restrict__ out) {
    long row = blockIdx.x;
    const float4* xr = (const float4*)(x + row * D_);
    float4 v = xr[threadIdx.x];
    float s = v.x + v.y + v.z + v.w;
    float mean = blk_reduce(s, false) * (1.0f / D_);
    float dx = v.x - mean, dy = v.y - mean, dz = v.z - mean, dw = v.w - mean;
    float s2 = dx * dx + dy * dy + dz * dz + dw * dw;
    float var = blk_reduce(s2, false) * (1.0f / D_);
    float inv = rsqrtf(var + 1e-5f);
    float4 g = ((const float4*)gamma)[threadIdx.x];
    __half2* o = (__half2*)(out + row * D_);
    o[2 * threadIdx.x]     = __floats2half2_rn(dx * inv * g.x, dy * inv * g.y);
    o[2 * threadIdx.x + 1] = __floats2half2_rn(dz * inv * g.z, dw * inv * g.w);
}

__global__ void softmax_pool_kernel(float* __restrict__ sim) {
    long row = blockIdx.x;
    float* p = sim + row * NTOK;
    int r = (int)(row % 4);
    int tid = threadIdx.x;

    float vals[5];
    float mx = -3.4e38f;
    #pragma unroll
    for (int it = 0; it < 5; it++) {
        int j = tid + it * 256;
        float v = -3.4e38f;
        if (j < NTOK) {
            bool ok = (r == 3) || (token_type(j) == r);
            v = ok ? p[j] : -3.4e38f;
        }
        vals[it] = v;
        mx = fmaxf(mx, v);
    }
    mx = blk_reduce(mx, true);

    float e[5];
    float s = 0.0f;
    #pragma unroll
    for (int it = 0; it < 5; it++) {
        float ex = __expf(vals[it] - mx);
        e[it] = ex;
        s += ex;
    }
    s = blk_reduce(s, false);
    float inv = 1.0f / s;
    #pragma unroll
    for (int it = 0; it < 5; it++) {
        int j = tid + it * 256;
        if (j < NTOK) p[j] = e[it] * inv;
    }
}

// ---------------------------------------------------------------------------
// Host side
// ---------------------------------------------------------------------------
static constexpr int SM_H128  = 3 * (128 * 40 + 128 * 40) * 2;   // 61440
static constexpr int SM_FLASH = (64 * 72 + 4 * 128 * 72) * 2;    // 82944

static inline void hg(const __half* A, const __half* Bt, void* C, const float* Res,
                      int M, int Nn, int K, int lda, int ldbT, int ldc, float alpha,
                      bool outh, int resRowMod = 0, int ldres = 0) {
    dim3 grid((Nn + 127) / 128, (M + 127) / 128, 1);
    if (outh)
        hgemm<128, 64, 32, true, false><<<grid, 256, SM_H128>>>(
            A, Bt, C, Res, M, Nn, K, lda, ldbT, ldc, alpha, resRowMod, ldres);
    else
        hgemm<128, 64, 32, false, false><<<grid, 256, SM_H128>>>(
            A, Bt, C, Res, M, Nn, K, lda, ldbT, ldc, alpha, resRowMod, ldres);
}

extern "C" void kernel_launch(void* const* d_in, const int* in_sizes, int n_in,
                              void* d_out, int out_size) {
    const float* m0        = (const float*)d_in[0];
    const float* m1        = (const float*)d_in[1];
    const float* fusion    = (const float*)d_in[2];
    const float* ret_tok   = (const float*)d_in[3];
    const float* ln_gamma  = (const float*)d_in[4];
    const float* wq        = (const float*)d_in[5];
    const float* wkv       = (const float*)d_in[6];
    const float* wo        = (const float*)d_in[7];
    const float* ff_w1     = (const float*)d_in[8];
    const float* ff_w2     = (const float*)d_in[9];
    const float* pool_wq   = (const float*)d_in[10];
    const float* pool_wkv  = (const float*)d_in[11];
    const float* pool_wo   = (const float*)d_in[12];
    const float* final_g   = (const float*)d_in[13];
    float* out = (float*)d_out;

    cudaFuncSetAttribute(hgemm<128, 64, 32, true, false>,
                         cudaFuncAttributeMaxDynamicSharedMemorySize, SM_H128);
    cudaFuncSetAttribute(hgemm<128, 64, 32, false, false>,
                         cudaFuncAttributeMaxDynamicSharedMemorySize, SM_H128);
    cudaFuncSetAttribute(hgemm<128, 64, 32, true, true>,
                         cudaFuncAttributeMaxDynamicSharedMemorySize, SM_H128);
    cudaFuncSetAttribute(flash_kernel,
                         cudaFuncAttributeMaxDynamicSharedMemorySize, SM_FLASH);

    float *tokens, *simbuf, *poolq, *poolao;
    __half *hbuf, *qkvbuf, *kvbuf, *aobuf, *actbuf;
    __half *wqkvT, *woT, *ff1T, *ff2T, *pkvT;
    cudaGetSymbolAddress((void**)&tokens, g_tokens);
    cudaGetSymbolAddress((void**)&simbuf, g_sim);
    cudaGetSymbolAddress((void**)&poolq,  g_poolq);
    cudaGetSymbolAddress((void**)&poolao, g_poolao);
    cudaGetSymbolAddress((void**)&hbuf,   h_h);
    cudaGetSymbolAddress((void**)&qkvbuf, h_qkv);
    cudaGetSymbolAddress((void**)&kvbuf,  h_kv);
    cudaGetSymbolAddress((void**)&aobuf,  h_ao);
    cudaGetSymbolAddress((void**)&actbuf, h_act);
    cudaGetSymbolAddress((void**)&wqkvT,  h_wqkvT);
    cudaGetSymbolAddress((void**)&woT,    h_woT);
    cudaGetSymbolAddress((void**)&ff1T,   h_ff1T);
    cudaGetSymbolAddress((void**)&ff2T,   h_ff2T);
    cudaGetSymbolAddress((void**)&pkvT,   h_pkvT);

    const float scale = 0.125f;

    // --- weight pre-transposes (fp32 -> fp16; q-scale folded into wq) ---
    {
        dim3 thr(32, 8);
        const long zq = (long)3 * D_ * D_;
        transpose_kernel<<<dim3(32, 32, 4),  thr>>>(wq,  wqkvT, 1024, 1024, 1024,
                                                    (long)D_ * D_, zq, scale);
        transpose_kernel<<<dim3(64, 32, 4),  thr>>>(wkv, wqkvT + (long)D_ * D_,
                                                    1024, 2048, 1024,
                                                    (long)2 * D_ * D_, zq, 1.0f);
        transpose_kernel<<<dim3(32, 32, 4),  thr>>>(wo, woT, 1024, 1024, 1024,
                                                    (long)D_ * D_, (long)D_ * D_, 1.0f);
        transpose_kernel<<<dim3(171, 32, 4), thr>>>(ff_w1, ff1T, 1024, 5460, 1024,
                                                    (long)D_ * FF2_, (long)FF2_ * D_, 1.0f);
        transpose_kernel<<<dim3(32, 86, 4),  thr>>>(ff_w2, ff2T, 2730, 1024, ACTLD,
                                                    (long)FF_ * D_, (long)D_ * ACTLD, 1.0f);
        transpose_kernel<<<dim3(64, 32, 1),  thr>>>(pool_wkv, pkvT, 1024, 2048, 1024,
                                                    0, 0, 1.0f);
    }

    {
        int total = B_ * NTOK * (D_ / 4);
        concat_kernel<<<(total + 255) / 256, 256>>>(
            (const float4*)m0, (const float4*)m1, (const float4*)fusion,
            (float4*)tokens);
    }

    const long sKVB = (long)NTOK * 2 * D_;

    for (int l = 0; l < L_; l++) {
        const __half* wqkvT_l = wqkvT + (long)l * 3 * D_ * D_;
        const __half* woT_l   = woT   + (long)l * D_ * D_;
        const __half* w1T_l   = ff1T  + (long)l * FF2_ * D_;
        const __half* w2T_l   = ff2T  + (long)l * D_ * ACTLD;
        const float*  g_l     = ln_gamma + (long)l * D_;

        // attention block
        ln_kernel<<<ROWS, 256>>>(tokens, g_l, hbuf);
        hg(hbuf, wqkvT_l, qkvbuf, nullptr, ROWS, 3 * D_, D_, D_, D_, 3 * D_, 1.0f, true);
        flash_kernel<<<dim3(17, 1, B_ * H_), 128, SM_FLASH>>>(qkvbuf, aobuf);
        hg(aobuf, woT_l, tokens, tokens, ROWS, D_, D_, D_, D_, D_, 1.0f, false, 0, D_);

        // feed-forward block: FF1 + GEGLU fused (N covers 2*ACTLD gemm cols)
        ln_kernel<<<ROWS, 256>>>(tokens, g_l, hbuf);
        hgemm<128, 64, 32, true, true><<<dim3(2 * ACTLD / 128, (ROWS + 127) / 128, 1),
                                         256, SM_H128>>>(
            hbuf, w1T_l, actbuf, nullptr,
            ROWS, 2 * ACTLD, D_, D_, D_, ACTLD, 1.0f, 0, 0);
        hg(actbuf, w2T_l, tokens, tokens, ROWS, D_, FF_, ACTLD, ACTLD, D_, 1.0f, false, 0, D_);
    }

    // --- final LN + attention pooling ---
    ln_kernel<<<ROWS, 256>>>(tokens, final_g, hbuf);

    gemm_kernel<64, 64, 16, 4, 4, false, float, float>
        <<<dim3(16, 1, 1), 256>>>(
        ret_tok, pool_wq, poolq, nullptr, 4, D_, D_, D_, D_, D_,
        0, 0, 0, 0, 0, 0, 1, scale, 0, 0);

    hg(hbuf, pkvT, kvbuf, nullptr, ROWS, 2 * D_, D_, D_, D_, 2 * D_, 1.0f, true);

    gemm_kernel<64, 64, 16, 4, 4, true, float, __half>
        <<<dim3((NTOK + 63) / 64, 1, B_ * H_), 256>>>(
        poolq, kvbuf, simbuf, nullptr,
        4, NTOK, DH_, D_, 2 * D_, NTOK,
        0L, DH_, sKVB, DH_,
        (long)H_ * 4 * NTOK, (long)4 * NTOK, H_,
        1.0f, 0, 0);

    softmax_pool_kernel<<<B_ * H_ * 4, 256>>>(simbuf);

    gemm_kernel<64, 64, 16, 4, 4, false, float, __half>
        <<<dim3(1, 1, B_ * H_), 256>>>(
        simbuf, kvbuf + D_, poolao, nullptr,
        4, DH_, NTOK, NTOK, 2 * D_, D_,
        (long)H_ * 4 * NTOK, (long)4 * NTOK,
        sKVB, DH_,
        (long)4 * D_, DH_, H_,
        1.0f, 0, 0);

    gemm_kernel<64, 64, 16, 4, 4, false, float, float>
        <<<dim3(16, 1, 1), 256>>>(
        poolao, pool_wo, out, ret_tok, B_ * 4, D_, D_, D_, D_, D_,
        0, 0, 0, 0, 0, 0, 1, 1.0f, /*resRowMod=*/4, /*ldres=*/D_);
}

// round 9
// speedup vs baseline: 7.3893x; 1.1262x over previous
#include <cuda_runtime.h>
#include <cuda_fp16.h>
#include <math.h>
#include <stdint.h>

// ---------------------------------------------------------------------------
// Problem constants
// ---------------------------------------------------------------------------
static constexpr int B_    = 4;
static constexpr int NTOK  = 1040;   // 512 + 512 + 16
static constexpr int D_    = 1024;
static constexpr int H_    = 16;
static constexpr int DH_   = 64;
static constexpr int L_    = 4;
static constexpr int FF_   = 2730;
static constexpr int FF2_  = 5460;
static constexpr int ROWS  = B_ * NTOK;   // 4160
static constexpr int ACTLD = 2752;        // act cols (43 blocks x 64), padded

// ---------------------------------------------------------------------------
// Device scratch
// ---------------------------------------------------------------------------
__device__ float  g_tokens[B_ * NTOK * D_];
__device__ float  g_sim   [B_ * H_ * 4 * NTOK];   // pool sim only
__device__ float  g_poolq [4 * D_];
__device__ float  g_poolao[B_ * 4 * D_];
__device__ __half h_h     [ROWS * D_];
__device__ __half h_qkv   [ROWS * 3 * D_];
__device__ __half h_kv    [ROWS * 2 * D_];        // pool kv
__device__ __half h_ao    [ROWS * D_];
__device__ __half h_act   [(long long)ROWS * ACTLD];
// transposed fp16 weights
__device__ __half h_wqkvT[(long long)L_ * 3 * D_ * D_];
__device__ __half h_woT  [L_ * D_ * D_];
__device__ __half h_ff1T [(long long)L_ * FF2_ * D_];
__device__ __half h_ff2T [(long long)L_ * D_ * ACTLD];   // pad rows stay zero
__device__ __half h_pkvT [2 * D_ * D_];

// ---------------------------------------------------------------------------
// Helpers
// ---------------------------------------------------------------------------
__device__ __forceinline__ uint32_t smem_u32(const void* p) {
    uint32_t a;
    asm("{ .reg .u64 t; cvta.to.shared.u64 t, %1; cvt.u32.u64 %0, t; }"
        : "=r"(a) : "l"(p));
    return a;
}

__device__ __forceinline__ void mma_f16(float* c, const uint32_t* a, const uint32_t* b) {
    asm volatile(
        "mma.sync.aligned.m16n8k16.row.col.f32.f16.f16.f32 "
        "{%0,%1,%2,%3}, {%4,%5,%6,%7}, {%8,%9}, {%0,%1,%2,%3};"
        : "+f"(c[0]), "+f"(c[1]), "+f"(c[2]), "+f"(c[3])
        : "r"(a[0]), "r"(a[1]), "r"(a[2]), "r"(a[3]), "r"(b[0]), "r"(b[1]));
}

#define LDSM4(d, addr)                                                         \
    asm volatile("ldmatrix.sync.aligned.m8n8.x4.shared.b16 {%0,%1,%2,%3}, [%4];" \
        : "=r"((d)[0]), "=r"((d)[1]), "=r"((d)[2]), "=r"((d)[3]) : "r"(addr))
#define LDSM4T(d, addr)                                                        \
    asm volatile("ldmatrix.sync.aligned.m8n8.x4.trans.shared.b16 {%0,%1,%2,%3}, [%4];" \
        : "=r"((d)[0]), "=r"((d)[1]), "=r"((d)[2]), "=r"((d)[3]) : "r"(addr))

__device__ __forceinline__ void cp16h(uint32_t dst, const __half* src, int bytes) {
    asm volatile("cp.async.cg.shared.global [%0], [%1], 16, %2;"
                 :: "r"(dst), "l"(src), "r"(bytes));
}
#define CP_COMMIT() asm volatile("cp.async.commit_group;" ::: "memory")
#define CP_WAIT1()  asm volatile("cp.async.wait_group 1;" ::: "memory")
#define CP_WAIT0()  asm volatile("cp.async.wait_group 0;" ::: "memory")

__device__ __forceinline__ uint32_t packh2(float x, float y) {
    __half2 h = __floats2half2_rn(x, y);
    return *(uint32_t*)&h;
}
__device__ __forceinline__ float gelu_exact(float g) {
    return 0.5f * g * (1.0f + erff(g * 0.70710678118654752f));
}

// ---------------------------------------------------------------------------
// Flash attention (block-masked).  qkv: [B*NTOK][3072] fp16 (q pre-scaled),
// ao: [B*NTOK][1024] fp16.  grid (17, 1, B*H), 128 threads.
// ---------------------------------------------------------------------------
__global__ void __launch_bounds__(128, 2)
flash_kernel(const __half* __restrict__ qkv, __half* __restrict__ ao) {
    constexpr int LDS_ = 72;
    constexpr int QOFF = 0;
    constexpr int KOFF = 64 * LDS_;
    constexpr int VOFF = KOFF + 2 * 128 * LDS_;
    extern __shared__ __half sm[];
    const uint32_t sb = smem_u32(sm);

    const int tid = threadIdx.x;
    const int w = tid >> 5, lane = tid & 31;
    const int g = lane >> 2, t4 = lane & 3;
    const int q8 = lane >> 3, r8 = lane & 7;

    const int bh = blockIdx.z;
    const int b = bh >> 4, h = bh & 15;
    const int qb = blockIdx.x;
    int q0, c0, clen, qrows;
    if (qb < 16) { q0 = qb * 64; c0 = (qb < 8) ? 0 : 512; clen = 512; qrows = 64; }
    else         { q0 = 1024;  c0 = 0;  clen = NTOK;  qrows = 16; }

    const __half* qb_g = qkv + ((long)b * NTOK) * 3072 + h * 64;
    const __half* kb_g = qkv + ((long)b * NTOK) * 3072 + 1024 + h * 64;
    const __half* vb_g = qkv + ((long)b * NTOK) * 3072 + 2048 + h * 64;

    {
        int row = tid >> 1;
        int gr = q0 + row;
        int bytes = (row < qrows) ? 16 : 0;
        const __half* src = qb_g + (long)(bytes ? gr : 0) * 3072 + (tid & 1) * 32;
        uint32_t dst = sb + (QOFF + row * LDS_ + (tid & 1) * 32) * 2;
        #pragma unroll
        for (int e = 0; e < 4; e++)
            cp16h(dst + e * 16, src + e * 8, bytes);
    }

    const int T = (clen + 127) >> 7;
    int issued = 0;
    auto issueKV = [&](int t) {
        int buf = t & 1;
        int j = c0 + t * 128 + tid;
        int bytes = (j < c0 + clen) ? 16 : 0;
        const __half* ks = kb_g + (long)(bytes ? j : 0) * 3072;
        const __half* vs = vb_g + (long)(bytes ? j : 0) * 3072;
        uint32_t kd = sb + (KOFF + buf * 128 * LDS_ + tid * LDS_) * 2;
        uint32_t vd = sb + (VOFF + buf * 128 * LDS_ + tid * LDS_) * 2;
        #pragma unroll
        for (int ch = 0; ch < 8; ch++) cp16h(kd + ch * 16, ks + ch * 8, bytes);
        #pragma unroll
        for (int ch = 0; ch < 8; ch++) cp16h(vd + ch * 16, vs + ch * 8, bytes);
        CP_COMMIT();
        issued++;
    };
    issueKV(0);
    if (T > 1) issueKV(1);

    float m0 = -1e30f, m1 = -1e30f, l0 = 0.f, l1 = 0.f;
    float o[8][4];
    #pragma unroll
    for (int i = 0; i < 8; i++)
        #pragma unroll
        for (int q = 0; q < 4; q++) o[i][q] = 0.f;

    const int aIdx = (w * 16 + (q8 & 1) * 8 + r8) * LDS_ + (q8 >> 1) * 8;
    const int kIdx = ((q8 >> 1) * 8 + r8) * LDS_ + (q8 & 1) * 8;
    const int vIdx = ((q8 & 1) * 8 + r8) * LDS_ + (q8 >> 1) * 8;

    for (int t = 0; t < T; t++) {
        if (issued - (t + 1) >= 1) { CP_WAIT1(); } else { CP_WAIT0(); }
        __syncthreads();

        const uint32_t kb_s = sb + (KOFF + (t & 1) * 128 * LDS_) * 2;
        const uint32_t vb_s = sb + (VOFF + (t & 1) * 128 * LDS_) * 2;
        const uint32_t qs = sb + QOFF * 2;

        float s[16][4];
        #pragma unroll
        for (int i = 0; i < 16; i++)
            #pragma unroll
            for (int q = 0; q < 4; q++) s[i][q] = 0.f;

        #pragma unroll
        for (int ks = 0; ks < 4; ks++) {
            uint32_t af[4];
            LDSM4(af, qs + (aIdx + ks * 16) * 2);
            #pragma unroll
            for (int p = 0; p < 8; p++) {
                uint32_t d[4];
                LDSM4(d, kb_s + (kIdx + p * 16 * LDS_ + ks * 16) * 2);
                mma_f16(s[2 * p], af, d);
                mma_f16(s[2 * p + 1], af, d + 2);
            }
        }

        int lim = clen - t * 128;
        if (lim < 128) {
            #pragma unroll
            for (int nt = 0; nt < 16; nt++) {
                int cc = nt * 8 + 2 * t4;
                if (cc >= lim)     { s[nt][0] = -1e30f; s[nt][2] = -1e30f; }
                if (cc + 1 >= lim) { s[nt][1] = -1e30f; s[nt][3] = -1e30f; }
            }
        }

        float tm0 = -1e30f, tm1 = -1e30f;
        #pragma unroll
        for (int nt = 0; nt < 16; nt++) {
            tm0 = fmaxf(tm0, fmaxf(s[nt][0], s[nt][1]));
            tm1 = fmaxf(tm1, fmaxf(s[nt][2], s[nt][3]));
        }
        tm0 = fmaxf(tm0, __shfl_xor_sync(0xffffffffu, tm0, 1));
        tm0 = fmaxf(tm0, __shfl_xor_sync(0xffffffffu, tm0, 2));
        tm1 = fmaxf(tm1, __shfl_xor_sync(0xffffffffu, tm1, 1));
        tm1 = fmaxf(tm1, __shfl_xor_sync(0xffffffffu, tm1, 2));

        float nm0 = fmaxf(m0, tm0), nm1 = fmaxf(m1, tm1);
        float sc0 = __expf(m0 - nm0), sc1 = __expf(m1 - nm1);
        m0 = nm0; m1 = nm1;
        l0 *= sc0; l1 *= sc1;
        #pragma unroll
        for (int nt = 0; nt < 8; nt++) {
            o[nt][0] *= sc0; o[nt][1] *= sc0;
            o[nt][2] *= sc1; o[nt][3] *= sc1;
        }

        uint32_t pf[16][2];
        #pragma unroll
        for (int nt = 0; nt < 16; nt++) {
            float p0 = __expf(s[nt][0] - m0);
            float p1 = __expf(s[nt][1] - m0);
            float p2 = __expf(s[nt][2] - m1);
            float p3 = __expf(s[nt][3] - m1);
            l0 += p0 + p1; l1 += p2 + p3;
            pf[nt][0] = packh2(p0, p1);
            pf[nt][1] = packh2(p2, p3);
        }

        #pragma unroll
        for (int kv = 0; kv < 8; kv++) {
            uint32_t a[4] = { pf[2 * kv][0], pf[2 * kv][1],
                              pf[2 * kv + 1][0], pf[2 * kv + 1][1] };
            #pragma unroll
            for (int p = 0; p < 4; p++) {
                uint32_t d[4];
                LDSM4T(d, vb_s + (vIdx + kv * 16 * LDS_ + p * 16) * 2);
                mma_f16(o[2 * p], a, d);
                mma_f16(o[2 * p + 1], a, d + 2);
            }
        }

        __syncthreads();
        if (t + 2 < T) issueKV(t + 2);
    }

    l0 += __shfl_xor_sync(0xffffffffu, l0, 1);
    l0 += __shfl_xor_sync(0xffffffffu, l0, 2);
    l1 += __shfl_xor_sync(0xffffffffu, l1, 1);
    l1 += __shfl_xor_sync(0xffffffffu, l1, 2);
    float inv0 = 1.0f / l0, inv1 = 1.0f / l1;

    int lr0 = w * 16 + g, lr1 = lr0 + 8;
    __half* aob = ao + ((long)b * NTOK) * 1024 + h * 64;
    if (lr0 < qrows) {
        __half* rp = aob + (long)(q0 + lr0) * 1024 + 2 * t4;
        #pragma unroll
        for (int nt = 0; nt < 8; nt++)
            *(__half2*)(rp + nt * 8) = __floats2half2_rn(o[nt][0] * inv0, o[nt][1] * inv0);
    }
    if (lr1 < qrows) {
        __half* rp = aob + (long)(q0 + lr1) * 1024 + 2 * t4;
        #pragma unroll
        for (int nt = 0; nt < 8; nt++)
            *(__half2*)(rp + nt * 8) = __floats2half2_rn(o[nt][2] * inv1, o[nt][3] * inv1);
    }
}

// ---------------------------------------------------------------------------
// fp16 mma.sync GEMM: BM=128, BN=128, BK=32, warp tile 64x64,
// 128 threads (4 warps), 2 CTAs/SM, 3-stage cp.async + ldmatrix.
//   GEGLU=true: FF1 weight-column remap (8 val | 8 gate per 16) + fused
//   gelu(gate)*val epilogue writing fp16 act (ldc = ACTLD).
// ---------------------------------------------------------------------------
template<bool OUTH, bool GEGLU>
__global__ void __launch_bounds__(128, 2)
hgemm(const __half* __restrict__ A, const __half* __restrict__ Bm,
      void* __restrict__ Cv, const float* __restrict__ Res,
      int M, int N, int K, int lda, int ldb, int ldc,
      float alpha, int resRowMod, int ldres) {
    constexpr int MT = 4;          // 64 / 16
    constexpr int NT = 8;          // 64 / 8
    constexpr int A_ST_H = 128 * 40;
    constexpr int B_ST_H = 128 * 40;
    constexpr int ST_H   = A_ST_H + B_ST_H;

    extern __shared__ __align__(16) __half smem[];
    const uint32_t sb = smem_u32(smem);

    const int tid = threadIdx.x;
    const int wid = tid >> 5, lane = tid & 31;
    const int g = lane >> 2, t4 = lane & 3;
    const int wm = wid >> 1, wn = wid & 1;
    const int q8 = lane >> 3, r8 = lane & 7;

    const int rowBase = blockIdx.y * 128;
    const int colBase = blockIdx.x * 128;
    const int KC = (K + 31) >> 5;

    const int chA = tid & 3;       // 8-half chunk within 32-half k-row
    const __half* aSrc[4];
    uint32_t aOff[4];
    bool aOk[4];
    #pragma unroll
    for (int e = 0; e < 4; e++) {
        int m = (tid >> 2) + 32 * e;
        int gr = rowBase + m;
        aOk[e] = gr < M;
        aSrc[e] = A + (long)(aOk[e] ? gr : 0) * lda + chA * 8;
        aOff[e] = (uint32_t)((m * 40 + chA * 8) * 2);
    }
    const __half* bSrc[4];
    uint32_t bOff[4];
    int bOkA[4];
    #pragma unroll
    for (int e = 0; e < 4; e++) {
        int n = (tid >> 2) + 32 * e;
        int gn = colBase + n;
        int srcRow;
        if (GEGLU) {
            int j = gn >> 4, ww = gn & 15;
            int f8 = j * 8 + (ww & 7);
            bOkA[e] = (f8 < FF_) ? 1 : 0;
            srcRow = (ww < 8) ? f8 : (FF_ + f8);
        } else {
            bOkA[e] = (gn < N) ? 1 : 0;
            srcRow = gn;
        }
        bSrc[e] = Bm + (long)(bOkA[e] ? srcRow : 0) * ldb + chA * 8;
        bOff[e] = (uint32_t)((n * 40 + chA * 8) * 2);
    }

    auto issue = [&](int c, int st) {
        const uint32_t stb = sb + (uint32_t)(st * ST_H * 2);
        int krem = K - (c << 5);
        int kb = (krem - chA * 8) * 2;
        kb = kb < 0 ? 0 : (kb > 16 ? 16 : kb);
        #pragma unroll
        for (int e = 0; e < 4; e++) {
            int bytes = aOk[e] ? kb : 0;
            cp16h(stb + aOff[e], bytes ? aSrc[e] : A, bytes);
            aSrc[e] += 32;
        }
        const uint32_t bstb = stb + (uint32_t)(A_ST_H * 2);
        #pragma unroll
        for (int e = 0; e < 4; e++) {
            int bytes = bOkA[e] ? kb : 0;
            cp16h(bstb + bOff[e], bytes ? bSrc[e] : Bm, bytes);
            bSrc[e] += 32;
        }
        CP_COMMIT();
    };

    float acc[MT][NT][4];
    #pragma unroll
    for (int i = 0; i < MT; i++)
        #pragma unroll
        for (int j = 0; j < NT; j++)
            #pragma unroll
            for (int q = 0; q < 4; q++) acc[i][j][q] = 0.0f;

    const int aIdx0 = (wm * 64 + (q8 & 1) * 8 + r8) * 40 + (q8 >> 1) * 8;
    const int bIdx0 = (wn * 64 + (q8 >> 1) * 8 + r8) * 40 + (q8 & 1) * 8;

    issue(0, 0);
    issue(1, 1);

    int st = 0;
    for (int c = 0; c < KC; c++) {
        CP_WAIT1();
        __syncthreads();
        if (c + 2 < KC) issue(c + 2, (st + 2) % 3);
        else CP_COMMIT();

        const uint32_t aStB = sb + (uint32_t)(st * ST_H * 2);
        const uint32_t bStB = aStB + (uint32_t)(A_ST_H * 2);

        #pragma unroll
        for (int ks = 0; ks < 2; ks++) {
            uint32_t af[MT][4], bf[NT][2];
            #pragma unroll
            for (int mt = 0; mt < MT; mt++)
                LDSM4(af[mt], aStB + (uint32_t)((aIdx0 + mt * 16 * 40 + ks * 16) * 2));
            #pragma unroll
            for (int p = 0; p < NT / 2; p++) {
                uint32_t d[4];
                LDSM4(d, bStB + (uint32_t)((bIdx0 + p * 16 * 40 + ks * 16) * 2));
                bf[2 * p][0] = d[0]; bf[2 * p][1] = d[1];
                bf[2 * p + 1][0] = d[2]; bf[2 * p + 1][1] = d[3];
            }
            #pragma unroll
            for (int mt = 0; mt < MT; mt++)
                #pragma unroll
                for (int nt = 0; nt < NT; nt++)
                    mma_f16(acc[mt][nt], af[mt], bf[nt]);
        }
        st++; if (st == 3) st = 0;
    }

    if (GEGLU) {
        __half* act = (__half*)Cv;
        const int actBase = (colBase >> 1) + wn * 32;
        #pragma unroll
        for (int mt = 0; mt < MT; mt++) {
            int r0 = rowBase + wm * 64 + mt * 16 + g;
            #pragma unroll
            for (int p = 0; p < NT / 2; p++) {
                int col = actBase + p * 8 + t4 * 2;
                #pragma unroll
                for (int hh = 0; hh < 2; hh++) {
                    int rr = r0 + hh * 8;
                    if (rr >= M) continue;
                    float v0 = acc[mt][2 * p][hh * 2];
                    float v1 = acc[mt][2 * p][hh * 2 + 1];
                    float g0 = acc[mt][2 * p + 1][hh * 2];
                    float g1 = acc[mt][2 * p + 1][hh * 2 + 1];
                    *(__half2*)(act + (long)rr * ldc + col) =
                        __floats2half2_rn(gelu_exact(g0) * v0, gelu_exact(g1) * v1);
                }
            }
        }
        return;
    }

    #pragma unroll
    for (int mt = 0; mt < MT; mt++) {
        int r0 = rowBase + wm * 64 + mt * 16 + g;
        #pragma unroll
        for (int nt = 0; nt < NT; nt++) {
            int col = colBase + wn * 64 + nt * 8 + t4 * 2;
            if (col >= N) continue;
            #pragma unroll
            for (int hh = 0; hh < 2; hh++) {
                int rr = r0 + hh * 8;
                if (rr >= M) continue;
                float vx = alpha * acc[mt][nt][hh * 2];
                float vy = alpha * acc[mt][nt][hh * 2 + 1];
                if (Res) {
                    int rx = resRowMod ? (rr % resRowMod) : rr;
                    float2 rv = *(const float2*)(Res + (long)rx * ldres + col);
                    vx += rv.x; vy += rv.y;
                }
                if (OUTH) {
                    *(__half2*)((__half*)Cv + (long)rr * ldc + col) = __floats2half2_rn(vx, vy);
                } else {
                    float2 v; v.x = vx; v.y = vy;
                    *(float2*)((float*)Cv + (long)rr * ldc + col) = v;
                }
            }
        }
    }
}

// ---------------------------------------------------------------------------
// Weight transpose: dst[z][n][k] = (half)(scale * src[z][k][n])
// 64-deep k tiles so each thread writes __half2 (128B per warp row).
// ---------------------------------------------------------------------------
__global__ void transpose_kernel(const float* __restrict__ src,
                                 __half* __restrict__ dst,
                                 int K, int N, int ldd,
                                 long srcZ, long dstZ, float scale) {
    __shared__ float tile[64][33];
    int k0 = blockIdx.y * 64, n0 = blockIdx.x * 32;
    long zS = (long)blockIdx.z * srcZ;
    long zD = (long)blockIdx.z * dstZ;
    int tx = threadIdx.x, ty = threadIdx.y;   // 32 x 8
    #pragma unroll
    for (int i = ty; i < 64; i += 8) {
        int k = k0 + i, n = n0 + tx;
        if (k < K && n < N) tile[i][tx] = src[zS + (long)k * N + n];
    }
    __syncthreads();
    #pragma unroll
    for (int i = ty; i < 32; i += 8) {
        int n = n0 + i, k = k0 + tx * 2;
        if (n < N && k + 1 < K)
            *(__half2*)(dst + zD + (long)n * ldd + k) =
                __floats2half2_rn(scale * tile[tx * 2][i], scale * tile[tx * 2 + 1][i]);
    }
}

// ---------------------------------------------------------------------------
// Small SIMT GEMM (pool)
// ---------------------------------------------------------------------------
template<typename T>
__device__ __forceinline__ float ldf(const T* p) { return (float)*p; }
template<>
__device__ __forceinline__ float ldf<__half>(const __half* p) { return __half2float(*p); }

template<int BM, int BN, int BK, int TM, int TN, bool TB, typename TAT, typename TBT>
__global__ void __launch_bounds__((BM / TM) * (BN / TN))
gemm_kernel(const TAT* __restrict__ A, const TBT* __restrict__ Bm,
            float* __restrict__ C, const float* __restrict__ Res,
            int M, int Nn, int K,
            int lda, int ldb, int ldc,
            long sAb, long sAh, long sBb, long sBh, long sCb, long sCh, int Hdiv,
            float alpha, int resRowMod, int ldres) {
    constexpr int THREADS = (BM / TM) * (BN / TN);
    constexpr int AELEM = BM * BK / THREADS;
    constexpr int BELEM = BK * BN / THREADS;

    int z = blockIdx.z;
    int zb = z / Hdiv, zh = z - zb * Hdiv;
    A  += (long)zb * sAb + (long)zh * sAh;
    Bm += (long)zb * sBb + (long)zh * sBh;
    C  += (long)zb * sCb + (long)zh * sCh;

    __shared__ __align__(16) float As[BK][BM + 4];
    __shared__ __align__(16) float Bs[BK][BN + 4];

    int tid = threadIdx.x;
    int tcol = tid % (BN / TN);
    int trow = tid / (BN / TN);
    int rowBase = blockIdx.y * BM;
    int colBase = blockIdx.x * BN;

    float acc[TM][TN] = {};

    for (int k0 = 0; k0 < K; k0 += BK) {
        #pragma unroll
        for (int e = 0; e < AELEM; e++) {
            int idx = tid + e * THREADS;
            int m = idx / BK, kk = idx % BK;
            int gr = rowBase + m, gc = k0 + kk;
            As[kk][m] = (gr < M && gc < K) ? ldf(A + (long)gr * lda + gc) : 0.0f;
        }
        #pragma unroll
        for (int e = 0; e < BELEM; e++) {
            int idx = tid + e * THREADS;
            int kk, n;
            if (!TB) { kk = idx / BN; n = idx % BN; }
            else     { n = idx / BK;  kk = idx % BK; }
            int gc = colBase + n, gk = k0 + kk;
            float v = 0.0f;
            if (gc < Nn && gk < K)
                v = TB ? ldf(Bm + (long)gc * ldb + gk) : ldf(Bm + (long)gk * ldb + gc);
            Bs[kk][n] = v;
        }
        __syncthreads();

        #pragma unroll
        for (int kk = 0; kk < BK; kk++) {
            float a[TM], bb[TN];
            #pragma unroll
            for (int i = 0; i < TM; i++) a[i] = As[kk][trow * TM + i];
            #pragma unroll
            for (int j = 0; j < TN; j++) bb[j] = Bs[kk][tcol * TN + j];
            #pragma unroll
            for (int i = 0; i < TM; i++)
                #pragma unroll
                for (int j = 0; j < TN; j++)
                    acc[i][j] += a[i] * bb[j];
        }
        __syncthreads();
    }

    #pragma unroll
    for (int i = 0; i < TM; i++) {
        int r = rowBase + trow * TM + i;
        if (r >= M) continue;
        #pragma unroll
        for (int j = 0; j < TN; j++) {
            int c = colBase + tcol * TN + j;
            if (c >= Nn) continue;
            float v = alpha * acc[i][j];
            if (Res) {
                int rr = resRowMod ? (r % resRowMod) : r;
                v += Res[(long)rr * ldres + c];
            }
            C[(long)r * ldc + c] = v;
        }
    }
}

// ---------------------------------------------------------------------------
// Elementwise / reduction kernels
// ---------------------------------------------------------------------------
__device__ __forceinline__ float blk_reduce(float v, bool ismax) {
    __shared__ float red[9];
    #pragma unroll
    for (int o = 16; o; o >>= 1) {
        float u = __shfl_xor_sync(0xffffffffu, v, o);
        v = ismax ? fmaxf(v, u) : (v + u);
    }
    if ((threadIdx.x & 31) == 0) red[threadIdx.x >> 5] = v;
    __syncthreads();
    if (threadIdx.x == 0) {
        float r = red[0];
        int nw = blockDim.x >> 5;
        for (int w = 1; w < nw; w++) r = ismax ? fmaxf(r, red[w]) : (r + red[w]);
        red[8] = r;
    }
    __syncthreads();
    float r = red[8];
    __syncthreads();
    return r;
}

__device__ __forceinline__ int token_type(int j) {
    return j < 512 ? 0 : (j < 1024 ? 1 : 2);
}

__global__ void concat_kernel(const float4* __restrict__ m0,
                              const float4* __restrict__ m1,
                              const float4* __restrict__ fus,
                              float4* __restrict__ tokens) {
    int idx = blockIdx.x * blockDim.x + threadIdx.x;
    const int D4 = D_ / 4;
    int total = B_ * NTOK * D4;
    if (idx >= total) return;
    int d = idx % D4;
    int t = (idx / D4) % NTOK;
    int b = idx / (D4 * NTOK);
    float4 v;
    if (t < 512)       v = m0[((long)b * 512 + t) * D4 + d];
    else if (t < 1024) v = m1[((long)b * 512 + (t - 512)) * D4 + d];
    else               v = fus[(long)(t - 1024) * D4 + d];
    tokens[idx] = v;
}

__global__ void ln_kernel(const float* __restrict__ x,
                          const float* __restrict__ gamma,
                          __half* __restrict__ out) {
    long row = blockIdx.x;
    const float4* xr = (const float4*)(x + row * D_);
    float4 v = xr[threadIdx.x];
    float s = v.x + v.y + v.z + v.w;
    float mean = blk_reduce(s, false) * (1.0f / D_);
    float dx = v.x - mean, dy = v.y - mean, dz = v.z - mean, dw = v.w - mean;
    float s2 = dx * dx + dy * dy + dz * dz + dw * dw;
    float var = blk_reduce(s2, false) * (1.0f / D_);
    float inv = rsqrtf(var + 1e-5f);
    float4 g = ((const float4*)gamma)[threadIdx.x];
    __half2* o = (__half2*)(out + row * D_);
    o[2 * threadIdx.x]     = __floats2half2_rn(dx * inv * g.x, dy * inv * g.y);
    o[2 * threadIdx.x + 1] = __floats2half2_rn(dz * inv * g.z, dw * inv * g.w);
}

__global__ void softmax_pool_kernel(float* __restrict__ sim) {
    long row = blockIdx.x;
    float* p = sim + row * NTOK;
    int r = (int)(row % 4);
    int tid = threadIdx.x;

    float vals[5];
    float mx = -3.4e38f;
    #pragma unroll
    for (int it = 0; it < 5; it++) {
        int j = tid + it * 256;
        float v = -3.4e38f;
        if (j < NTOK) {
            bool ok = (r == 3) || (token_type(j) == r);
            v = ok ? p[j] : -3.4e38f;
        }
        vals[it] = v;
        mx = fmaxf(mx, v);
    }
    mx = blk_reduce(mx, true);

    float e[5];
    float s = 0.0f;
    #pragma unroll
    for (int it = 0; it < 5; it++) {
        float ex = __expf(vals[it] - mx);
        e[it] = ex;
        s += ex;
    }
    s = blk_reduce(s, false);
    float inv = 1.0f / s;
    #pragma unroll
    for (int it = 0; it < 5; it++) {
        int j = tid + it * 256;
        if (j < NTOK) p[j] = e[it] * inv;
    }
}

// ---------------------------------------------------------------------------
// Host side
// ---------------------------------------------------------------------------
static constexpr int SM_H128  = 3 * (128 * 40 + 128 * 40) * 2;   // 61440
static constexpr int SM_FLASH = (64 * 72 + 4 * 128 * 72) * 2;    // 82944

static inline void hg(const __half* A, const __half* Bt, void* C, const float* Res,
                      int M, int Nn, int K, int lda, int ldbT, int ldc, float alpha,
                      bool outh, int resRowMod = 0, int ldres = 0) {
    dim3 grid((Nn + 127) / 128, (M + 127) / 128, 1);
    if (outh)
        hgemm<true, false><<<grid, 128, SM_H128>>>(
            A, Bt, C, Res, M, Nn, K, lda, ldbT, ldc, alpha, resRowMod, ldres);
    else
        hgemm<false, false><<<grid, 128, SM_H128>>>(
            A, Bt, C, Res, M, Nn, K, lda, ldbT, ldc, alpha, resRowMod, ldres);
}

extern "C" void kernel_launch(void* const* d_in, const int* in_sizes, int n_in,
                              void* d_out, int out_size) {
    const float* m0        = (const float*)d_in[0];
    const float* m1        = (const float*)d_in[1];
    const float* fusion    = (const float*)d_in[2];
    const float* ret_tok   = (const float*)d_in[3];
    const float* ln_gamma  = (const float*)d_in[4];
    const float* wq        = (const float*)d_in[5];
    const float* wkv       = (const float*)d_in[6];
    const float* wo        = (const float*)d_in[7];
    const float* ff_w1     = (const float*)d_in[8];
    const float* ff_w2     = (const float*)d_in[9];
    const float* pool_wq   = (const float*)d_in[10];
    const float* pool_wkv  = (const float*)d_in[11];
    const float* pool_wo   = (const float*)d_in[12];
    const float* final_g   = (const float*)d_in[13];
    float* out = (float*)d_out;

    cudaFuncSetAttribute(hgemm<true, false>,
                         cudaFuncAttributeMaxDynamicSharedMemorySize, SM_H128);
    cudaFuncSetAttribute(hgemm<false, false>,
                         cudaFuncAttributeMaxDynamicSharedMemorySize, SM_H128);
    cudaFuncSetAttribute(hgemm<true, true>,
                         cudaFuncAttributeMaxDynamicSharedMemorySize, SM_H128);
    cudaFuncSetAttribute(flash_kernel,
                         cudaFuncAttributeMaxDynamicSharedMemorySize, SM_FLASH);

    float *tokens, *simbuf, *poolq, *poolao;
    __half *hbuf, *qkvbuf, *kvbuf, *aobuf, *actbuf;
    __half *wqkvT, *woT, *ff1T, *ff2T, *pkvT;
    cudaGetSymbolAddress((void**)&tokens, g_tokens);
    cudaGetSymbolAddress((void**)&simbuf, g_sim);
    cudaGetSymbolAddress((void**)&poolq,  g_poolq);
    cudaGetSymbolAddress((void**)&poolao, g_poolao);
    cudaGetSymbolAddress((void**)&hbuf,   h_h);
    cudaGetSymbolAddress((void**)&qkvbuf, h_qkv);
    cudaGetSymbolAddress((void**)&kvbuf,  h_kv);
    cudaGetSymbolAddress((void**)&aobuf,  h_ao);
    cudaGetSymbolAddress((void**)&actbuf, h_act);
    cudaGetSymbolAddress((void**)&wqkvT,  h_wqkvT);
    cudaGetSymbolAddress((void**)&woT,    h_woT);
    cudaGetSymbolAddress((void**)&ff1T,   h_ff1T);
    cudaGetSymbolAddress((void**)&ff2T,   h_ff2T);
    cudaGetSymbolAddress((void**)&pkvT,   h_pkvT);

    const float scale = 0.125f;

    // --- weight pre-transposes (fp32 -> fp16; q-scale folded into wq) ---
    {
        dim3 thr(32, 8);
        const long zq = (long)3 * D_ * D_;
        transpose_kernel<<<dim3(32, 16, 4),  thr>>>(wq,  wqkvT, 1024, 1024, 1024,
                                                    (long)D_ * D_, zq, scale);
        transpose_kernel<<<dim3(64, 16, 4),  thr>>>(wkv, wqkvT + (long)D_ * D_,
                                                    1024, 2048, 1024,
                                                    (long)2 * D_ * D_, zq, 1.0f);
        transpose_kernel<<<dim3(32, 16, 4),  thr>>>(wo, woT, 1024, 1024, 1024,
                                                    (long)D_ * D_, (long)D_ * D_, 1.0f);
        transpose_kernel<<<dim3(171, 16, 4), thr>>>(ff_w1, ff1T, 1024, 5460, 1024,
                                                    (long)D_ * FF2_, (long)FF2_ * D_, 1.0f);
        transpose_kernel<<<dim3(32, 43, 4),  thr>>>(ff_w2, ff2T, 2730, 1024, ACTLD,
                                                    (long)FF_ * D_, (long)D_ * ACTLD, 1.0f);
        transpose_kernel<<<dim3(64, 16, 1),  thr>>>(pool_wkv, pkvT, 1024, 2048, 1024,
                                                    0, 0, 1.0f);
    }

    {
        int total = B_ * NTOK * (D_ / 4);
        concat_kernel<<<(total + 255) / 256, 256>>>(
            (const float4*)m0, (const float4*)m1, (const float4*)fusion,
            (float4*)tokens);
    }

    const long sKVB = (long)NTOK * 2 * D_;

    for (int l = 0; l < L_; l++) {
        const __half* wqkvT_l = wqkvT + (long)l * 3 * D_ * D_;
        const __half* woT_l   = woT   + (long)l * D_ * D_;
        const __half* w1T_l   = ff1T  + (long)l * FF2_ * D_;
        const __half* w2T_l   = ff2T  + (long)l * D_ * ACTLD;
        const float*  g_l     = ln_gamma + (long)l * D_;

        // attention block
        ln_kernel<<<ROWS, 256>>>(tokens, g_l, hbuf);
        hg(hbuf, wqkvT_l, qkvbuf, nullptr, ROWS, 3 * D_, D_, D_, D_, 3 * D_, 1.0f, true);
        flash_kernel<<<dim3(17, 1, B_ * H_), 128, SM_FLASH>>>(qkvbuf, aobuf);
        hg(aobuf, woT_l, tokens, tokens, ROWS, D_, D_, D_, D_, D_, 1.0f, false, 0, D_);

        // feed-forward block: FF1 + GEGLU fused
        ln_kernel<<<ROWS, 256>>>(tokens, g_l, hbuf);
        hgemm<true, true><<<dim3(2 * ACTLD / 128, (ROWS + 127) / 128, 1),
                            128, SM_H128>>>(
            hbuf, w1T_l, actbuf, nullptr,
            ROWS, 2 * ACTLD, D_, D_, D_, ACTLD, 1.0f, 0, 0);
        hg(actbuf, w2T_l, tokens, tokens, ROWS, D_, FF_, ACTLD, ACTLD, D_, 1.0f, false, 0, D_);
    }

    // --- final LN + attention pooling ---
    ln_kernel<<<ROWS, 256>>>(tokens, final_g, hbuf);

    gemm_kernel<64, 64, 16, 4, 4, false, float, float>
        <<<dim3(16, 1, 1), 256>>>(
        ret_tok, pool_wq, poolq, nullptr, 4, D_, D_, D_, D_, D_,
        0, 0, 0, 0, 0, 0, 1, scale, 0, 0);

    hg(hbuf, pkvT, kvbuf, nullptr, ROWS, 2 * D_, D_, D_, D_, 2 * D_, 1.0f, true);

    gemm_kernel<64, 64, 16, 4, 4, true, float, __half>
        <<<dim3((NTOK + 63) / 64, 1, B_ * H_), 256>>>(
        poolq, kvbuf, simbuf, nullptr,
        4, NTOK, DH_, D_, 2 * D_, NTOK,
        0L, DH_, sKVB, DH_,
        (long)H_ * 4 * NTOK, (long)4 * NTOK, H_,
        1.0f, 0, 0);

    softmax_pool_kernel<<<B_ * H_ * 4, 256>>>(simbuf);

    gemm_kernel<64, 64, 16, 4, 4, false, float, __half>
        <<<dim3(1, 1, B_ * H_), 256>>>(
        simbuf, kvbuf + D_, poolao, nullptr,
        4, DH_, NTOK, NTOK, 2 * D_, D_,
        (long)H_ * 4 * NTOK, (long)4 * NTOK,
        sKVB, DH_,
        (long)4 * D_, DH_, H_,
        1.0f, 0, 0);

    gemm_kernel<64, 64, 16, 4, 4, false, float, float>
        <<<dim3(16, 1, 1), 256>>>(
        poolao, pool_wo, out, ret_tok, B_ * 4, D_, D_, D_, D_, D_,
        0, 0, 0, 0, 0, 0, 1, 1.0f, /*resRowMod=*/4, /*ldres=*/D_);
}